// round 2
// baseline (speedup 1.0000x reference)
#include <cuda_runtime.h>
#include <math.h>

// ---------------- problem constants ----------------
#define NN    8192
#define EE    262144
#define HID   128
#define NRBF  50
#define RBF_P 52          // padded rbf row (16B-friendly, even for k-pairing)
#define NLAY  6

// ---------------- packed f32x2 helpers (SASS FFMA2; ptxas never auto-emits) ----
__device__ __forceinline__ void fma2(unsigned long long& d, unsigned long long a,
                                     unsigned long long b) {
    asm("fma.rn.f32x2 %0, %1, %2, %3;" : "=l"(d) : "l"(a), "l"(b), "l"(d));
}
__device__ __forceinline__ float sum2(unsigned long long v) {
    float lo, hi;
    asm("mov.b64 {%0, %1}, %2;" : "=f"(lo), "=f"(hi) : "l"(v));
    return lo + hi;
}

// ---------------- device scratch (static, no runtime allocs) ----------------
__device__ float g_rbf[(size_t)EE * RBF_P];   // sorted-order rbf, padded
__device__ float g_cut[EE];                   // sorted-order cutoff
__device__ float g_cutm[EE];                  // cutoff * (row!=col)
__device__ int   g_srow[EE];
__device__ int   g_sdst[EE];
__device__ int   g_perm[EE];
__device__ int   g_cnt[NN];
__device__ int   g_offm[NN];
__device__ float g_x  [NN * HID];
__device__ float g_h  [NN * HID];
__device__ float g_h2 [NN * HID];
__device__ float g_agg[NN * HID];
__device__ float g_nex[NN * HID];

// ---------------- small helper kernels ----------------
__global__ void k_zero_cnt() {
    int i = blockIdx.x * blockDim.x + threadIdx.x;
    if (i < NN) g_cnt[i] = 0;
}

__global__ void k_zero_agg() {
    int i = blockIdx.x * blockDim.x + threadIdx.x;
    if (i < NN * HID) g_agg[i] = 0.f;
}

__global__ void k_hist(const int* __restrict__ ei) {
    int e = blockIdx.x * blockDim.x + threadIdx.x;
    if (e < EE) atomicAdd(&g_cnt[ei[EE + e]], 1);
}

__global__ void k_scan() {
    __shared__ int part[1024];
    int t = threadIdx.x;
    int base = t * 8;
    int loc[8];
    int s = 0;
#pragma unroll
    for (int i = 0; i < 8; i++) { loc[i] = s; s += g_cnt[base + i]; }
    part[t] = s;
    __syncthreads();
    int val = s;
    for (int off = 1; off < 1024; off <<= 1) {
        int v = (t >= off) ? part[t - off] : 0;
        __syncthreads();
        val += v;
        part[t] = val;
        __syncthreads();
    }
    int pre = (t == 0) ? 0 : part[t - 1];
#pragma unroll
    for (int i = 0; i < 8; i++) g_offm[base + i] = pre + loc[i];
}

__global__ void k_place(const int* __restrict__ ei) {
    int e = blockIdx.x * blockDim.x + threadIdx.x;
    if (e < EE) {
        int c = ei[EE + e];
        int p = atomicAdd(&g_offm[c], 1);
        g_perm[p] = e;
    }
}

__global__ void k_build(const int* __restrict__ ei, const float* __restrict__ ew,
                        const float* __restrict__ means, const float* __restrict__ betas) {
    int warp = (blockIdx.x * blockDim.x + threadIdx.x) >> 5;
    int lane = threadIdx.x & 31;
    if (warp >= EE) return;
    int e = g_perm[warp];
    int r = ei[e];
    int c = ei[EE + e];
    float d = ew[e];
    float cut = 0.5f * (cosf(d * 0.628318530717958647692f) + 1.0f);
    if (!(d < 5.0f)) cut = 0.f;
    float ex = __expf(-d);
    size_t ro = (size_t)warp * RBF_P;
    {
        float m = means[lane], b = betas[lane];
        float v = ex - m;
        g_rbf[ro + lane] = cut * __expf(-b * v * v);
    }
    int k2 = lane + 32;
    if (k2 < NRBF) {
        float m = means[k2], b = betas[k2];
        float v = ex - m;
        g_rbf[ro + k2] = cut * __expf(-b * v * v);
    } else if (k2 < RBF_P) {
        g_rbf[ro + k2] = 0.f;
    }
    if (lane == 0) {
        g_cut[warp]  = cut;
        g_cutm[warp] = (r != c) ? cut : 0.f;
        g_srow[warp] = r;
        g_sdst[warp] = c;
    }
}

__global__ void k_gather(const int* __restrict__ z, const float* __restrict__ emb,
                         const float* __restrict__ neemb) {
    int i = blockIdx.x * blockDim.x + threadIdx.x;
    if (i >= NN * HID) return;
    int n = i >> 7, c = i & 127;
    int zi = z[n];
    g_x[i]   = emb[zi * HID + c];
    g_nex[i] = neemb[zi * HID + c];
}

// ---------------- fused edge MLP + segmented aggregation (FFMA2 version) ------
// Weights stored in smem k-pair interleaved: sW[(k>>1)*256 + j*2 + (k&1)].
// Accumulators are f32x2 pairs (even-k partial, odd-k partial), reduced at end.
template <int NE>
__global__ void __launch_bounds__(512, 1)
k_edge(const float* __restrict__ W1g, const float* __restrict__ b1g,
       const float* __restrict__ W2g, const float* __restrict__ b2g) {
    extern __shared__ float sm[];
    const int W1SZ = NRBF * HID;                 // 6400
    const int W2SZ = NE ? 0 : HID * HID;         // 16384
    float* sW1  = sm;                            // interleaved
    float* sW2  = sW1 + W1SZ;                    // interleaved
    float* sRbf = sW2 + W2SZ;                    // 128 x 52 row-major
    float* sBuf = sRbf + 128 * RBF_P;            // 128 x 132 row-major
    float* sB1  = sBuf + 128 * 132;
    float* sB2  = sB1 + 128;
    float* sCut = sB2 + 128;
    int*   sRow = (int*)(sCut + 128);
    int*   sDst = sRow + 128;

    int tid = threadIdx.x;
    long ebase = (long)blockIdx.x * 128;

    // stage weights (k-pair interleaved) + per-tile data
    for (int i = tid; i < W1SZ; i += 512) {
        int k = i >> 7, j = i & 127;
        sW1[(k >> 1) * 256 + j * 2 + (k & 1)] = W1g[i];
    }
    if (!NE)
        for (int i = tid; i < HID * HID; i += 512) {
            int k = i >> 7, j = i & 127;
            sW2[(k >> 1) * 256 + j * 2 + (k & 1)] = W2g[i];
        }
    for (int i = tid; i < 128 * RBF_P; i += 512) sRbf[i] = g_rbf[ebase * RBF_P + i];
    if (tid < 128) {
        sB1[tid]  = b1g[tid];
        sB2[tid]  = NE ? 0.f : b2g[tid];
        sCut[tid] = NE ? g_cutm[ebase + tid] : g_cut[ebase + tid];
        sRow[tid] = g_srow[ebase + tid];
        sDst[tid] = g_sdst[ebase + tid];
    }
    __syncthreads();

    int tx = tid & 15, ty = tid >> 4;            // 16 x 32 thread grid
    int r0 = ty * 4, c0 = tx * 8;                // 4 rows x 8 cols per thread
    unsigned long long acc2[4][8];
#pragma unroll
    for (int i = 0; i < 4; i++)
#pragma unroll
        for (int j = 0; j < 8; j++) acc2[i][j] = 0ULL;

    // GEMM1: rbf[128,50] @ W1[50,128]  (25 k-pairs)
#pragma unroll 5
    for (int kp = 0; kp < NRBF / 2; kp++) {
        unsigned long long a2[4];
#pragma unroll
        for (int i = 0; i < 4; i++)
            a2[i] = *(const unsigned long long*)&sRbf[(r0 + i) * RBF_P + 2 * kp];
        const float* bp = &sW1[kp * 256 + c0 * 2];
        unsigned long long b2[8];
#pragma unroll
        for (int j = 0; j < 4; j++) {
            ulonglong2 q = *(const ulonglong2*)(bp + 4 * j);
            b2[2 * j] = q.x; b2[2 * j + 1] = q.y;
        }
#pragma unroll
        for (int i = 0; i < 4; i++)
#pragma unroll
            for (int j = 0; j < 8; j++) fma2(acc2[i][j], a2[i], b2[j]);
    }

    if (NE) {
#pragma unroll
        for (int i = 0; i < 4; i++) {
            float cu = sCut[r0 + i];
#pragma unroll
            for (int j = 0; j < 8; j++)
                sBuf[(r0 + i) * 132 + c0 + j] = (sum2(acc2[i][j]) + sB1[c0 + j]) * cu;
        }
        __syncthreads();
    } else {
        // silu -> smem
#pragma unroll
        for (int i = 0; i < 4; i++)
#pragma unroll
            for (int j = 0; j < 8; j++) {
                float v = sum2(acc2[i][j]) + sB1[c0 + j];
                sBuf[(r0 + i) * 132 + c0 + j] = v / (1.0f + __expf(-v));
            }
        __syncthreads();

        // GEMM2: t[128,128] @ W2[128,128]  (64 k-pairs)
#pragma unroll
        for (int i = 0; i < 4; i++)
#pragma unroll
            for (int j = 0; j < 8; j++) acc2[i][j] = 0ULL;
#pragma unroll 4
        for (int kp = 0; kp < HID / 2; kp++) {
            unsigned long long a2[4];
#pragma unroll
            for (int i = 0; i < 4; i++)
                a2[i] = *(const unsigned long long*)&sBuf[(r0 + i) * 132 + 2 * kp];
            const float* bp = &sW2[kp * 256 + c0 * 2];
            unsigned long long b2[8];
#pragma unroll
            for (int j = 0; j < 4; j++) {
                ulonglong2 q = *(const ulonglong2*)(bp + 4 * j);
                b2[2 * j] = q.x; b2[2 * j + 1] = q.y;
            }
#pragma unroll
            for (int i = 0; i < 4; i++)
#pragma unroll
                for (int j = 0; j < 8; j++) fma2(acc2[i][j], a2[i], b2[j]);
        }
        __syncthreads();
#pragma unroll
        for (int i = 0; i < 4; i++) {
            float cu = sCut[r0 + i];
#pragma unroll
            for (int j = 0; j < 8; j++)
                sBuf[(r0 + i) * 132 + c0 + j] = (sum2(acc2[i][j]) + sB2[c0 + j]) * cu;
        }
        __syncthreads();
    }

    // segmented aggregation: 4 groups x 128 channels, 32 edges per group
    const float* hsrc = NE ? g_nex : g_h;
    int g = tid >> 7;
    int f = tid & 127;
    int e0 = g * 32;
    float accv = 0.f;
    int cur = sDst[e0];
#pragma unroll 1
    for (int b = 0; b < 4; b++) {
        float hb[8];
#pragma unroll
        for (int j = 0; j < 8; j++)
            hb[j] = hsrc[(long)sRow[e0 + b * 8 + j] * HID + f];
#pragma unroll
        for (int j = 0; j < 8; j++) {
            int e = e0 + b * 8 + j;
            int dd = sDst[e];
            if (dd != cur) {
                atomicAdd(&g_agg[(long)cur * HID + f], accv);
                accv = 0.f;
                cur = dd;
            }
            accv = fmaf(hb[j], sBuf[e * 132 + f], accv);
        }
    }
    atomicAdd(&g_agg[(long)cur * HID + f], accv);
}

// ---------------- generic node GEMM: out = base + act(A @ W + bias) ----------------
__device__ __forceinline__ float* selp(int s, float* dout) {
    switch (s) {
        case 0: return g_x;
        case 1: return g_h;
        case 2: return g_h2;
        case 3: return g_agg;
        default: return dout;
    }
}

__global__ void __launch_bounds__(256, 1)
k_ngemm(int Asel, const float* __restrict__ Wg, const float* __restrict__ bias,
        int baseSel, int outSel, int silu, float* dout) {
    extern __shared__ float sm[];
    float* sA = sm;                    // 64 x 132 row-major
    float* sW = sA + 64 * 132;         // 128 x 128 interleaved
    float* sB = sW + HID * HID;        // 128
    const float* A = selp(Asel, dout);
    float* out = selp(outSel, dout);
    const float* base = (baseSel >= 0) ? selp(baseSel, dout) : nullptr;

    int tid = threadIdx.x;
    int rb = blockIdx.x * 64;
    for (int i = tid; i < 64 * HID; i += 256) {
        int r = i >> 7, k = i & 127;
        sA[r * 132 + k] = A[(long)(rb + r) * HID + k];
    }
    for (int i = tid; i < HID * HID; i += 256) {
        int k = i >> 7, j = i & 127;
        sW[(k >> 1) * 256 + j * 2 + (k & 1)] = Wg[i];
    }
    if (tid < 128) sB[tid] = bias ? bias[tid] : 0.f;
    __syncthreads();

    int tx = tid & 15, ty = tid >> 4;
    int r0 = ty * 4, c0 = tx * 8;
    unsigned long long acc2[4][8];
#pragma unroll
    for (int i = 0; i < 4; i++)
#pragma unroll
        for (int j = 0; j < 8; j++) acc2[i][j] = 0ULL;
#pragma unroll 4
    for (int kp = 0; kp < HID / 2; kp++) {
        unsigned long long a2[4];
#pragma unroll
        for (int i = 0; i < 4; i++)
            a2[i] = *(const unsigned long long*)&sA[(r0 + i) * 132 + 2 * kp];
        const float* bp = &sW[kp * 256 + c0 * 2];
        unsigned long long b2[8];
#pragma unroll
        for (int j = 0; j < 4; j++) {
            ulonglong2 q = *(const ulonglong2*)(bp + 4 * j);
            b2[2 * j] = q.x; b2[2 * j + 1] = q.y;
        }
#pragma unroll
        for (int i = 0; i < 4; i++)
#pragma unroll
            for (int j = 0; j < 8; j++) fma2(acc2[i][j], a2[i], b2[j]);
    }
#pragma unroll
    for (int i = 0; i < 4; i++) {
        long ro = (long)(rb + r0 + i) * HID;
#pragma unroll
        for (int j = 0; j < 8; j++) {
            float v = sum2(acc2[i][j]) + sB[c0 + j];
            if (silu) v = v / (1.0f + __expf(-v));
            if (base) v += base[ro + c0 + j];
            out[ro + c0 + j] = v;
        }
    }
}

// ---------------- launch ----------------
extern "C" void kernel_launch(void* const* d_in, const int* in_sizes, int n_in,
                              void* d_out, int out_size) {
    const int*   z       = (const int*)d_in[0];
    const int*   ei      = (const int*)d_in[1];
    const float* ew      = (const float*)d_in[2];
    const float* emb     = (const float*)d_in[3];
    const float* neemb   = (const float*)d_in[4];
    const float* neprojw = (const float*)d_in[5];
    const float* neprojb = (const float*)d_in[6];
    const float* necatw  = (const float*)d_in[7];
    const float* necatb  = (const float*)d_in[8];
    const float* means   = (const float*)d_in[9];
    const float* betas   = (const float*)d_in[10];
    const float* mlpw1   = (const float*)d_in[11];
    const float* mlpb1   = (const float*)d_in[12];
    const float* mlpw2   = (const float*)d_in[13];
    const float* mlpb2   = (const float*)d_in[14];
    const float* lin1w   = (const float*)d_in[15];
    const float* lin2w   = (const float*)d_in[16];
    const float* lin2b   = (const float*)d_in[17];
    const float* linw    = (const float*)d_in[18];
    const float* linb    = (const float*)d_in[19];
    float* outp = (float*)d_out;

    const size_t smI = (size_t)(NRBF * HID + HID * HID + 128 * RBF_P + 128 * 132 + 3 * 128) * 4
                       + 2 * 128 * 4;
    const size_t smN = (size_t)(NRBF * HID + 128 * RBF_P + 128 * 132 + 3 * 128) * 4
                       + 2 * 128 * 4;
    const size_t smG = (size_t)(64 * 132 + HID * HID + 128) * 4;

    cudaFuncSetAttribute(k_edge<0>, cudaFuncAttributeMaxDynamicSharedMemorySize, (int)smI);
    cudaFuncSetAttribute(k_edge<1>, cudaFuncAttributeMaxDynamicSharedMemorySize, (int)smN);
    cudaFuncSetAttribute(k_ngemm,   cudaFuncAttributeMaxDynamicSharedMemorySize, (int)smG);

    // ---- sort edges by destination + precompute per-edge data ----
    k_zero_cnt<<<NN / 256, 256>>>();
    k_hist<<<EE / 256, 256>>>(ei);
    k_scan<<<1, 1024>>>();
    k_place<<<EE / 256, 256>>>(ei);
    k_build<<<EE / 8, 256>>>(ei, ew, means, betas);
    k_gather<<<NN * HID / 256, 256>>>(z, emb, neemb);

    // ---- NeighborEmbedding ----
    k_zero_agg<<<NN * HID / 256, 256>>>();
    k_edge<1><<<EE / 128, 512, smN>>>(neprojw, neprojb, nullptr, nullptr);
    k_ngemm<<<NN / 64, 256, smG>>>(0, necatw, necatb, -1, 2, 0, outp);
    k_ngemm<<<NN / 64, 256, smG>>>(3, necatw + HID * HID, nullptr, 2, 0, 0, outp);

    // ---- interaction layers ----
    for (int l = 0; l < NLAY; l++) {
        k_zero_agg<<<NN * HID / 256, 256>>>();
        k_ngemm<<<NN / 64, 256, smG>>>(0, lin1w + (size_t)l * HID * HID, nullptr, -1, 1, 0, outp);
        k_edge<0><<<EE / 128, 512, smI>>>(mlpw1 + (size_t)l * NRBF * HID, mlpb1 + (size_t)l * HID,
                                          mlpw2 + (size_t)l * HID * HID, mlpb2 + (size_t)l * HID);
        k_ngemm<<<NN / 64, 256, smG>>>(3, lin2w + (size_t)l * HID * HID, lin2b + (size_t)l * HID,
                                       -1, 2, 1, outp);
        k_ngemm<<<NN / 64, 256, smG>>>(2, linw + (size_t)l * HID * HID, linb + (size_t)l * HID,
                                       0, (l == NLAY - 1) ? 4 : 0, 0, outp);
    }
}

// round 3
// speedup vs baseline: 1.8100x; 1.8100x over previous
#include <cuda_runtime.h>
#include <math.h>

// ---------------- problem constants ----------------
#define NN    8192
#define EE    262144
#define HID   128
#define NRBF  50
#define RBF_P 52          // padded rbf row (even, 16B-friendly)
#define K1P   52          // padded K for GEMM1
#define NLAY  6

// ---------------- device scratch (static, no runtime allocs) ----------------
__device__ float g_rbf[(size_t)EE * RBF_P];   // sorted-order rbf, padded
__device__ float g_cut[EE];                   // sorted-order cutoff
__device__ float g_cutm[EE];                  // cutoff * (row!=col)
__device__ int   g_srow[EE];
__device__ int   g_sdst[EE];
__device__ int   g_perm[EE];
__device__ int   g_cnt[NN];
__device__ int   g_offm[NN];
__device__ float g_x  [NN * HID];
__device__ float g_h  [NN * HID];
__device__ float g_h2 [NN * HID];
__device__ float g_agg[NN * HID];
__device__ float g_nex[NN * HID];

// ---------------- small helper kernels ----------------
__global__ void k_zero_cnt() {
    int i = blockIdx.x * blockDim.x + threadIdx.x;
    if (i < NN) g_cnt[i] = 0;
}

__global__ void k_zero_agg() {
    int i = blockIdx.x * blockDim.x + threadIdx.x;
    if (i < NN * HID) g_agg[i] = 0.f;
}

__global__ void k_hist(const int* __restrict__ ei) {
    int e = blockIdx.x * blockDim.x + threadIdx.x;
    if (e < EE) atomicAdd(&g_cnt[ei[EE + e]], 1);
}

__global__ void k_scan() {
    __shared__ int part[1024];
    int t = threadIdx.x;
    int base = t * 8;
    int loc[8];
    int s = 0;
#pragma unroll
    for (int i = 0; i < 8; i++) { loc[i] = s; s += g_cnt[base + i]; }
    part[t] = s;
    __syncthreads();
    int val = s;
    for (int off = 1; off < 1024; off <<= 1) {
        int v = (t >= off) ? part[t - off] : 0;
        __syncthreads();
        val += v;
        part[t] = val;
        __syncthreads();
    }
    int pre = (t == 0) ? 0 : part[t - 1];
#pragma unroll
    for (int i = 0; i < 8; i++) g_offm[base + i] = pre + loc[i];
}

__global__ void k_place(const int* __restrict__ ei) {
    int e = blockIdx.x * blockDim.x + threadIdx.x;
    if (e < EE) {
        int c = ei[EE + e];
        int p = atomicAdd(&g_offm[c], 1);
        g_perm[p] = e;
    }
}

__global__ void k_build(const int* __restrict__ ei, const float* __restrict__ ew,
                        const float* __restrict__ means, const float* __restrict__ betas) {
    int warp = (blockIdx.x * blockDim.x + threadIdx.x) >> 5;
    int lane = threadIdx.x & 31;
    if (warp >= EE) return;
    int e = g_perm[warp];
    int r = ei[e];
    int c = ei[EE + e];
    float d = ew[e];
    float cut = 0.5f * (cosf(d * 0.628318530717958647692f) + 1.0f);
    if (!(d < 5.0f)) cut = 0.f;
    float ex = __expf(-d);
    size_t ro = (size_t)warp * RBF_P;
    {
        float m = means[lane], b = betas[lane];
        float v = ex - m;
        g_rbf[ro + lane] = cut * __expf(-b * v * v);
    }
    int k2 = lane + 32;
    if (k2 < NRBF) {
        float m = means[k2], b = betas[k2];
        float v = ex - m;
        g_rbf[ro + k2] = cut * __expf(-b * v * v);
    } else if (k2 < RBF_P) {
        g_rbf[ro + k2] = 0.f;
    }
    if (lane == 0) {
        g_cut[warp]  = cut;
        g_cutm[warp] = (r != c) ? cut : 0.f;
        g_srow[warp] = r;
        g_sdst[warp] = c;
    }
}

__global__ void k_gather(const int* __restrict__ z, const float* __restrict__ emb,
                         const float* __restrict__ neemb) {
    int i = blockIdx.x * blockDim.x + threadIdx.x;
    if (i >= NN * HID) return;
    int n = i >> 7, c = i & 127;
    int zi = z[n];
    g_x[i]   = emb[zi * HID + c];
    g_nex[i] = neemb[zi * HID + c];
}

// ---------------- fused edge MLP + segmented aggregation ----------------
// 512-thread block; GEMMs run on threads 0..255 with 8x8 register tiles,
// K-pair blocking, row-major A (float2 loads), row-major B (float4 loads).
// NE=1: F = (rbf@W1 + b1) * cutm ; msg = nex[row]*F
// NE=0: F = (silu(rbf@W1+b1)@W2 + b2) * cut ; msg = h[row]*F
template <int NE>
__global__ void __launch_bounds__(512, 1)
k_edge(const float* __restrict__ W1g, const float* __restrict__ b1g,
       const float* __restrict__ W2g, const float* __restrict__ b2g) {
    extern __shared__ float sm[];
    const int W1SZ = K1P * HID;                  // 6656 (rows 50,51 zeroed)
    const int W2SZ = NE ? 0 : HID * HID;         // 16384
    float* sW1  = sm;                            // [52][128] row-major
    float* sW2  = sW1 + W1SZ;                    // [128][128] row-major
    float* sRbf = sW2 + W2SZ;                    // [128][52] row-major
    float* sT   = sRbf + 128 * RBF_P;            // [128][132]; silu acts, reused as F
    float* sB1  = sT + 128 * 132;
    float* sB2  = sB1 + 128;
    float* sCut = sB2 + 128;
    int*   sRow = (int*)(sCut + 128);
    int*   sDst = sRow + 128;

    int tid = threadIdx.x;
    long ebase = (long)blockIdx.x * 128;

    // ---- stage ----
    for (int i = tid; i < W1SZ; i += 512)
        sW1[i] = (i < NRBF * HID) ? W1g[i] : 0.f;
    if (!NE)
        for (int i = tid; i < HID * HID; i += 512) sW2[i] = W2g[i];
    for (int i = tid; i < 128 * RBF_P; i += 512) sRbf[i] = g_rbf[ebase * RBF_P + i];
    if (tid < 128) {
        sB1[tid]  = b1g[tid];
        sB2[tid]  = NE ? 0.f : b2g[tid];
        sCut[tid] = NE ? g_cutm[ebase + tid] : g_cut[ebase + tid];
        sRow[tid] = g_srow[ebase + tid];
        sDst[tid] = g_sdst[ebase + tid];
    }
    __syncthreads();

    // GEMM thread mapping: 256 threads, 8 rows x 8 cols each
    int tx = tid & 15, ty = (tid >> 4) & 15;
    int r0 = ty * 8, c0 = tx * 8;

    // ---- GEMM1: rbf[128,52] @ W1[52,128] ----
    if (tid < 256) {
        float acc[8][8];
#pragma unroll
        for (int i = 0; i < 8; i++)
#pragma unroll
            for (int j = 0; j < 8; j++) acc[i][j] = 0.f;

#pragma unroll 2
        for (int kp = 0; kp < K1P / 2; kp++) {
            float2 a[8];
#pragma unroll
            for (int i = 0; i < 8; i++)
                a[i] = *(const float2*)&sRbf[(r0 + i) * RBF_P + 2 * kp];
            float4 b0 = *(const float4*)&sW1[(2 * kp) * HID + c0];
            float4 b1 = *(const float4*)&sW1[(2 * kp) * HID + c0 + 4];
            float4 b2 = *(const float4*)&sW1[(2 * kp + 1) * HID + c0];
            float4 b3 = *(const float4*)&sW1[(2 * kp + 1) * HID + c0 + 4];
            float bb0[8] = {b0.x, b0.y, b0.z, b0.w, b1.x, b1.y, b1.z, b1.w};
            float bb1[8] = {b2.x, b2.y, b2.z, b2.w, b3.x, b3.y, b3.z, b3.w};
#pragma unroll
            for (int i = 0; i < 8; i++) {
#pragma unroll
                for (int j = 0; j < 8; j++) acc[i][j] = fmaf(a[i].x, bb0[j], acc[i][j]);
#pragma unroll
                for (int j = 0; j < 8; j++) acc[i][j] = fmaf(a[i].y, bb1[j], acc[i][j]);
            }
        }

        if (NE) {
            // F = (acc + b1) * cutm, float4 stores
#pragma unroll
            for (int i = 0; i < 8; i++) {
                float cu = sCut[r0 + i];
                float4 v0, v1;
                v0.x = (acc[i][0] + sB1[c0 + 0]) * cu;
                v0.y = (acc[i][1] + sB1[c0 + 1]) * cu;
                v0.z = (acc[i][2] + sB1[c0 + 2]) * cu;
                v0.w = (acc[i][3] + sB1[c0 + 3]) * cu;
                v1.x = (acc[i][4] + sB1[c0 + 4]) * cu;
                v1.y = (acc[i][5] + sB1[c0 + 5]) * cu;
                v1.z = (acc[i][6] + sB1[c0 + 6]) * cu;
                v1.w = (acc[i][7] + sB1[c0 + 7]) * cu;
                *(float4*)&sT[(r0 + i) * 132 + c0]     = v0;
                *(float4*)&sT[(r0 + i) * 132 + c0 + 4] = v1;
            }
        } else {
            // silu -> sT
#pragma unroll
            for (int i = 0; i < 8; i++) {
                float v[8];
#pragma unroll
                for (int j = 0; j < 8; j++) {
                    float t = acc[i][j] + sB1[c0 + j];
                    v[j] = t / (1.0f + __expf(-t));
                }
                *(float4*)&sT[(r0 + i) * 132 + c0]     = make_float4(v[0], v[1], v[2], v[3]);
                *(float4*)&sT[(r0 + i) * 132 + c0 + 4] = make_float4(v[4], v[5], v[6], v[7]);
            }
        }
    }
    __syncthreads();

    // ---- GEMM2 (interaction only): T[128,128] @ W2[128,128] ----
    if (!NE && tid < 256) {
        float acc[8][8];
#pragma unroll
        for (int i = 0; i < 8; i++)
#pragma unroll
            for (int j = 0; j < 8; j++) acc[i][j] = 0.f;

#pragma unroll 2
        for (int kp = 0; kp < HID / 2; kp++) {
            float2 a[8];
#pragma unroll
            for (int i = 0; i < 8; i++)
                a[i] = *(const float2*)&sT[(r0 + i) * 132 + 2 * kp];
            float4 b0 = *(const float4*)&sW2[(2 * kp) * HID + c0];
            float4 b1 = *(const float4*)&sW2[(2 * kp) * HID + c0 + 4];
            float4 b2 = *(const float4*)&sW2[(2 * kp + 1) * HID + c0];
            float4 b3 = *(const float4*)&sW2[(2 * kp + 1) * HID + c0 + 4];
            float bb0[8] = {b0.x, b0.y, b0.z, b0.w, b1.x, b1.y, b1.z, b1.w};
            float bb1[8] = {b2.x, b2.y, b2.z, b2.w, b3.x, b3.y, b3.z, b3.w};
#pragma unroll
            for (int i = 0; i < 8; i++) {
#pragma unroll
                for (int j = 0; j < 8; j++) acc[i][j] = fmaf(a[i].x, bb0[j], acc[i][j]);
#pragma unroll
                for (int j = 0; j < 8; j++) acc[i][j] = fmaf(a[i].y, bb1[j], acc[i][j]);
            }
        }
        __syncthreads();   // all T reads done before overwrite (paired below for tid>=256)

        // F = (acc + b2) * cut  -> overwrite sT
#pragma unroll
        for (int i = 0; i < 8; i++) {
            float cu = sCut[r0 + i];
            float4 v0, v1;
            v0.x = (acc[i][0] + sB2[c0 + 0]) * cu;
            v0.y = (acc[i][1] + sB2[c0 + 1]) * cu;
            v0.z = (acc[i][2] + sB2[c0 + 2]) * cu;
            v0.w = (acc[i][3] + sB2[c0 + 3]) * cu;
            v1.x = (acc[i][4] + sB2[c0 + 4]) * cu;
            v1.y = (acc[i][5] + sB2[c0 + 5]) * cu;
            v1.z = (acc[i][6] + sB2[c0 + 6]) * cu;
            v1.w = (acc[i][7] + sB2[c0 + 7]) * cu;
            *(float4*)&sT[(r0 + i) * 132 + c0]     = v0;
            *(float4*)&sT[(r0 + i) * 132 + c0 + 4] = v1;
        }
    } else if (!NE) {
        __syncthreads();   // matching barrier for tid >= 256
    }
    __syncthreads();

    // ---- segmented aggregation: 4 groups x 128 channels, 32 edges/group ----
    const float* hsrc = NE ? g_nex : g_h;
    int g = tid >> 7;
    int f = tid & 127;
    int e0 = g * 32;
    float accv = 0.f;
    int cur = sDst[e0];
#pragma unroll 1
    for (int b = 0; b < 4; b++) {
        float hb[8];
#pragma unroll
        for (int j = 0; j < 8; j++)
            hb[j] = hsrc[(long)sRow[e0 + b * 8 + j] * HID + f];
#pragma unroll
        for (int j = 0; j < 8; j++) {
            int e = e0 + b * 8 + j;
            int dd = sDst[e];
            if (dd != cur) {
                atomicAdd(&g_agg[(long)cur * HID + f], accv);
                accv = 0.f;
                cur = dd;
            }
            accv = fmaf(hb[j], sT[e * 132 + f], accv);
        }
    }
    atomicAdd(&g_agg[(long)cur * HID + f], accv);
}

// ---------------- generic node GEMM: out = base + act(A @ W + bias) ----------------
__device__ __forceinline__ float* selp(int s, float* dout) {
    switch (s) {
        case 0: return g_x;
        case 1: return g_h;
        case 2: return g_h2;
        case 3: return g_agg;
        default: return dout;
    }
}

__global__ void __launch_bounds__(256, 1)
k_ngemm(int Asel, const float* __restrict__ Wg, const float* __restrict__ bias,
        int baseSel, int outSel, int silu, float* dout) {
    extern __shared__ float sm[];
    float* sA = sm;                    // 64 x 132
    float* sW = sA + 64 * 132;         // 128 x 128
    float* sB = sW + HID * HID;        // 128
    const float* A = selp(Asel, dout);
    float* out = selp(outSel, dout);
    const float* base = (baseSel >= 0) ? selp(baseSel, dout) : nullptr;

    int tid = threadIdx.x;
    int rb = blockIdx.x * 64;
    for (int i = tid; i < 64 * HID; i += 256) {
        int r = i >> 7, k = i & 127;
        sA[r * 132 + k] = A[(long)(rb + r) * HID + k];
    }
    for (int i = tid; i < HID * HID; i += 256) sW[i] = Wg[i];
    if (tid < 128) sB[tid] = bias ? bias[tid] : 0.f;
    __syncthreads();

    int tx = tid & 15, ty = tid >> 4;
    int r0 = ty * 4, c0 = tx * 8;
    float acc[4][8];
#pragma unroll
    for (int i = 0; i < 4; i++)
#pragma unroll
        for (int j = 0; j < 8; j++) acc[i][j] = 0.f;
#pragma unroll 2
    for (int kp = 0; kp < HID / 2; kp++) {
        float2 a[4];
#pragma unroll
        for (int i = 0; i < 4; i++)
            a[i] = *(const float2*)&sA[(r0 + i) * 132 + 2 * kp];
        float4 b0 = *(const float4*)&sW[(2 * kp) * HID + c0];
        float4 b1 = *(const float4*)&sW[(2 * kp) * HID + c0 + 4];
        float4 b2 = *(const float4*)&sW[(2 * kp + 1) * HID + c0];
        float4 b3 = *(const float4*)&sW[(2 * kp + 1) * HID + c0 + 4];
        float bb0[8] = {b0.x, b0.y, b0.z, b0.w, b1.x, b1.y, b1.z, b1.w};
        float bb1[8] = {b2.x, b2.y, b2.z, b2.w, b3.x, b3.y, b3.z, b3.w};
#pragma unroll
        for (int i = 0; i < 4; i++) {
#pragma unroll
            for (int j = 0; j < 8; j++) acc[i][j] = fmaf(a[i].x, bb0[j], acc[i][j]);
#pragma unroll
            for (int j = 0; j < 8; j++) acc[i][j] = fmaf(a[i].y, bb1[j], acc[i][j]);
        }
    }
#pragma unroll
    for (int i = 0; i < 4; i++) {
        long ro = (long)(rb + r0 + i) * HID;
#pragma unroll
        for (int j = 0; j < 8; j++) {
            float v = acc[i][j] + sB[c0 + j];
            if (silu) v = v / (1.0f + __expf(-v));
            if (base) v += base[ro + c0 + j];
            out[ro + c0 + j] = v;
        }
    }
}

// ---------------- launch ----------------
extern "C" void kernel_launch(void* const* d_in, const int* in_sizes, int n_in,
                              void* d_out, int out_size) {
    const int*   z       = (const int*)d_in[0];
    const int*   ei      = (const int*)d_in[1];
    const float* ew      = (const float*)d_in[2];
    const float* emb     = (const float*)d_in[3];
    const float* neemb   = (const float*)d_in[4];
    const float* neprojw = (const float*)d_in[5];
    const float* neprojb = (const float*)d_in[6];
    const float* necatw  = (const float*)d_in[7];
    const float* necatb  = (const float*)d_in[8];
    const float* means   = (const float*)d_in[9];
    const float* betas   = (const float*)d_in[10];
    const float* mlpw1   = (const float*)d_in[11];
    const float* mlpb1   = (const float*)d_in[12];
    const float* mlpw2   = (const float*)d_in[13];
    const float* mlpb2   = (const float*)d_in[14];
    const float* lin1w   = (const float*)d_in[15];
    const float* lin2w   = (const float*)d_in[16];
    const float* lin2b   = (const float*)d_in[17];
    const float* linw    = (const float*)d_in[18];
    const float* linb    = (const float*)d_in[19];
    float* outp = (float*)d_out;

    const size_t smI = (size_t)(K1P * HID + HID * HID + 128 * RBF_P + 128 * 132 + 3 * 128) * 4
                       + 2 * 128 * 4;
    const size_t smN = (size_t)(K1P * HID + 128 * RBF_P + 128 * 132 + 3 * 128) * 4
                       + 2 * 128 * 4;
    const size_t smG = (size_t)(64 * 132 + HID * HID + 128) * 4;

    cudaFuncSetAttribute(k_edge<0>, cudaFuncAttributeMaxDynamicSharedMemorySize, (int)smI);
    cudaFuncSetAttribute(k_edge<1>, cudaFuncAttributeMaxDynamicSharedMemorySize, (int)smN);
    cudaFuncSetAttribute(k_ngemm,   cudaFuncAttributeMaxDynamicSharedMemorySize, (int)smG);

    // ---- sort edges by destination + precompute per-edge data ----
    k_zero_cnt<<<NN / 256, 256>>>();
    k_hist<<<EE / 256, 256>>>(ei);
    k_scan<<<1, 1024>>>();
    k_place<<<EE / 256, 256>>>(ei);
    k_build<<<EE / 8, 256>>>(ei, ew, means, betas);
    k_gather<<<NN * HID / 256, 256>>>(z, emb, neemb);

    // ---- NeighborEmbedding ----
    k_zero_agg<<<NN * HID / 256, 256>>>();
    k_edge<1><<<EE / 128, 512, smN>>>(neprojw, neprojb, nullptr, nullptr);
    k_ngemm<<<NN / 64, 256, smG>>>(0, necatw, necatb, -1, 2, 0, outp);
    k_ngemm<<<NN / 64, 256, smG>>>(3, necatw + HID * HID, nullptr, 2, 0, 0, outp);

    // ---- interaction layers ----
    for (int l = 0; l < NLAY; l++) {
        k_zero_agg<<<NN * HID / 256, 256>>>();
        k_ngemm<<<NN / 64, 256, smG>>>(0, lin1w + (size_t)l * HID * HID, nullptr, -1, 1, 0, outp);
        k_edge<0><<<EE / 128, 512, smI>>>(mlpw1 + (size_t)l * NRBF * HID, mlpb1 + (size_t)l * HID,
                                          mlpw2 + (size_t)l * HID * HID, mlpb2 + (size_t)l * HID);
        k_ngemm<<<NN / 64, 256, smG>>>(3, lin2w + (size_t)l * HID * HID, lin2b + (size_t)l * HID,
                                       -1, 2, 1, outp);
        k_ngemm<<<NN / 64, 256, smG>>>(2, linw + (size_t)l * HID * HID, linb + (size_t)l * HID,
                                       0, (l == NLAY - 1) ? 4 : 0, 0, outp);
    }
}

// round 4
// speedup vs baseline: 2.4151x; 1.3344x over previous
#include <cuda_runtime.h>
#include <cuda_bf16.h>
#include <math.h>

// ---------------- problem constants ----------------
#define NN    8192
#define EE    262144
#define HID   128
#define NRBF  50
#define K1    64           // padded K for GEMM1 (50 -> 64)
#define NLAY  6
#define PR    72           // smem pitch (bf16) for rbf / W1^T  (bank-safe)
#define PT    136          // smem pitch (bf16) for T / W2^T    (bank-safe)
#define PF    132          // smem pitch (f32) for F tile

typedef __nv_bfloat16  bf16;
typedef __nv_bfloat162 bf162;

// ---------------- device scratch ----------------
__device__ bf16 g_rbf_hi[(size_t)EE * K1];
__device__ bf16 g_rbf_lo[(size_t)EE * K1];
__device__ bf16 g_w1t_hi[NLAY * HID * K1];
__device__ bf16 g_w1t_lo[NLAY * HID * K1];
__device__ bf16 g_w2t_hi[NLAY * HID * HID];
__device__ bf16 g_w2t_lo[NLAY * HID * HID];
__device__ bf16 g_npt_hi[HID * K1];
__device__ bf16 g_npt_lo[HID * K1];
__device__ float g_cut[EE];
__device__ float g_cutm[EE];
__device__ int   g_srow[EE];
__device__ int   g_sdst[EE];
__device__ int   g_perm[EE];
__device__ int   g_cnt[NN];
__device__ int   g_offm[NN];
__device__ float g_x  [NN * HID];
__device__ float g_h  [NN * HID];
__device__ float g_h2 [NN * HID];
__device__ float g_agg[NN * HID];
__device__ float g_nex[NN * HID];

// ---------------- small helper kernels ----------------
__global__ void k_zero_cnt() {
    int i = blockIdx.x * blockDim.x + threadIdx.x;
    if (i < NN) g_cnt[i] = 0;
}

__global__ void k_zero_agg() {
    int i = blockIdx.x * blockDim.x + threadIdx.x;
    if (i < NN * HID) g_agg[i] = 0.f;
}

__global__ void k_hist(const int* __restrict__ ei) {
    int e = blockIdx.x * blockDim.x + threadIdx.x;
    if (e < EE) atomicAdd(&g_cnt[ei[EE + e]], 1);
}

__global__ void k_scan() {
    __shared__ int part[1024];
    int t = threadIdx.x;
    int base = t * 8;
    int loc[8];
    int s = 0;
#pragma unroll
    for (int i = 0; i < 8; i++) { loc[i] = s; s += g_cnt[base + i]; }
    part[t] = s;
    __syncthreads();
    int val = s;
    for (int off = 1; off < 1024; off <<= 1) {
        int v = (t >= off) ? part[t - off] : 0;
        __syncthreads();
        val += v;
        part[t] = val;
        __syncthreads();
    }
    int pre = (t == 0) ? 0 : part[t - 1];
#pragma unroll
    for (int i = 0; i < 8; i++) g_offm[base + i] = pre + loc[i];
}

__global__ void k_place(const int* __restrict__ ei) {
    int e = blockIdx.x * blockDim.x + threadIdx.x;
    if (e < EE) {
        int c = ei[EE + e];
        int p = atomicAdd(&g_offm[c], 1);
        g_perm[p] = e;
    }
}

// one warp per sorted edge: rbf hi/lo bf16 (K padded to 64), cut, srow/sdst
__global__ void k_build(const int* __restrict__ ei, const float* __restrict__ ew,
                        const float* __restrict__ means, const float* __restrict__ betas) {
    int warp = (blockIdx.x * blockDim.x + threadIdx.x) >> 5;
    int lane = threadIdx.x & 31;
    if (warp >= EE) return;
    int e = g_perm[warp];
    int r = ei[e];
    int c = ei[EE + e];
    float d = ew[e];
    float cut = 0.5f * (cosf(d * 0.628318530717958647692f) + 1.0f);
    if (!(d < 5.0f)) cut = 0.f;
    float ex = __expf(-d);
    size_t ro = (size_t)warp * K1;
    {
        float m = means[lane], b = betas[lane];      // lane < 32 < 50
        float v = ex - m;
        float val = cut * __expf(-b * v * v);
        bf16 hi = __float2bfloat16(val);
        g_rbf_hi[ro + lane] = hi;
        g_rbf_lo[ro + lane] = __float2bfloat16(val - __bfloat162float(hi));
    }
    int k2 = lane + 32;
    float val2 = 0.f;
    if (k2 < NRBF) {
        float m = means[k2], b = betas[k2];
        float v = ex - m;
        val2 = cut * __expf(-b * v * v);
    }
    bf16 hi2 = __float2bfloat16(val2);
    g_rbf_hi[ro + k2] = hi2;
    g_rbf_lo[ro + k2] = __float2bfloat16(val2 - __bfloat162float(hi2));
    if (lane == 0) {
        g_cut[warp]  = cut;
        g_cutm[warp] = (r != c) ? cut : 0.f;
        g_srow[warp] = r;
        g_sdst[warp] = c;
    }
}

__global__ void k_gather(const int* __restrict__ z, const float* __restrict__ emb,
                         const float* __restrict__ neemb) {
    int i = blockIdx.x * blockDim.x + threadIdx.x;
    if (i >= NN * HID) return;
    int n = i >> 7, c = i & 127;
    int zi = z[n];
    g_x[i]   = emb[zi * HID + c];
    g_nex[i] = neemb[zi * HID + c];
}

// weight prep: transpose + bf16 hi/lo split
// mode 0: mlp_w1 [NLAY][50][128] -> g_w1t [NLAY][128][64]
// mode 1: ne_proj [50][128]      -> g_npt [128][64]
__global__ void k_wprep1(const float* __restrict__ w, int mode, int layers) {
    int i = blockIdx.x * blockDim.x + threadIdx.x;
    if (i >= layers * HID * K1) return;
    int k = i & (K1 - 1);
    int n = (i >> 6) & (HID - 1);
    int l = i >> 13;
    float v = (k < NRBF) ? w[((size_t)l * NRBF + k) * HID + n] : 0.f;
    bf16 hi = __float2bfloat16(v);
    bf16 lo = __float2bfloat16(v - __bfloat162float(hi));
    if (mode == 0) { g_w1t_hi[i] = hi; g_w1t_lo[i] = lo; }
    else           { g_npt_hi[i] = hi; g_npt_lo[i] = lo; }
}

// mlp_w2 [NLAY][128][128] -> g_w2t [NLAY][128][128] (transposed per layer)
__global__ void k_wprep2(const float* __restrict__ w) {
    int i = blockIdx.x * blockDim.x + threadIdx.x;
    if (i >= NLAY * HID * HID) return;
    int k = i & (HID - 1);
    int n = (i >> 7) & (HID - 1);
    int l = i >> 14;
    float v = w[((size_t)l * HID + k) * HID + n];
    bf16 hi = __float2bfloat16(v);
    g_w2t_hi[i] = hi;
    g_w2t_lo[i] = __float2bfloat16(v - __bfloat162float(hi));
}

// ---------------- warp-MMA helpers ----------------
__device__ __forceinline__ void mma16816(float c[4], const unsigned a[4], const unsigned b[2]) {
    asm volatile(
        "mma.sync.aligned.m16n8k16.row.col.f32.bf16.bf16.f32 "
        "{%0,%1,%2,%3}, {%4,%5,%6,%7}, {%8,%9}, {%0,%1,%2,%3};\n"
        : "+f"(c[0]), "+f"(c[1]), "+f"(c[2]), "+f"(c[3])
        : "r"(a[0]), "r"(a[1]), "r"(a[2]), "r"(a[3]), "r"(b[0]), "r"(b[1]));
}

// compensated bf16 GEMM: acc += A*B with A=Ahi+Alo, B=Bhi+Blo (drop lo*lo)
// warp computes rows [m0,m0+16) x cols [n0,n0+64); A pitch/B pitch = P (bf16)
template <int KSTEPS, int P>
__device__ __forceinline__ void wgemm(const bf16* __restrict__ Ahi, const bf16* __restrict__ Alo,
                                      const bf16* __restrict__ Bhi, const bf16* __restrict__ Blo,
                                      float acc[8][4], int m0, int n0, int lane) {
    int g = lane >> 2, tc = lane & 3;
#pragma unroll
    for (int s = 0; s < 3; s++) {
        const bf16* A = (s == 2) ? Alo : Ahi;
        const bf16* B = (s == 1) ? Blo : Bhi;
#pragma unroll
        for (int ks = 0; ks < KSTEPS; ks++) {
            int k0 = ks * 16;
            const bf16* pa = A + (m0 + g) * P + k0 + 2 * tc;
            unsigned a[4];
            a[0] = *(const unsigned*)pa;
            a[1] = *(const unsigned*)(pa + 8 * P);
            a[2] = *(const unsigned*)(pa + 8);
            a[3] = *(const unsigned*)(pa + 8 * P + 8);
#pragma unroll
            for (int nt = 0; nt < 8; nt++) {
                const bf16* pb = B + (n0 + nt * 8 + g) * P + k0 + 2 * tc;
                unsigned b[2];
                b[0] = *(const unsigned*)pb;
                b[1] = *(const unsigned*)(pb + 8);
                mma16816(acc[nt], a, b);
            }
        }
    }
}

// ---------------- fused edge MLP + segmented aggregation (tensor-core) -------
// NE=1: F = (rbf@W1 + b1) * cutm ; msg = nex[row]*F
// NE=0: F = (silu(rbf@W1+b1)@W2 + b2) * cut ; msg = h[row]*F
template <int NE>
__global__ void __launch_bounds__(512, 1)
k_edge(int layer, const float* __restrict__ b1g, const float* __restrict__ b2g) {
    extern __shared__ __align__(16) char smref[];
    // byte offsets
    const int OFF_THI  = 0;
    const int OFF_TLO  = OFF_THI + HID * PT * 2;          // 34816
    const int OFF_W2HI = OFF_TLO + HID * PT * 2;          // 69632
    const int OFF_W2LO = OFF_W2HI + HID * PT * 2;         // 104448
    const int OFF_RA   = NE ? 0 : (OFF_W2LO + HID * PT * 2);  // 139264 (interaction)
    const int OFF_RHI  = OFF_RA;
    const int OFF_RLO  = OFF_RHI + HID * PR * 2;          // +18432
    const int OFF_W1HI = OFF_RLO + HID * PR * 2;
    const int OFF_W1LO = OFF_W1HI + HID * PR * 2;
    const int OFF_F    = NE ? (OFF_W1LO + HID * PR * 2) : OFF_RA;   // overlay in interaction
    const int OFF_SM   = NE ? (OFF_F + HID * PF * 4)
                            : (OFF_RA + 4 * HID * PR * 2);

    bf16* sThi  = (bf16*)(smref + OFF_THI);
    bf16* sTlo  = (bf16*)(smref + OFF_TLO);
    bf16* sW2hi = (bf16*)(smref + OFF_W2HI);
    bf16* sW2lo = (bf16*)(smref + OFF_W2LO);
    bf16* sRhi  = (bf16*)(smref + OFF_RHI);
    bf16* sRlo  = (bf16*)(smref + OFF_RLO);
    bf16* sW1hi = (bf16*)(smref + OFF_W1HI);
    bf16* sW1lo = (bf16*)(smref + OFF_W1LO);
    float* sF   = (float*)(smref + OFF_F);
    float* sB1  = (float*)(smref + OFF_SM);
    float* sB2  = sB1 + 128;
    float* sCut = sB2 + 128;
    int*   sRow = (int*)(sCut + 128);
    int*   sDst = sRow + 128;

    int tid = threadIdx.x;
    long ebase = (long)blockIdx.x * 128;

    // ---- stage rbf hi/lo (global pitch 64 -> smem pitch 72) ----
    {
        const unsigned* ghi = (const unsigned*)(g_rbf_hi + ebase * K1);
        const unsigned* glo = (const unsigned*)(g_rbf_lo + ebase * K1);
        unsigned* shi = (unsigned*)sRhi;
        unsigned* slo = (unsigned*)sRlo;
        for (int i = tid; i < 128 * 32; i += 512) {
            int r = i >> 5, wd = i & 31;
            shi[r * (PR / 2) + wd] = ghi[i];
            slo[r * (PR / 2) + wd] = glo[i];
        }
    }
    // ---- stage W1^T hi/lo ----
    {
        const unsigned* ghi = (const unsigned*)(NE ? g_npt_hi : g_w1t_hi + (size_t)layer * HID * K1);
        const unsigned* glo = (const unsigned*)(NE ? g_npt_lo : g_w1t_lo + (size_t)layer * HID * K1);
        unsigned* shi = (unsigned*)sW1hi;
        unsigned* slo = (unsigned*)sW1lo;
        for (int i = tid; i < 128 * 32; i += 512) {
            int r = i >> 5, wd = i & 31;
            shi[r * (PR / 2) + wd] = ghi[i];
            slo[r * (PR / 2) + wd] = glo[i];
        }
    }
    // ---- stage W2^T hi/lo (interaction only) ----
    if (!NE) {
        const unsigned* ghi = (const unsigned*)(g_w2t_hi + (size_t)layer * HID * HID);
        const unsigned* glo = (const unsigned*)(g_w2t_lo + (size_t)layer * HID * HID);
        unsigned* shi = (unsigned*)sW2hi;
        unsigned* slo = (unsigned*)sW2lo;
        for (int i = tid; i < 128 * 64; i += 512) {
            int r = i >> 6, wd = i & 63;
            shi[r * (PT / 2) + wd] = ghi[i];
            slo[r * (PT / 2) + wd] = glo[i];
        }
    }
    if (tid < 128) {
        sB1[tid]  = b1g[tid];
        sB2[tid]  = NE ? 0.f : b2g[tid];
        sCut[tid] = NE ? g_cutm[ebase + tid] : g_cut[ebase + tid];
        sRow[tid] = g_srow[ebase + tid];
        sDst[tid] = g_sdst[ebase + tid];
    }
    __syncthreads();

    // warp tiling: 16 warps; warp w -> rows [(w&7)*16, +16), cols [(w>>3)*64, +64)
    int w = tid >> 5, lane = tid & 31;
    int m0 = (w & 7) * 16, n0 = (w >> 3) * 64;
    int g = lane >> 2, tc = lane & 3;

    // ---- GEMM1: rbf[128,64] @ W1[64,128] ----
    {
        float acc[8][4];
#pragma unroll
        for (int i = 0; i < 8; i++)
#pragma unroll
            for (int j = 0; j < 4; j++) acc[i][j] = 0.f;
        wgemm<K1 / 16, PR>(sRhi, sRlo, sW1hi, sW1lo, acc, m0, n0, lane);

        if (NE) {
            // F = (acc + b1) * cutm -> sF (fp32)  [F region separate in NE]
            float cu0 = sCut[m0 + g], cu1 = sCut[m0 + g + 8];
#pragma unroll
            for (int nt = 0; nt < 8; nt++) {
                int col = n0 + nt * 8 + 2 * tc;
                float2 v0, v1;
                v0.x = (acc[nt][0] + sB1[col])     * cu0;
                v0.y = (acc[nt][1] + sB1[col + 1]) * cu0;
                v1.x = (acc[nt][2] + sB1[col])     * cu1;
                v1.y = (acc[nt][3] + sB1[col + 1]) * cu1;
                *(float2*)&sF[(m0 + g) * PF + col]     = v0;
                *(float2*)&sF[(m0 + g + 8) * PF + col] = v1;
            }
        } else {
            // T = silu(acc + b1) -> bf16 hi/lo
#pragma unroll
            for (int nt = 0; nt < 8; nt++) {
                int col = n0 + nt * 8 + 2 * tc;
                float x0 = acc[nt][0] + sB1[col];
                float x1 = acc[nt][1] + sB1[col + 1];
                float x2 = acc[nt][2] + sB1[col];
                float x3 = acc[nt][3] + sB1[col + 1];
                x0 = x0 / (1.f + __expf(-x0));
                x1 = x1 / (1.f + __expf(-x1));
                x2 = x2 / (1.f + __expf(-x2));
                x3 = x3 / (1.f + __expf(-x3));
                bf162 h0, h1, l0, l1;
                h0.x = __float2bfloat16(x0); h0.y = __float2bfloat16(x1);
                h1.x = __float2bfloat16(x2); h1.y = __float2bfloat16(x3);
                l0.x = __float2bfloat16(x0 - __bfloat162float(h0.x));
                l0.y = __float2bfloat16(x1 - __bfloat162float(h0.y));
                l1.x = __float2bfloat16(x2 - __bfloat162float(h1.x));
                l1.y = __float2bfloat16(x3 - __bfloat162float(h1.y));
                *(bf162*)&sThi[(m0 + g) * PT + col]     = h0;
                *(bf162*)&sThi[(m0 + g + 8) * PT + col] = h1;
                *(bf162*)&sTlo[(m0 + g) * PT + col]     = l0;
                *(bf162*)&sTlo[(m0 + g + 8) * PT + col] = l1;
            }
        }
    }
    __syncthreads();

    // ---- GEMM2 (interaction only): T[128,128] @ W2[128,128] ----
    if (!NE) {
        float acc[8][4];
#pragma unroll
        for (int i = 0; i < 8; i++)
#pragma unroll
            for (int j = 0; j < 4; j++) acc[i][j] = 0.f;
        wgemm<HID / 16, PT>(sThi, sTlo, sW2hi, sW2lo, acc, m0, n0, lane);

        // F = (acc + b2) * cut -> sF (overlays rbf/W1 region; safe post-sync)
        float cu0 = sCut[m0 + g], cu1 = sCut[m0 + g + 8];
#pragma unroll
        for (int nt = 0; nt < 8; nt++) {
            int col = n0 + nt * 8 + 2 * tc;
            float2 v0, v1;
            v0.x = (acc[nt][0] + sB2[col])     * cu0;
            v0.y = (acc[nt][1] + sB2[col + 1]) * cu0;
            v1.x = (acc[nt][2] + sB2[col])     * cu1;
            v1.y = (acc[nt][3] + sB2[col + 1]) * cu1;
            *(float2*)&sF[(m0 + g) * PF + col]     = v0;
            *(float2*)&sF[(m0 + g + 8) * PF + col] = v1;
        }
    }
    __syncthreads();

    // ---- segmented aggregation: 4 groups x 128 channels, 32 edges/group ----
    const float* hsrc = NE ? g_nex : g_h;
    int grp = tid >> 7;
    int f = tid & 127;
    int e0 = grp * 32;
    float accv = 0.f;
    int cur = sDst[e0];
#pragma unroll 1
    for (int b = 0; b < 4; b++) {
        float hb[8];
#pragma unroll
        for (int j = 0; j < 8; j++)
            hb[j] = hsrc[(long)sRow[e0 + b * 8 + j] * HID + f];
#pragma unroll
        for (int j = 0; j < 8; j++) {
            int e = e0 + b * 8 + j;
            int dd = sDst[e];
            if (dd != cur) {
                atomicAdd(&g_agg[(long)cur * HID + f], accv);
                accv = 0.f;
                cur = dd;
            }
            accv = fmaf(hb[j], sF[e * PF + f], accv);
        }
    }
    atomicAdd(&g_agg[(long)cur * HID + f], accv);
}

// ---------------- generic node GEMM: out = base + act(A @ W + bias) ----------------
__device__ __forceinline__ float* selp(int s, float* dout) {
    switch (s) {
        case 0: return g_x;
        case 1: return g_h;
        case 2: return g_h2;
        case 3: return g_agg;
        default: return dout;
    }
}

__global__ void __launch_bounds__(256, 1)
k_ngemm(int Asel, const float* __restrict__ Wg, const float* __restrict__ bias,
        int baseSel, int outSel, int silu, float* dout) {
    extern __shared__ float sm[];
    float* sA = sm;                    // 64 x 132
    float* sW = sA + 64 * 132;         // 128 x 128
    float* sB = sW + HID * HID;        // 128
    const float* A = selp(Asel, dout);
    float* out = selp(outSel, dout);
    const float* base = (baseSel >= 0) ? selp(baseSel, dout) : nullptr;

    int tid = threadIdx.x;
    int rb = blockIdx.x * 64;
    for (int i = tid; i < 64 * HID; i += 256) {
        int r = i >> 7, k = i & 127;
        sA[r * 132 + k] = A[(long)(rb + r) * HID + k];
    }
    for (int i = tid; i < HID * HID; i += 256) sW[i] = Wg[i];
    if (tid < 128) sB[tid] = bias ? bias[tid] : 0.f;
    __syncthreads();

    int tx = tid & 15, ty = tid >> 4;
    int r0 = ty * 4, c0 = tx * 8;
    float acc[4][8];
#pragma unroll
    for (int i = 0; i < 4; i++)
#pragma unroll
        for (int j = 0; j < 8; j++) acc[i][j] = 0.f;
#pragma unroll 2
    for (int kp = 0; kp < HID / 2; kp++) {
        float2 a[4];
#pragma unroll
        for (int i = 0; i < 4; i++)
            a[i] = *(const float2*)&sA[(r0 + i) * 132 + 2 * kp];
        float4 b0 = *(const float4*)&sW[(2 * kp) * HID + c0];
        float4 b1 = *(const float4*)&sW[(2 * kp) * HID + c0 + 4];
        float4 b2 = *(const float4*)&sW[(2 * kp + 1) * HID + c0];
        float4 b3 = *(const float4*)&sW[(2 * kp + 1) * HID + c0 + 4];
        float bb0[8] = {b0.x, b0.y, b0.z, b0.w, b1.x, b1.y, b1.z, b1.w};
        float bb1[8] = {b2.x, b2.y, b2.z, b2.w, b3.x, b3.y, b3.z, b3.w};
#pragma unroll
        for (int i = 0; i < 4; i++) {
#pragma unroll
            for (int j = 0; j < 8; j++) acc[i][j] = fmaf(a[i].x, bb0[j], acc[i][j]);
#pragma unroll
            for (int j = 0; j < 8; j++) acc[i][j] = fmaf(a[i].y, bb1[j], acc[i][j]);
        }
    }
#pragma unroll
    for (int i = 0; i < 4; i++) {
        long ro = (long)(rb + r0 + i) * HID;
#pragma unroll
        for (int j = 0; j < 8; j++) {
            float v = acc[i][j] + sB[c0 + j];
            if (silu) v = v / (1.0f + __expf(-v));
            if (base) v += base[ro + c0 + j];
            out[ro + c0 + j] = v;
        }
    }
}

// ---------------- launch ----------------
extern "C" void kernel_launch(void* const* d_in, const int* in_sizes, int n_in,
                              void* d_out, int out_size) {
    const int*   z       = (const int*)d_in[0];
    const int*   ei      = (const int*)d_in[1];
    const float* ew      = (const float*)d_in[2];
    const float* emb     = (const float*)d_in[3];
    const float* neemb   = (const float*)d_in[4];
    const float* neprojw = (const float*)d_in[5];
    const float* neprojb = (const float*)d_in[6];
    const float* necatw  = (const float*)d_in[7];
    const float* necatb  = (const float*)d_in[8];
    const float* means   = (const float*)d_in[9];
    const float* betas   = (const float*)d_in[10];
    const float* mlpw1   = (const float*)d_in[11];
    const float* mlpb1   = (const float*)d_in[12];
    const float* mlpw2   = (const float*)d_in[13];
    const float* mlpb2   = (const float*)d_in[14];
    const float* lin1w   = (const float*)d_in[15];
    const float* lin2w   = (const float*)d_in[16];
    const float* lin2b   = (const float*)d_in[17];
    const float* linw    = (const float*)d_in[18];
    const float* linb    = (const float*)d_in[19];
    float* outp = (float*)d_out;

    // smem sizes
    const int smI = 4 * HID * PT * 2 + 4 * HID * PR * 2 + 5 * 128 * 4;   // 215552
    const int smN = 4 * HID * PR * 2 + HID * PF * 4 + 5 * 128 * 4;       // 143872
    const int smG = (64 * 132 + HID * HID + 128) * 4;

    cudaFuncSetAttribute(k_edge<0>, cudaFuncAttributeMaxDynamicSharedMemorySize, smI);
    cudaFuncSetAttribute(k_edge<1>, cudaFuncAttributeMaxDynamicSharedMemorySize, smN);
    cudaFuncSetAttribute(k_ngemm,   cudaFuncAttributeMaxDynamicSharedMemorySize, smG);

    // ---- sort edges by destination + precompute per-edge data ----
    k_zero_cnt<<<NN / 256, 256>>>();
    k_hist<<<EE / 256, 256>>>(ei);
    k_scan<<<1, 1024>>>();
    k_place<<<EE / 256, 256>>>(ei);
    k_build<<<EE / 8, 256>>>(ei, ew, means, betas);
    k_gather<<<NN * HID / 256, 256>>>(z, emb, neemb);

    // ---- weight prep (bf16 hi/lo, transposed) ----
    k_wprep1<<<(NLAY * HID * K1 + 255) / 256, 256>>>(mlpw1, 0, NLAY);
    k_wprep1<<<(HID * K1 + 255) / 256, 256>>>(neprojw, 1, 1);
    k_wprep2<<<(NLAY * HID * HID + 255) / 256, 256>>>(mlpw2);

    // ---- NeighborEmbedding ----
    k_zero_agg<<<NN * HID / 256, 256>>>();
    k_edge<1><<<EE / 128, 512, smN>>>(0, neprojb, nullptr);
    k_ngemm<<<NN / 64, 256, smG>>>(0, necatw, necatb, -1, 2, 0, outp);
    k_ngemm<<<NN / 64, 256, smG>>>(3, necatw + HID * HID, nullptr, 2, 0, 0, outp);

    // ---- interaction layers ----
    for (int l = 0; l < NLAY; l++) {
        k_zero_agg<<<NN * HID / 256, 256>>>();
        k_ngemm<<<NN / 64, 256, smG>>>(0, lin1w + (size_t)l * HID * HID, nullptr, -1, 1, 0, outp);
        k_edge<0><<<EE / 128, 512, smI>>>(l, mlpb1 + (size_t)l * HID, mlpb2 + (size_t)l * HID);
        k_ngemm<<<NN / 64, 256, smG>>>(3, lin2w + (size_t)l * HID * HID, lin2b + (size_t)l * HID,
                                       -1, 2, 1, outp);
        k_ngemm<<<NN / 64, 256, smG>>>(2, linw + (size_t)l * HID * HID, linb + (size_t)l * HID,
                                       0, (l == NLAY - 1) ? 4 : 0, 0, outp);
    }
}

// round 5
// speedup vs baseline: 4.1485x; 1.7177x over previous
#include <cuda_runtime.h>
#include <cuda_bf16.h>
#include <math.h>

// ---------------- problem constants ----------------
#define NN    8192
#define EE    262144
#define HID   128
#define NRBF  50
#define K1    64           // padded K for GEMM1 (50 -> 64)
#define NLAY  6
#define PR    72           // smem pitch (bf16) for rbf / W1^T
#define PT    136          // smem pitch (bf16) for T / W2^T / ngemm tiles
#define PF    132          // smem pitch (f32) for F tile
#define NSLOT 20

typedef __nv_bfloat16  bf16;
typedef __nv_bfloat162 bf162;

// ---------------- device scratch ----------------
__device__ bf16 g_rbf_hi[(size_t)EE * K1];
__device__ bf16 g_rbf_lo[(size_t)EE * K1];
__device__ bf16 g_w1t_hi[NLAY * HID * K1];
__device__ bf16 g_w1t_lo[NLAY * HID * K1];
__device__ bf16 g_w2t_hi[NLAY * HID * HID];
__device__ bf16 g_w2t_lo[NLAY * HID * HID];
__device__ bf16 g_npt_hi[HID * K1];
__device__ bf16 g_npt_lo[HID * K1];
__device__ bf16 g_nwt_hi[NSLOT * HID * HID];   // node-GEMM weights, transposed hi
__device__ bf16 g_nwt_lo[NSLOT * HID * HID];
__device__ float g_cut[EE];
__device__ float g_cutm[EE];
__device__ int   g_srow[EE];
__device__ int   g_sdst[EE];
__device__ int   g_perm[EE];
__device__ int   g_cnt[NN];
__device__ int   g_offm[NN];
__device__ float g_x  [NN * HID];
__device__ float g_h  [NN * HID];
__device__ float g_h2 [NN * HID];
__device__ float g_agg[NN * HID];
__device__ float g_nex[NN * HID];

// ---------------- small helper kernels ----------------
__global__ void k_zero_cnt() {
    int i = blockIdx.x * blockDim.x + threadIdx.x;
    if (i < NN) g_cnt[i] = 0;
}

__global__ void k_zero_agg() {
    int i = blockIdx.x * blockDim.x + threadIdx.x;
    if (i < NN * HID) g_agg[i] = 0.f;
}

__global__ void k_hist(const int* __restrict__ ei) {
    int e = blockIdx.x * blockDim.x + threadIdx.x;
    if (e < EE) atomicAdd(&g_cnt[ei[EE + e]], 1);
}

__global__ void k_scan() {
    __shared__ int part[1024];
    int t = threadIdx.x;
    int base = t * 8;
    int loc[8];
    int s = 0;
#pragma unroll
    for (int i = 0; i < 8; i++) { loc[i] = s; s += g_cnt[base + i]; }
    part[t] = s;
    __syncthreads();
    int val = s;
    for (int off = 1; off < 1024; off <<= 1) {
        int v = (t >= off) ? part[t - off] : 0;
        __syncthreads();
        val += v;
        part[t] = val;
        __syncthreads();
    }
    int pre = (t == 0) ? 0 : part[t - 1];
#pragma unroll
    for (int i = 0; i < 8; i++) g_offm[base + i] = pre + loc[i];
}

__global__ void k_place(const int* __restrict__ ei) {
    int e = blockIdx.x * blockDim.x + threadIdx.x;
    if (e < EE) {
        int c = ei[EE + e];
        int p = atomicAdd(&g_offm[c], 1);
        g_perm[p] = e;
    }
}

__global__ void k_build(const int* __restrict__ ei, const float* __restrict__ ew,
                        const float* __restrict__ means, const float* __restrict__ betas) {
    int warp = (blockIdx.x * blockDim.x + threadIdx.x) >> 5;
    int lane = threadIdx.x & 31;
    if (warp >= EE) return;
    int e = g_perm[warp];
    int r = ei[e];
    int c = ei[EE + e];
    float d = ew[e];
    float cut = 0.5f * (cosf(d * 0.628318530717958647692f) + 1.0f);
    if (!(d < 5.0f)) cut = 0.f;
    float ex = __expf(-d);
    size_t ro = (size_t)warp * K1;
    {
        float m = means[lane], b = betas[lane];
        float v = ex - m;
        float val = cut * __expf(-b * v * v);
        bf16 hi = __float2bfloat16(val);
        g_rbf_hi[ro + lane] = hi;
        g_rbf_lo[ro + lane] = __float2bfloat16(val - __bfloat162float(hi));
    }
    int k2 = lane + 32;
    float val2 = 0.f;
    if (k2 < NRBF) {
        float m = means[k2], b = betas[k2];
        float v = ex - m;
        val2 = cut * __expf(-b * v * v);
    }
    bf16 hi2 = __float2bfloat16(val2);
    g_rbf_hi[ro + k2] = hi2;
    g_rbf_lo[ro + k2] = __float2bfloat16(val2 - __bfloat162float(hi2));
    if (lane == 0) {
        g_cut[warp]  = cut;
        g_cutm[warp] = (r != c) ? cut : 0.f;
        g_srow[warp] = r;
        g_sdst[warp] = c;
    }
}

__global__ void k_gather(const int* __restrict__ z, const float* __restrict__ emb,
                         const float* __restrict__ neemb) {
    int i = blockIdx.x * blockDim.x + threadIdx.x;
    if (i >= NN * HID) return;
    int n = i >> 7, c = i & 127;
    int zi = z[n];
    g_x[i]   = emb[zi * HID + c];
    g_nex[i] = neemb[zi * HID + c];
}

// weight prep: transpose + bf16 hi/lo split
__global__ void k_wprep1(const float* __restrict__ w, int mode, int layers) {
    int i = blockIdx.x * blockDim.x + threadIdx.x;
    if (i >= layers * HID * K1) return;
    int k = i & (K1 - 1);
    int n = (i >> 6) & (HID - 1);
    int l = i >> 13;
    float v = (k < NRBF) ? w[((size_t)l * NRBF + k) * HID + n] : 0.f;
    bf16 hi = __float2bfloat16(v);
    bf16 lo = __float2bfloat16(v - __bfloat162float(hi));
    if (mode == 0) { g_w1t_hi[i] = hi; g_w1t_lo[i] = lo; }
    else           { g_npt_hi[i] = hi; g_npt_lo[i] = lo; }
}

__global__ void k_wprep2(const float* __restrict__ w) {
    int i = blockIdx.x * blockDim.x + threadIdx.x;
    if (i >= NLAY * HID * HID) return;
    int k = i & (HID - 1);
    int n = (i >> 7) & (HID - 1);
    int l = i >> 14;
    float v = w[((size_t)l * HID + k) * HID + n];
    bf16 hi = __float2bfloat16(v);
    g_w2t_hi[i] = hi;
    g_w2t_lo[i] = __float2bfloat16(v - __bfloat162float(hi));
}

// node-GEMM weight: src [128][128] (row k, col n) -> slot [n][k] hi/lo
__global__ void k_wprepN(const float* __restrict__ src, int slot) {
    int i = blockIdx.x * blockDim.x + threadIdx.x;
    if (i >= HID * HID) return;
    int k = i & (HID - 1);
    int n = i >> 7;
    float v = src[k * HID + n];
    bf16 hi = __float2bfloat16(v);
    g_nwt_hi[(size_t)slot * HID * HID + i] = hi;
    g_nwt_lo[(size_t)slot * HID * HID + i] = __float2bfloat16(v - __bfloat162float(hi));
}

// ---------------- warp-MMA helpers ----------------
__device__ __forceinline__ void mma16816(float c[4], const unsigned a[4], const unsigned b[2]) {
    asm volatile(
        "mma.sync.aligned.m16n8k16.row.col.f32.bf16.bf16.f32 "
        "{%0,%1,%2,%3}, {%4,%5,%6,%7}, {%8,%9}, {%0,%1,%2,%3};\n"
        : "+f"(c[0]), "+f"(c[1]), "+f"(c[2]), "+f"(c[3])
        : "r"(a[0]), "r"(a[1]), "r"(a[2]), "r"(a[3]), "r"(b[0]), "r"(b[1]));
}

__device__ __forceinline__ void ldsm4(unsigned r[4], unsigned addr) {
    asm volatile("ldmatrix.sync.aligned.m8n8.x4.shared.b16 {%0,%1,%2,%3}, [%4];"
        : "=r"(r[0]), "=r"(r[1]), "=r"(r[2]), "=r"(r[3]) : "r"(addr));
}

// lane-specific ldmatrix addresses (PB = pitch in bytes)
__device__ __forceinline__ unsigned a_addr(unsigned base, int m0, int PB, int lane) {
    int sel = lane >> 3, li = lane & 7;
    return base + (m0 + li + (sel & 1) * 8) * PB + ((sel >> 1) * 8) * 2;
}
__device__ __forceinline__ unsigned b_addr(unsigned base, int n0, int PB, int lane) {
    int sel = lane >> 3, li = lane & 7;
    return base + (n0 + li + (sel >> 1) * 8) * PB + ((sel & 1) * 8) * 2;
}

// compensated bf16 32x32 warp GEMM: acc += (Ahi+Alo)(Bhi+Blo), drop lo*lo
template <int KSTEPS, int PB>
__device__ __forceinline__ void wgemm32(unsigned aHi, unsigned aLo,
                                        unsigned bHi, unsigned bLo,
                                        float acc[2][4][4]) {
#pragma unroll
    for (int ks = 0; ks < KSTEPS; ks++) {
        unsigned off = ks * 32;
        unsigned ah0[4], ah1[4], al0[4], al1[4], bh0[4], bh1[4], bl0[4], bl1[4];
        ldsm4(ah0, aHi + off);
        ldsm4(ah1, aHi + 16 * PB + off);
        ldsm4(al0, aLo + off);
        ldsm4(al1, aLo + 16 * PB + off);
        ldsm4(bh0, bHi + off);
        ldsm4(bh1, bHi + 16 * PB + off);
        ldsm4(bl0, bLo + off);
        ldsm4(bl1, bLo + 16 * PB + off);
#pragma unroll
        for (int nt = 0; nt < 4; nt++) {
            const unsigned* bh = (nt < 2) ? (bh0 + 2 * nt) : (bh1 + 2 * (nt - 2));
            const unsigned* bl = (nt < 2) ? (bl0 + 2 * nt) : (bl1 + 2 * (nt - 2));
            mma16816(acc[0][nt], ah0, bh);
            mma16816(acc[1][nt], ah1, bh);
            mma16816(acc[0][nt], ah0, bl);
            mma16816(acc[1][nt], ah1, bl);
            mma16816(acc[0][nt], al0, bh);
            mma16816(acc[1][nt], al1, bh);
        }
    }
}

// ---------------- fused edge MLP + segmented aggregation (persistent) --------
// NE=1: F = (rbf@W1 + b1) * cutm ; msg = nex[row]*F
// NE=0: F = (silu(rbf@W1+b1)@W2 + b2) * cut ; msg = h[row]*F
template <int NE>
__global__ void __launch_bounds__(512, 1)
k_edge(int layer, const float* __restrict__ b1g, const float* __restrict__ b2g) {
    extern __shared__ __align__(16) char smref[];
    constexpr int T_BYTES = HID * PT * 2;   // 34816
    constexpr int R_BYTES = HID * PR * 2;   // 18432
    const int OFF_THI  = 0;
    const int OFF_TLO  = T_BYTES;
    const int OFF_W2HI = 2 * T_BYTES;
    const int OFF_W2LO = 3 * T_BYTES;
    const int OFF_RHI  = NE ? 0 : 4 * T_BYTES;
    const int OFF_RLO  = OFF_RHI + R_BYTES;
    const int OFF_W1HI = OFF_RLO + R_BYTES;
    const int OFF_W1LO = OFF_W1HI + R_BYTES;
    const int OFF_F    = NE ? (OFF_W1LO + R_BYTES) : 0;   // I: overlay T region
    const int OFF_MISC = NE ? (OFF_F + HID * PF * 4) : (OFF_RHI + 4 * R_BYTES);

    bf16* sThi  = (bf16*)(smref + OFF_THI);
    bf16* sTlo  = (bf16*)(smref + OFF_TLO);
    float* sF   = (float*)(smref + OFF_F);
    float* sB1  = (float*)(smref + OFF_MISC);
    float* sB2  = sB1 + 128;
    float* sCut = sB2 + 128;
    int*   sRow = (int*)(sCut + 128);
    int*   sDst = sRow + 128;

    int tid = threadIdx.x;
    unsigned sbase = (unsigned)__cvta_generic_to_shared(smref);

    // ---- stage weights once (resident across tiles) ----
    {
        const unsigned* ghi = (const unsigned*)(NE ? g_npt_hi : (g_w1t_hi + (size_t)layer * HID * K1));
        const unsigned* glo = (const unsigned*)(NE ? g_npt_lo : (g_w1t_lo + (size_t)layer * HID * K1));
        unsigned* shi = (unsigned*)(smref + OFF_W1HI);
        unsigned* slo = (unsigned*)(smref + OFF_W1LO);
        for (int i = tid; i < 128 * 32; i += 512) {
            int r = i >> 5, wd = i & 31;
            shi[r * (PR / 2) + wd] = ghi[i];
            slo[r * (PR / 2) + wd] = glo[i];
        }
    }
    if (!NE) {
        const unsigned* ghi = (const unsigned*)(g_w2t_hi + (size_t)layer * HID * HID);
        const unsigned* glo = (const unsigned*)(g_w2t_lo + (size_t)layer * HID * HID);
        unsigned* shi = (unsigned*)(smref + OFF_W2HI);
        unsigned* slo = (unsigned*)(smref + OFF_W2LO);
        for (int i = tid; i < 128 * 64; i += 512) {
            int r = i >> 6, wd = i & 63;
            shi[r * (PT / 2) + wd] = ghi[i];
            slo[r * (PT / 2) + wd] = glo[i];
        }
    }
    if (tid < 128) {
        sB1[tid] = b1g[tid];
        sB2[tid] = NE ? 0.f : b2g[tid];
    }

    // warp tiling: 4m x 4n, 32x32 per warp
    int w = tid >> 5, lane = tid & 31;
    int m0 = (w & 3) * 32, n0 = (w >> 2) * 32;
    int g = lane >> 2, tc = lane & 3;

    unsigned g1aHi = a_addr(sbase + OFF_RHI,  m0, PR * 2, lane);
    unsigned g1aLo = g1aHi + R_BYTES;
    unsigned g1bHi = b_addr(sbase + OFF_W1HI, n0, PR * 2, lane);
    unsigned g1bLo = g1bHi + R_BYTES;
    unsigned g2aHi = a_addr(sbase + OFF_THI,  m0, PT * 2, lane);
    unsigned g2aLo = g2aHi + T_BYTES;
    unsigned g2bHi = b_addr(sbase + OFF_W2HI, n0, PT * 2, lane);
    unsigned g2bLo = g2bHi + T_BYTES;

    const float* hsrc = NE ? g_nex : g_h;

    for (long tile = blockIdx.x; tile < EE / 128; tile += gridDim.x) {
        long ebase = tile * 128;
        __syncthreads();   // protect prev tile's F / metadata readers

        // ---- stage rbf hi/lo + per-tile metadata ----
        {
            const unsigned* ghi = (const unsigned*)(g_rbf_hi + ebase * K1);
            const unsigned* glo = (const unsigned*)(g_rbf_lo + ebase * K1);
            unsigned* shi = (unsigned*)(smref + OFF_RHI);
            unsigned* slo = (unsigned*)(smref + OFF_RLO);
            for (int i = tid; i < 128 * 32; i += 512) {
                int r = i >> 5, wd = i & 31;
                shi[r * (PR / 2) + wd] = ghi[i];
                slo[r * (PR / 2) + wd] = glo[i];
            }
        }
        if (tid < 128) {
            sCut[tid] = NE ? g_cutm[ebase + tid] : g_cut[ebase + tid];
            sRow[tid] = g_srow[ebase + tid];
            sDst[tid] = g_sdst[ebase + tid];
        }
        __syncthreads();

        // ---- GEMM1: rbf[128,64] @ W1[64,128] ----
        {
            float acc[2][4][4];
#pragma unroll
            for (int a = 0; a < 2; a++)
#pragma unroll
                for (int b = 0; b < 4; b++)
#pragma unroll
                    for (int c = 0; c < 4; c++) acc[a][b][c] = 0.f;
            wgemm32<K1 / 16, PR * 2>(g1aHi, g1aLo, g1bHi, g1bLo, acc);

            if (NE) {
#pragma unroll
                for (int mt = 0; mt < 2; mt++) {
                    int ra = m0 + mt * 16 + g, rb2 = ra + 8;
                    float cua = sCut[ra], cub = sCut[rb2];
#pragma unroll
                    for (int nt = 0; nt < 4; nt++) {
                        int col = n0 + nt * 8 + 2 * tc;
                        float2 v0, v1;
                        v0.x = (acc[mt][nt][0] + sB1[col])     * cua;
                        v0.y = (acc[mt][nt][1] + sB1[col + 1]) * cua;
                        v1.x = (acc[mt][nt][2] + sB1[col])     * cub;
                        v1.y = (acc[mt][nt][3] + sB1[col + 1]) * cub;
                        *(float2*)&sF[ra * PF + col]  = v0;
                        *(float2*)&sF[rb2 * PF + col] = v1;
                    }
                }
            } else {
#pragma unroll
                for (int mt = 0; mt < 2; mt++) {
                    int ra = m0 + mt * 16 + g, rb2 = ra + 8;
#pragma unroll
                    for (int nt = 0; nt < 4; nt++) {
                        int col = n0 + nt * 8 + 2 * tc;
                        float x0 = acc[mt][nt][0] + sB1[col];
                        float x1 = acc[mt][nt][1] + sB1[col + 1];
                        float x2 = acc[mt][nt][2] + sB1[col];
                        float x3 = acc[mt][nt][3] + sB1[col + 1];
                        x0 = x0 / (1.f + __expf(-x0));
                        x1 = x1 / (1.f + __expf(-x1));
                        x2 = x2 / (1.f + __expf(-x2));
                        x3 = x3 / (1.f + __expf(-x3));
                        bf162 h0, h1, l0, l1;
                        h0.x = __float2bfloat16(x0); h0.y = __float2bfloat16(x1);
                        h1.x = __float2bfloat16(x2); h1.y = __float2bfloat16(x3);
                        l0.x = __float2bfloat16(x0 - __bfloat162float(h0.x));
                        l0.y = __float2bfloat16(x1 - __bfloat162float(h0.y));
                        l1.x = __float2bfloat16(x2 - __bfloat162float(h1.x));
                        l1.y = __float2bfloat16(x3 - __bfloat162float(h1.y));
                        *(bf162*)&sThi[ra * PT + col]  = h0;
                        *(bf162*)&sThi[rb2 * PT + col] = h1;
                        *(bf162*)&sTlo[ra * PT + col]  = l0;
                        *(bf162*)&sTlo[rb2 * PT + col] = l1;
                    }
                }
            }
        }
        __syncthreads();

        // ---- GEMM2 (interaction only) ----
        if (!NE) {
            float acc[2][4][4];
#pragma unroll
            for (int a = 0; a < 2; a++)
#pragma unroll
                for (int b = 0; b < 4; b++)
#pragma unroll
                    for (int c = 0; c < 4; c++) acc[a][b][c] = 0.f;
            wgemm32<HID / 16, PT * 2>(g2aHi, g2aLo, g2bHi, g2bLo, acc);
            __syncthreads();   // all T reads done before F overlays T

#pragma unroll
            for (int mt = 0; mt < 2; mt++) {
                int ra = m0 + mt * 16 + g, rb2 = ra + 8;
                float cua = sCut[ra], cub = sCut[rb2];
#pragma unroll
                for (int nt = 0; nt < 4; nt++) {
                    int col = n0 + nt * 8 + 2 * tc;
                    float2 v0, v1;
                    v0.x = (acc[mt][nt][0] + sB2[col])     * cua;
                    v0.y = (acc[mt][nt][1] + sB2[col + 1]) * cua;
                    v1.x = (acc[mt][nt][2] + sB2[col])     * cub;
                    v1.y = (acc[mt][nt][3] + sB2[col + 1]) * cub;
                    *(float2*)&sF[ra * PF + col]  = v0;
                    *(float2*)&sF[rb2 * PF + col] = v1;
                }
            }
        }
        __syncthreads();

        // ---- segmented aggregation ----
        int grp = tid >> 7;
        int f = tid & 127;
        int e0 = grp * 32;
        float accv = 0.f;
        int cur = sDst[e0];
#pragma unroll 1
        for (int b = 0; b < 4; b++) {
            float hb[8];
#pragma unroll
            for (int j = 0; j < 8; j++)
                hb[j] = hsrc[(long)sRow[e0 + b * 8 + j] * HID + f];
#pragma unroll
            for (int j = 0; j < 8; j++) {
                int e = e0 + b * 8 + j;
                int dd = sDst[e];
                if (dd != cur) {
                    atomicAdd(&g_agg[(long)cur * HID + f], accv);
                    accv = 0.f;
                    cur = dd;
                }
                accv = fmaf(hb[j], sF[e * PF + f], accv);
            }
        }
        atomicAdd(&g_agg[(long)cur * HID + f], accv);
    }
}

// ---------------- tensor-core node GEMM: out = base + act(A @ W + bias) -------
__device__ __forceinline__ float* selp(int s, float* dout) {
    switch (s) {
        case 0: return g_x;
        case 1: return g_h;
        case 2: return g_h2;
        case 3: return g_agg;
        default: return dout;
    }
}

__global__ void __launch_bounds__(256, 1)
k_ngemm(int Asel, int slot, const float* __restrict__ bias,
        int baseSel, int outSel, int silu, float* dout) {
    extern __shared__ __align__(16) char smref[];
    constexpr int A_BYTES = 64 * PT * 2;    // 17408
    constexpr int W_BYTES = HID * PT * 2;   // 34816
    const int OFF_AHI = 0;
    const int OFF_ALO = A_BYTES;
    const int OFF_WHI = 2 * A_BYTES;
    const int OFF_WLO = OFF_WHI + W_BYTES;
    const int OFF_B   = OFF_WLO + W_BYTES;

    bf16* sAhi = (bf16*)(smref + OFF_AHI);
    bf16* sAlo = (bf16*)(smref + OFF_ALO);
    float* sB  = (float*)(smref + OFF_B);

    const float* A = selp(Asel, dout);
    float* out = selp(outSel, dout);
    const float* base = (baseSel >= 0) ? selp(baseSel, dout) : nullptr;

    int tid = threadIdx.x;
    int rb = blockIdx.x * 64;
    unsigned sbase = (unsigned)__cvta_generic_to_shared(smref);

    // stage A (fp32 -> hi/lo)
    for (int i = tid; i < 64 * HID; i += 256) {
        int r = i >> 7, k = i & 127;
        float v = A[(long)(rb + r) * HID + k];
        bf16 hi = __float2bfloat16(v);
        sAhi[r * PT + k] = hi;
        sAlo[r * PT + k] = __float2bfloat16(v - __bfloat162float(hi));
    }
    // stage W (pre-split bf16, transposed [n][k])
    {
        const unsigned* ghi = (const unsigned*)(g_nwt_hi + (size_t)slot * HID * HID);
        const unsigned* glo = (const unsigned*)(g_nwt_lo + (size_t)slot * HID * HID);
        unsigned* shi = (unsigned*)(smref + OFF_WHI);
        unsigned* slo = (unsigned*)(smref + OFF_WLO);
        for (int i = tid; i < 128 * 64; i += 256) {
            int r = i >> 6, wd = i & 63;
            shi[r * (PT / 2) + wd] = ghi[i];
            slo[r * (PT / 2) + wd] = glo[i];
        }
    }
    if (tid < 128) sB[tid] = bias ? bias[tid] : 0.f;
    __syncthreads();

    // 8 warps: 2m x 4n, 32x32 tiles over 64x128
    int w = tid >> 5, lane = tid & 31;
    int m0 = (w & 1) * 32, n0 = (w >> 1) * 32;
    int g = lane >> 2, tc = lane & 3;

    unsigned aHi = a_addr(sbase + OFF_AHI, m0, PT * 2, lane);
    unsigned aLo = aHi + A_BYTES;
    unsigned bHi = b_addr(sbase + OFF_WHI, n0, PT * 2, lane);
    unsigned bLo = bHi + W_BYTES;

    float acc[2][4][4];
#pragma unroll
    for (int a = 0; a < 2; a++)
#pragma unroll
        for (int b = 0; b < 4; b++)
#pragma unroll
            for (int c = 0; c < 4; c++) acc[a][b][c] = 0.f;
    wgemm32<HID / 16, PT * 2>(aHi, aLo, bHi, bLo, acc);

#pragma unroll
    for (int mt = 0; mt < 2; mt++) {
#pragma unroll
        for (int dr = 0; dr < 2; dr++) {
            int r = m0 + mt * 16 + g + dr * 8;
            long ro = (long)(rb + r) * HID;
#pragma unroll
            for (int nt = 0; nt < 4; nt++) {
                int col = n0 + nt * 8 + 2 * tc;
                float v0 = acc[mt][nt][2 * dr]     + sB[col];
                float v1 = acc[mt][nt][2 * dr + 1] + sB[col + 1];
                if (silu) {
                    v0 = v0 / (1.f + __expf(-v0));
                    v1 = v1 / (1.f + __expf(-v1));
                }
                if (base) {
                    v0 += base[ro + col];
                    v1 += base[ro + col + 1];
                }
                *(float2*)&out[ro + col] = make_float2(v0, v1);
            }
        }
    }
}

// ---------------- launch ----------------
extern "C" void kernel_launch(void* const* d_in, const int* in_sizes, int n_in,
                              void* d_out, int out_size) {
    const int*   z       = (const int*)d_in[0];
    const int*   ei      = (const int*)d_in[1];
    const float* ew      = (const float*)d_in[2];
    const float* emb     = (const float*)d_in[3];
    const float* neemb   = (const float*)d_in[4];
    const float* neprojw = (const float*)d_in[5];
    const float* neprojb = (const float*)d_in[6];
    const float* necatw  = (const float*)d_in[7];
    const float* necatb  = (const float*)d_in[8];
    const float* means   = (const float*)d_in[9];
    const float* betas   = (const float*)d_in[10];
    const float* mlpw1   = (const float*)d_in[11];
    const float* mlpb1   = (const float*)d_in[12];
    const float* mlpw2   = (const float*)d_in[13];
    const float* mlpb2   = (const float*)d_in[14];
    const float* lin1w   = (const float*)d_in[15];
    const float* lin2w   = (const float*)d_in[16];
    const float* lin2b   = (const float*)d_in[17];
    const float* linw    = (const float*)d_in[18];
    const float* linb    = (const float*)d_in[19];
    float* outp = (float*)d_out;

    const int T_BYTES = HID * PT * 2, R_BYTES = HID * PR * 2;
    const int smI = 4 * T_BYTES + 4 * R_BYTES + 5 * 128 * 4;               // 215552
    const int smN = 4 * R_BYTES + HID * PF * 4 + 5 * 128 * 4;              // 143872
    const int smG = 2 * (64 * PT * 2) + 2 * T_BYTES + 512;                 // 104960

    cudaFuncSetAttribute(k_edge<0>, cudaFuncAttributeMaxDynamicSharedMemorySize, smI);
    cudaFuncSetAttribute(k_edge<1>, cudaFuncAttributeMaxDynamicSharedMemorySize, smN);
    cudaFuncSetAttribute(k_ngemm,   cudaFuncAttributeMaxDynamicSharedMemorySize, smG);

    // ---- sort edges by destination + precompute per-edge data ----
    k_zero_cnt<<<NN / 256, 256>>>();
    k_hist<<<EE / 256, 256>>>(ei);
    k_scan<<<1, 1024>>>();
    k_place<<<EE / 256, 256>>>(ei);
    k_build<<<EE / 8, 256>>>(ei, ew, means, betas);
    k_gather<<<NN * HID / 256, 256>>>(z, emb, neemb);

    // ---- weight prep ----
    k_wprep1<<<(NLAY * HID * K1 + 255) / 256, 256>>>(mlpw1, 0, NLAY);
    k_wprep1<<<(HID * K1 + 255) / 256, 256>>>(neprojw, 1, 1);
    k_wprep2<<<(NLAY * HID * HID + 255) / 256, 256>>>(mlpw2);
    k_wprepN<<<64, 256>>>(necatw, 0);
    k_wprepN<<<64, 256>>>(necatw + HID * HID, 1);
    for (int l = 0; l < NLAY; l++) {
        k_wprepN<<<64, 256>>>(lin1w + (size_t)l * HID * HID, 2 + l);
        k_wprepN<<<64, 256>>>(lin2w + (size_t)l * HID * HID, 8 + l);
        k_wprepN<<<64, 256>>>(linw  + (size_t)l * HID * HID, 14 + l);
    }

    // ---- NeighborEmbedding ----
    k_zero_agg<<<NN * HID / 256, 256>>>();
    k_edge<1><<<148, 512, smN>>>(0, neprojb, nullptr);
    k_ngemm<<<NN / 64, 256, smG>>>(0, 0, necatb, -1, 2, 0, outp);
    k_ngemm<<<NN / 64, 256, smG>>>(3, 1, nullptr, 2, 0, 0, outp);

    // ---- interaction layers ----
    for (int l = 0; l < NLAY; l++) {
        k_zero_agg<<<NN * HID / 256, 256>>>();
        k_ngemm<<<NN / 64, 256, smG>>>(0, 2 + l, nullptr, -1, 1, 0, outp);
        k_edge<0><<<148, 512, smI>>>(l, mlpb1 + (size_t)l * HID, mlpb2 + (size_t)l * HID);
        k_ngemm<<<NN / 64, 256, smG>>>(3, 8 + l, lin2b + (size_t)l * HID, -1, 2, 1, outp);
        k_ngemm<<<NN / 64, 256, smG>>>(2, 14 + l, linb + (size_t)l * HID,
                                       0, (l == NLAY - 1) ? 4 : 0, 0, outp);
    }
}

// round 6
// speedup vs baseline: 4.6472x; 1.1202x over previous
#include <cuda_runtime.h>
#include <cuda_bf16.h>
#include <math.h>

// ---------------- problem constants ----------------
#define NN    8192
#define EE    262144
#define HID   128
#define NRBF  50
#define K1    64
#define NLAY  6
#define PR    72           // smem pitch (bf16) for rbf / W1^T
#define PT    136          // smem pitch (bf16) for T / W2^T / ngemm tiles
#define PF    132          // smem pitch (f32) for F tile
#define NSLOT 20

typedef __nv_bfloat16  bf16;
typedef __nv_bfloat162 bf162;

// ---------------- device scratch ----------------
__device__ bf16 g_rbf_hi[(size_t)EE * K1];
__device__ bf16 g_rbf_lo[(size_t)EE * K1];
__device__ bf16 g_w1t_hi[NLAY * HID * K1];
__device__ bf16 g_w1t_lo[NLAY * HID * K1];
__device__ bf16 g_w2t_hi[NLAY * HID * HID];
__device__ bf16 g_w2t_lo[NLAY * HID * HID];
__device__ bf16 g_npt_hi[HID * K1];
__device__ bf16 g_npt_lo[HID * K1];
__device__ bf16 g_nwt_hi[NSLOT * HID * HID];
__device__ bf16 g_nwt_lo[NSLOT * HID * HID];
__device__ float g_cut[EE];
__device__ float g_cutm[EE];
__device__ int   g_srow[EE];
__device__ int   g_sdst[EE];
__device__ int   g_perm[EE];
__device__ int   g_cnt[NN];
__device__ int   g_offm[NN];
__device__ float g_x  [NN * HID];
__device__ float g_h  [NN * HID];
__device__ float g_h2 [NN * HID];
__device__ float g_agg[NN * HID];
__device__ float g_nex[NN * HID];

// ---------------- small helper kernels ----------------
__global__ void k_zero_cnt() {
    int i = blockIdx.x * blockDim.x + threadIdx.x;
    if (i < NN) g_cnt[i] = 0;
}

__global__ void k_hist(const int* __restrict__ ei) {
    int e = blockIdx.x * blockDim.x + threadIdx.x;
    if (e < EE) atomicAdd(&g_cnt[ei[EE + e]], 1);
}

__global__ void k_scan() {
    __shared__ int part[1024];
    int t = threadIdx.x;
    int base = t * 8;
    int loc[8];
    int s = 0;
#pragma unroll
    for (int i = 0; i < 8; i++) { loc[i] = s; s += g_cnt[base + i]; }
    part[t] = s;
    __syncthreads();
    int val = s;
    for (int off = 1; off < 1024; off <<= 1) {
        int v = (t >= off) ? part[t - off] : 0;
        __syncthreads();
        val += v;
        part[t] = val;
        __syncthreads();
    }
    int pre = (t == 0) ? 0 : part[t - 1];
#pragma unroll
    for (int i = 0; i < 8; i++) g_offm[base + i] = pre + loc[i];
}

__global__ void k_place(const int* __restrict__ ei) {
    int e = blockIdx.x * blockDim.x + threadIdx.x;
    if (e < EE) {
        int c = ei[EE + e];
        int p = atomicAdd(&g_offm[c], 1);
        g_perm[p] = e;
    }
}

__global__ void k_build(const int* __restrict__ ei, const float* __restrict__ ew,
                        const float* __restrict__ means, const float* __restrict__ betas) {
    int warp = (blockIdx.x * blockDim.x + threadIdx.x) >> 5;
    int lane = threadIdx.x & 31;
    if (warp >= EE) return;
    int e = g_perm[warp];
    int r = ei[e];
    int c = ei[EE + e];
    float d = ew[e];
    float cut = 0.5f * (cosf(d * 0.628318530717958647692f) + 1.0f);
    if (!(d < 5.0f)) cut = 0.f;
    float ex = __expf(-d);
    size_t ro = (size_t)warp * K1;
    {
        float m = means[lane], b = betas[lane];
        float v = ex - m;
        float val = cut * __expf(-b * v * v);
        bf16 hi = __float2bfloat16(val);
        g_rbf_hi[ro + lane] = hi;
        g_rbf_lo[ro + lane] = __float2bfloat16(val - __bfloat162float(hi));
    }
    int k2 = lane + 32;
    float val2 = 0.f;
    if (k2 < NRBF) {
        float m = means[k2], b = betas[k2];
        float v = ex - m;
        val2 = cut * __expf(-b * v * v);
    }
    bf16 hi2 = __float2bfloat16(val2);
    g_rbf_hi[ro + k2] = hi2;
    g_rbf_lo[ro + k2] = __float2bfloat16(val2 - __bfloat162float(hi2));
    if (lane == 0) {
        g_cut[warp]  = cut;
        g_cutm[warp] = (r != c) ? cut : 0.f;
        g_srow[warp] = r;
        g_sdst[warp] = c;
    }
}

// gather node embeddings; also zero g_agg (for NeighborEmbedding pass)
__global__ void k_gather(const int* __restrict__ z, const float* __restrict__ emb,
                         const float* __restrict__ neemb) {
    int i = blockIdx.x * blockDim.x + threadIdx.x;
    if (i >= NN * HID) return;
    int n = i >> 7, c = i & 127;
    int zi = z[n];
    g_x[i]   = emb[zi * HID + c];
    g_nex[i] = neemb[zi * HID + c];
    g_agg[i] = 0.f;
}

// weight prep: transpose + bf16 hi/lo split
__global__ void k_wprep1(const float* __restrict__ w, int mode, int layers) {
    int i = blockIdx.x * blockDim.x + threadIdx.x;
    if (i >= layers * HID * K1) return;
    int k = i & (K1 - 1);
    int n = (i >> 6) & (HID - 1);
    int l = i >> 13;
    float v = (k < NRBF) ? w[((size_t)l * NRBF + k) * HID + n] : 0.f;
    bf16 hi = __float2bfloat16(v);
    bf16 lo = __float2bfloat16(v - __bfloat162float(hi));
    if (mode == 0) { g_w1t_hi[i] = hi; g_w1t_lo[i] = lo; }
    else           { g_npt_hi[i] = hi; g_npt_lo[i] = lo; }
}

__global__ void k_wprep2(const float* __restrict__ w) {
    int i = blockIdx.x * blockDim.x + threadIdx.x;
    if (i >= NLAY * HID * HID) return;
    int k = i & (HID - 1);
    int n = (i >> 7) & (HID - 1);
    int l = i >> 14;
    float v = w[((size_t)l * HID + k) * HID + n];
    bf16 hi = __float2bfloat16(v);
    g_w2t_hi[i] = hi;
    g_w2t_lo[i] = __float2bfloat16(v - __bfloat162float(hi));
}

__global__ void k_wprepN(const float* __restrict__ src, int slot) {
    int i = blockIdx.x * blockDim.x + threadIdx.x;
    if (i >= HID * HID) return;
    int k = i & (HID - 1);
    int n = i >> 7;
    float v = src[k * HID + n];
    bf16 hi = __float2bfloat16(v);
    g_nwt_hi[(size_t)slot * HID * HID + i] = hi;
    g_nwt_lo[(size_t)slot * HID * HID + i] = __float2bfloat16(v - __bfloat162float(hi));
}

// ---------------- warp-MMA helpers ----------------
__device__ __forceinline__ void mma16816(float c[4], const unsigned a[4], const unsigned b[2]) {
    asm volatile(
        "mma.sync.aligned.m16n8k16.row.col.f32.bf16.bf16.f32 "
        "{%0,%1,%2,%3}, {%4,%5,%6,%7}, {%8,%9}, {%0,%1,%2,%3};\n"
        : "+f"(c[0]), "+f"(c[1]), "+f"(c[2]), "+f"(c[3])
        : "r"(a[0]), "r"(a[1]), "r"(a[2]), "r"(a[3]), "r"(b[0]), "r"(b[1]));
}

__device__ __forceinline__ void ldsm4(unsigned r[4], unsigned addr) {
    asm volatile("ldmatrix.sync.aligned.m8n8.x4.shared.b16 {%0,%1,%2,%3}, [%4];"
        : "=r"(r[0]), "=r"(r[1]), "=r"(r[2]), "=r"(r[3]) : "r"(addr));
}

__device__ __forceinline__ unsigned a_addr(unsigned base, int m0, int PB, int lane) {
    int sel = lane >> 3, li = lane & 7;
    return base + (m0 + li + (sel & 1) * 8) * PB + ((sel >> 1) * 8) * 2;
}
__device__ __forceinline__ unsigned b_addr(unsigned base, int n0, int PB, int lane) {
    int sel = lane >> 3, li = lane & 7;
    return base + (n0 + li + (sel >> 1) * 8) * PB + ((sel & 1) * 8) * 2;
}

template <int KSTEPS, int PB>
__device__ __forceinline__ void wgemm32(unsigned aHi, unsigned aLo,
                                        unsigned bHi, unsigned bLo,
                                        float acc[2][4][4]) {
#pragma unroll
    for (int ks = 0; ks < KSTEPS; ks++) {
        unsigned off = ks * 32;
        unsigned ah0[4], ah1[4], al0[4], al1[4], bh0[4], bh1[4], bl0[4], bl1[4];
        ldsm4(ah0, aHi + off);
        ldsm4(ah1, aHi + 16 * PB + off);
        ldsm4(al0, aLo + off);
        ldsm4(al1, aLo + 16 * PB + off);
        ldsm4(bh0, bHi + off);
        ldsm4(bh1, bHi + 16 * PB + off);
        ldsm4(bl0, bLo + off);
        ldsm4(bl1, bLo + 16 * PB + off);
#pragma unroll
        for (int nt = 0; nt < 4; nt++) {
            const unsigned* bh = (nt < 2) ? (bh0 + 2 * nt) : (bh1 + 2 * (nt - 2));
            const unsigned* bl = (nt < 2) ? (bl0 + 2 * nt) : (bl1 + 2 * (nt - 2));
            mma16816(acc[0][nt], ah0, bh);
            mma16816(acc[1][nt], ah1, bh);
            mma16816(acc[0][nt], ah0, bl);
            mma16816(acc[1][nt], ah1, bl);
            mma16816(acc[0][nt], al0, bh);
            mma16816(acc[1][nt], al1, bh);
        }
    }
}

// ---------------- cp.async helpers ----------------
__device__ __forceinline__ void cpa16(unsigned saddr, const void* gaddr) {
    asm volatile("cp.async.ca.shared.global [%0], [%1], 16;" :: "r"(saddr), "l"(gaddr));
}
__device__ __forceinline__ void cpa_commit() { asm volatile("cp.async.commit_group;"); }
__device__ __forceinline__ void cpa_wait0()  { asm volatile("cp.async.wait_group 0;"); }

// ---------------- fused edge MLP + segmented aggregation (persistent, pipelined)
template <int NE>
__global__ void __launch_bounds__(512, 1)
k_edge(int layer, const float* __restrict__ b1g, const float* __restrict__ b2g) {
    extern __shared__ __align__(16) char smref[];
    constexpr int T_BYTES = HID * PT * 2;   // 34816
    constexpr int R_BYTES = HID * PR * 2;   // 18432
    const int OFF_THI  = 0;
    const int OFF_TLO  = T_BYTES;
    const int OFF_W2HI = 2 * T_BYTES;
    const int OFF_W2LO = 3 * T_BYTES;
    const int OFF_RHI  = NE ? 0 : 4 * T_BYTES;
    const int OFF_RLO  = OFF_RHI + R_BYTES;
    const int OFF_W1HI = OFF_RLO + R_BYTES;
    const int OFF_W1LO = OFF_W1HI + R_BYTES;
    const int OFF_F    = NE ? (OFF_W1LO + R_BYTES) : 0;   // interaction: overlay T region
    const int OFF_MISC = NE ? (OFF_F + HID * PF * 4) : (OFF_RHI + 4 * R_BYTES);
    const int OFF_CUT  = OFF_MISC;          // [2][128] f32
    const int OFF_ROW  = OFF_MISC + 1024;   // [2][128] i32
    const int OFF_DST  = OFF_MISC + 2048;   // [2][128] i32
    const int OFF_B1   = OFF_MISC + 3072;
    const int OFF_B2   = OFF_MISC + 3584;

    bf16* sThi  = (bf16*)(smref + OFF_THI);
    bf16* sTlo  = (bf16*)(smref + OFF_TLO);
    float* sF   = (float*)(smref + OFF_F);
    float* sB1  = (float*)(smref + OFF_B1);
    float* sB2  = (float*)(smref + OFF_B2);

    int tid = threadIdx.x;
    unsigned sbase = (unsigned)__cvta_generic_to_shared(smref);

    const long NT = EE / 128;
    long tile = blockIdx.x;
    int buf = 0;

    // issue tile-0 rbf + metadata copy (overlaps with weight staging)
    if (tile < NT) {
        long ebase = tile * 128;
        for (int c = tid; c < 1024; c += 512) {
            int r = c >> 3, ch = c & 7;
            cpa16(sbase + OFF_RHI + r * 144 + ch * 16, &g_rbf_hi[(ebase + r) * K1 + ch * 8]);
            cpa16(sbase + OFF_RLO + r * 144 + ch * 16, &g_rbf_lo[(ebase + r) * K1 + ch * 8]);
        }
        if (tid < 32) {
            const float* cs = NE ? g_cutm : g_cut;
            cpa16(sbase + OFF_CUT + tid * 16, cs + ebase + tid * 4);
        } else if (tid < 64) {
            int t = tid - 32;
            cpa16(sbase + OFF_ROW + t * 16, g_srow + ebase + t * 4);
        } else if (tid < 96) {
            int t = tid - 64;
            cpa16(sbase + OFF_DST + t * 16, g_sdst + ebase + t * 4);
        }
    }
    cpa_commit();

    // ---- stage weights once ----
    {
        const unsigned* ghi = (const unsigned*)(NE ? g_npt_hi : (g_w1t_hi + (size_t)layer * HID * K1));
        const unsigned* glo = (const unsigned*)(NE ? g_npt_lo : (g_w1t_lo + (size_t)layer * HID * K1));
        unsigned* shi = (unsigned*)(smref + OFF_W1HI);
        unsigned* slo = (unsigned*)(smref + OFF_W1LO);
        for (int i = tid; i < 128 * 32; i += 512) {
            int r = i >> 5, wd = i & 31;
            shi[r * (PR / 2) + wd] = ghi[i];
            slo[r * (PR / 2) + wd] = glo[i];
        }
    }
    if (!NE) {
        const unsigned* ghi = (const unsigned*)(g_w2t_hi + (size_t)layer * HID * HID);
        const unsigned* glo = (const unsigned*)(g_w2t_lo + (size_t)layer * HID * HID);
        unsigned* shi = (unsigned*)(smref + OFF_W2HI);
        unsigned* slo = (unsigned*)(smref + OFF_W2LO);
        for (int i = tid; i < 128 * 64; i += 512) {
            int r = i >> 6, wd = i & 63;
            shi[r * (PT / 2) + wd] = ghi[i];
            slo[r * (PT / 2) + wd] = glo[i];
        }
    }
    if (tid < 128) {
        sB1[tid] = b1g[tid];
        sB2[tid] = NE ? 0.f : b2g[tid];
    }

    int w = tid >> 5, lane = tid & 31;
    int m0 = (w & 3) * 32, n0 = (w >> 2) * 32;
    int g = lane >> 2, tc = lane & 3;

    unsigned g1aHi = a_addr(sbase + OFF_RHI,  m0, PR * 2, lane);
    unsigned g1aLo = g1aHi + R_BYTES;
    unsigned g1bHi = b_addr(sbase + OFF_W1HI, n0, PR * 2, lane);
    unsigned g1bLo = g1bHi + R_BYTES;
    unsigned g2aHi = a_addr(sbase + OFF_THI,  m0, PT * 2, lane);
    unsigned g2aLo = g2aHi + T_BYTES;
    unsigned g2bHi = b_addr(sbase + OFF_W2HI, n0, PT * 2, lane);
    unsigned g2bLo = g2bHi + T_BYTES;

    const float* hsrc = NE ? g_nex : g_h;

    for (; tile < NT; tile += gridDim.x, buf ^= 1) {
        cpa_wait0();
        __syncthreads();   // rbf + meta[buf] ready; prev aggregation done (F/T safe)

        float* sCut = (float*)(smref + OFF_CUT + buf * 512);
        int*   sRow = (int*)(smref + OFF_ROW + buf * 512);
        int*   sDst = (int*)(smref + OFF_DST + buf * 512);

        // ---- GEMM1: rbf[128,64] @ W1[64,128] ----
        {
            float acc[2][4][4];
#pragma unroll
            for (int a = 0; a < 2; a++)
#pragma unroll
                for (int b = 0; b < 4; b++)
#pragma unroll
                    for (int c = 0; c < 4; c++) acc[a][b][c] = 0.f;
            wgemm32<K1 / 16, PR * 2>(g1aHi, g1aLo, g1bHi, g1bLo, acc);

            if (NE) {
#pragma unroll
                for (int mt = 0; mt < 2; mt++) {
                    int ra = m0 + mt * 16 + g, rb2 = ra + 8;
                    float cua = sCut[ra], cub = sCut[rb2];
#pragma unroll
                    for (int nt = 0; nt < 4; nt++) {
                        int col = n0 + nt * 8 + 2 * tc;
                        float2 v0, v1;
                        v0.x = (acc[mt][nt][0] + sB1[col])     * cua;
                        v0.y = (acc[mt][nt][1] + sB1[col + 1]) * cua;
                        v1.x = (acc[mt][nt][2] + sB1[col])     * cub;
                        v1.y = (acc[mt][nt][3] + sB1[col + 1]) * cub;
                        *(float2*)&sF[ra * PF + col]  = v0;
                        *(float2*)&sF[rb2 * PF + col] = v1;
                    }
                }
            } else {
#pragma unroll
                for (int mt = 0; mt < 2; mt++) {
                    int ra = m0 + mt * 16 + g, rb2 = ra + 8;
#pragma unroll
                    for (int nt = 0; nt < 4; nt++) {
                        int col = n0 + nt * 8 + 2 * tc;
                        float x0 = acc[mt][nt][0] + sB1[col];
                        float x1 = acc[mt][nt][1] + sB1[col + 1];
                        float x2 = acc[mt][nt][2] + sB1[col];
                        float x3 = acc[mt][nt][3] + sB1[col + 1];
                        x0 = x0 / (1.f + __expf(-x0));
                        x1 = x1 / (1.f + __expf(-x1));
                        x2 = x2 / (1.f + __expf(-x2));
                        x3 = x3 / (1.f + __expf(-x3));
                        bf162 h0, h1, l0, l1;
                        h0.x = __float2bfloat16(x0); h0.y = __float2bfloat16(x1);
                        h1.x = __float2bfloat16(x2); h1.y = __float2bfloat16(x3);
                        l0.x = __float2bfloat16(x0 - __bfloat162float(h0.x));
                        l0.y = __float2bfloat16(x1 - __bfloat162float(h0.y));
                        l1.x = __float2bfloat16(x2 - __bfloat162float(h1.x));
                        l1.y = __float2bfloat16(x3 - __bfloat162float(h1.y));
                        *(bf162*)&sThi[ra * PT + col]  = h0;
                        *(bf162*)&sThi[rb2 * PT + col] = h1;
                        *(bf162*)&sTlo[ra * PT + col]  = l0;
                        *(bf162*)&sTlo[rb2 * PT + col] = l1;
                    }
                }
            }
        }
        __syncthreads();   // all rbf reads done; T written

        // ---- issue next tile's rbf + metadata (overlaps GEMM2 + aggregation) ----
        {
            long nxt = tile + gridDim.x;
            if (nxt < NT) {
                long ebase = nxt * 128;
                int nb = buf ^ 1;
                for (int c = tid; c < 1024; c += 512) {
                    int r = c >> 3, ch = c & 7;
                    cpa16(sbase + OFF_RHI + r * 144 + ch * 16, &g_rbf_hi[(ebase + r) * K1 + ch * 8]);
                    cpa16(sbase + OFF_RLO + r * 144 + ch * 16, &g_rbf_lo[(ebase + r) * K1 + ch * 8]);
                }
                if (tid < 32) {
                    const float* cs = NE ? g_cutm : g_cut;
                    cpa16(sbase + OFF_CUT + nb * 512 + tid * 16, cs + ebase + tid * 4);
                } else if (tid < 64) {
                    int t = tid - 32;
                    cpa16(sbase + OFF_ROW + nb * 512 + t * 16, g_srow + ebase + t * 4);
                } else if (tid < 96) {
                    int t = tid - 64;
                    cpa16(sbase + OFF_DST + nb * 512 + t * 16, g_sdst + ebase + t * 4);
                }
            }
            cpa_commit();
        }

        // ---- GEMM2 (interaction only) ----
        if (!NE) {
            float acc[2][4][4];
#pragma unroll
            for (int a = 0; a < 2; a++)
#pragma unroll
                for (int b = 0; b < 4; b++)
#pragma unroll
                    for (int c = 0; c < 4; c++) acc[a][b][c] = 0.f;
            wgemm32<HID / 16, PT * 2>(g2aHi, g2aLo, g2bHi, g2bLo, acc);
            __syncthreads();   // all T reads done before F overlays T

#pragma unroll
            for (int mt = 0; mt < 2; mt++) {
                int ra = m0 + mt * 16 + g, rb2 = ra + 8;
                float cua = sCut[ra], cub = sCut[rb2];
#pragma unroll
                for (int nt = 0; nt < 4; nt++) {
                    int col = n0 + nt * 8 + 2 * tc;
                    float2 v0, v1;
                    v0.x = (acc[mt][nt][0] + sB2[col])     * cua;
                    v0.y = (acc[mt][nt][1] + sB2[col + 1]) * cua;
                    v1.x = (acc[mt][nt][2] + sB2[col])     * cub;
                    v1.y = (acc[mt][nt][3] + sB2[col + 1]) * cub;
                    *(float2*)&sF[ra * PF + col]  = v0;
                    *(float2*)&sF[rb2 * PF + col] = v1;
                }
            }
        }
        __syncthreads();   // F ready

        // ---- segmented aggregation ----
        int grp = tid >> 7;
        int f = tid & 127;
        int e0 = grp * 32;
        float accv = 0.f;
        int cur = sDst[e0];
#pragma unroll 1
        for (int b = 0; b < 4; b++) {
            float hb[8];
#pragma unroll
            for (int j = 0; j < 8; j++)
                hb[j] = hsrc[(long)sRow[e0 + b * 8 + j] * HID + f];
#pragma unroll
            for (int j = 0; j < 8; j++) {
                int e = e0 + b * 8 + j;
                int dd = sDst[e];
                if (dd != cur) {
                    atomicAdd(&g_agg[(long)cur * HID + f], accv);
                    accv = 0.f;
                    cur = dd;
                }
                accv = fmaf(hb[j], sF[e * PF + f], accv);
            }
        }
        atomicAdd(&g_agg[(long)cur * HID + f], accv);
    }
}

// ---------------- tensor-core node GEMM ----------------
__device__ __forceinline__ float* selp(int s, float* dout) {
    switch (s) {
        case 0: return g_x;
        case 1: return g_h;
        case 2: return g_h2;
        case 3: return g_agg;
        default: return dout;
    }
}

__global__ void __launch_bounds__(256, 1)
k_ngemm(int Asel, int slot, const float* __restrict__ bias,
        int baseSel, int outSel, int silu, int zeroAgg, float* dout) {
    extern __shared__ __align__(16) char smref[];
    constexpr int A_BYTES = 64 * PT * 2;
    constexpr int W_BYTES = HID * PT * 2;
    const int OFF_AHI = 0;
    const int OFF_ALO = A_BYTES;
    const int OFF_WHI = 2 * A_BYTES;
    const int OFF_WLO = OFF_WHI + W_BYTES;
    const int OFF_B   = OFF_WLO + W_BYTES;

    bf16* sAhi = (bf16*)(smref + OFF_AHI);
    bf16* sAlo = (bf16*)(smref + OFF_ALO);
    float* sB  = (float*)(smref + OFF_B);

    const float* A = selp(Asel, dout);
    float* out = selp(outSel, dout);
    const float* base = (baseSel >= 0) ? selp(baseSel, dout) : nullptr;

    int tid = threadIdx.x;
    int rb = blockIdx.x * 64;
    unsigned sbase = (unsigned)__cvta_generic_to_shared(smref);

    if (zeroAgg) {
        float4* za = (float4*)(g_agg + (long)rb * HID);
        for (int i = tid; i < 64 * HID / 4; i += 256) za[i] = make_float4(0.f, 0.f, 0.f, 0.f);
    }
    for (int i = tid; i < 64 * HID; i += 256) {
        int r = i >> 7, k = i & 127;
        float v = A[(long)(rb + r) * HID + k];
        bf16 hi = __float2bfloat16(v);
        sAhi[r * PT + k] = hi;
        sAlo[r * PT + k] = __float2bfloat16(v - __bfloat162float(hi));
    }
    {
        const unsigned* ghi = (const unsigned*)(g_nwt_hi + (size_t)slot * HID * HID);
        const unsigned* glo = (const unsigned*)(g_nwt_lo + (size_t)slot * HID * HID);
        unsigned* shi = (unsigned*)(smref + OFF_WHI);
        unsigned* slo = (unsigned*)(smref + OFF_WLO);
        for (int i = tid; i < 128 * 64; i += 256) {
            int r = i >> 6, wd = i & 63;
            shi[r * (PT / 2) + wd] = ghi[i];
            slo[r * (PT / 2) + wd] = glo[i];
        }
    }
    if (tid < 128) sB[tid] = bias ? bias[tid] : 0.f;
    __syncthreads();

    int w = tid >> 5, lane = tid & 31;
    int m0 = (w & 1) * 32, n0 = (w >> 1) * 32;
    int g = lane >> 2, tc = lane & 3;

    unsigned aHi = a_addr(sbase + OFF_AHI, m0, PT * 2, lane);
    unsigned aLo = aHi + A_BYTES;
    unsigned bHi = b_addr(sbase + OFF_WHI, n0, PT * 2, lane);
    unsigned bLo = bHi + W_BYTES;

    float acc[2][4][4];
#pragma unroll
    for (int a = 0; a < 2; a++)
#pragma unroll
        for (int b = 0; b < 4; b++)
#pragma unroll
            for (int c = 0; c < 4; c++) acc[a][b][c] = 0.f;
    wgemm32<HID / 16, PT * 2>(aHi, aLo, bHi, bLo, acc);

#pragma unroll
    for (int mt = 0; mt < 2; mt++) {
#pragma unroll
        for (int dr = 0; dr < 2; dr++) {
            int r = m0 + mt * 16 + g + dr * 8;
            long ro = (long)(rb + r) * HID;
#pragma unroll
            for (int nt = 0; nt < 4; nt++) {
                int col = n0 + nt * 8 + 2 * tc;
                float v0 = acc[mt][nt][2 * dr]     + sB[col];
                float v1 = acc[mt][nt][2 * dr + 1] + sB[col + 1];
                if (silu) {
                    v0 = v0 / (1.f + __expf(-v0));
                    v1 = v1 / (1.f + __expf(-v1));
                }
                if (base) {
                    v0 += base[ro + col];
                    v1 += base[ro + col + 1];
                }
                *(float2*)&out[ro + col] = make_float2(v0, v1);
            }
        }
    }
}

// ---------------- fused node GEMM pair: x (+)= (silu(agg@W2+b2)) @ W3 + b3 -----
__global__ void __launch_bounds__(256, 1)
k_ngemm2(int slotA, int slotB, const float* __restrict__ b2g,
         const float* __restrict__ b3g, int last, float* dout) {
    extern __shared__ __align__(16) char smref[];
    constexpr int A_BYTES = 64 * PT * 2;    // 17408
    constexpr int W_BYTES = HID * PT * 2;   // 34816
    const int OFF_AHI  = 0;
    const int OFF_ALO  = A_BYTES;
    const int OFF_W2HI = 2 * A_BYTES;
    const int OFF_W2LO = OFF_W2HI + W_BYTES;
    const int OFF_W3HI = OFF_W2LO + W_BYTES;
    const int OFF_W3LO = OFF_W3HI + W_BYTES;
    const int OFF_HHI  = OFF_W3LO + W_BYTES;
    const int OFF_HLO  = OFF_HHI + A_BYTES;
    const int OFF_B    = OFF_HLO + A_BYTES;   // b2[128], b3[128]

    bf16* sAhi = (bf16*)(smref + OFF_AHI);
    bf16* sAlo = (bf16*)(smref + OFF_ALO);
    bf16* sHhi = (bf16*)(smref + OFF_HHI);
    bf16* sHlo = (bf16*)(smref + OFF_HLO);
    float* sB2 = (float*)(smref + OFF_B);
    float* sB3 = sB2 + 128;

    int tid = threadIdx.x;
    int rb = blockIdx.x * 64;
    unsigned sbase = (unsigned)__cvta_generic_to_shared(smref);

    for (int i = tid; i < 64 * HID; i += 256) {
        int r = i >> 7, k = i & 127;
        float v = g_agg[(long)(rb + r) * HID + k];
        bf16 hi = __float2bfloat16(v);
        sAhi[r * PT + k] = hi;
        sAlo[r * PT + k] = __float2bfloat16(v - __bfloat162float(hi));
    }
    {
        const unsigned* g2hi = (const unsigned*)(g_nwt_hi + (size_t)slotA * HID * HID);
        const unsigned* g2lo = (const unsigned*)(g_nwt_lo + (size_t)slotA * HID * HID);
        const unsigned* g3hi = (const unsigned*)(g_nwt_hi + (size_t)slotB * HID * HID);
        const unsigned* g3lo = (const unsigned*)(g_nwt_lo + (size_t)slotB * HID * HID);
        unsigned* s2hi = (unsigned*)(smref + OFF_W2HI);
        unsigned* s2lo = (unsigned*)(smref + OFF_W2LO);
        unsigned* s3hi = (unsigned*)(smref + OFF_W3HI);
        unsigned* s3lo = (unsigned*)(smref + OFF_W3LO);
        for (int i = tid; i < 128 * 64; i += 256) {
            int r = i >> 6, wd = i & 63;
            s2hi[r * (PT / 2) + wd] = g2hi[i];
            s2lo[r * (PT / 2) + wd] = g2lo[i];
            s3hi[r * (PT / 2) + wd] = g3hi[i];
            s3lo[r * (PT / 2) + wd] = g3lo[i];
        }
    }
    if (tid < 128) { sB2[tid] = b2g[tid]; sB3[tid] = b3g[tid]; }
    __syncthreads();

    int w = tid >> 5, lane = tid & 31;
    int m0 = (w & 1) * 32, n0 = (w >> 1) * 32;
    int g = lane >> 2, tc = lane & 3;

    // GEMM A: H = silu(agg @ W2 + b2)
    {
        unsigned aHi = a_addr(sbase + OFF_AHI, m0, PT * 2, lane);
        unsigned aLo = aHi + A_BYTES;
        unsigned bHi = b_addr(sbase + OFF_W2HI, n0, PT * 2, lane);
        unsigned bLo = bHi + W_BYTES;
        float acc[2][4][4];
#pragma unroll
        for (int a = 0; a < 2; a++)
#pragma unroll
            for (int b = 0; b < 4; b++)
#pragma unroll
                for (int c = 0; c < 4; c++) acc[a][b][c] = 0.f;
        wgemm32<HID / 16, PT * 2>(aHi, aLo, bHi, bLo, acc);

#pragma unroll
        for (int mt = 0; mt < 2; mt++) {
            int ra = m0 + mt * 16 + g, rb2 = ra + 8;
#pragma unroll
            for (int nt = 0; nt < 4; nt++) {
                int col = n0 + nt * 8 + 2 * tc;
                float x0 = acc[mt][nt][0] + sB2[col];
                float x1 = acc[mt][nt][1] + sB2[col + 1];
                float x2 = acc[mt][nt][2] + sB2[col];
                float x3 = acc[mt][nt][3] + sB2[col + 1];
                x0 = x0 / (1.f + __expf(-x0));
                x1 = x1 / (1.f + __expf(-x1));
                x2 = x2 / (1.f + __expf(-x2));
                x3 = x3 / (1.f + __expf(-x3));
                bf162 h0, h1, l0, l1;
                h0.x = __float2bfloat16(x0); h0.y = __float2bfloat16(x1);
                h1.x = __float2bfloat16(x2); h1.y = __float2bfloat16(x3);
                l0.x = __float2bfloat16(x0 - __bfloat162float(h0.x));
                l0.y = __float2bfloat16(x1 - __bfloat162float(h0.y));
                l1.x = __float2bfloat16(x2 - __bfloat162float(h1.x));
                l1.y = __float2bfloat16(x3 - __bfloat162float(h1.y));
                *(bf162*)&sHhi[ra * PT + col]  = h0;
                *(bf162*)&sHhi[rb2 * PT + col] = h1;
                *(bf162*)&sHlo[ra * PT + col]  = l0;
                *(bf162*)&sHlo[rb2 * PT + col] = l1;
            }
        }
    }
    __syncthreads();

    // GEMM B: out = x + H @ W3 + b3
    {
        unsigned aHi = a_addr(sbase + OFF_HHI, m0, PT * 2, lane);
        unsigned aLo = aHi + A_BYTES;
        unsigned bHi = b_addr(sbase + OFF_W3HI, n0, PT * 2, lane);
        unsigned bLo = bHi + W_BYTES;
        float acc[2][4][4];
#pragma unroll
        for (int a = 0; a < 2; a++)
#pragma unroll
            for (int b = 0; b < 4; b++)
#pragma unroll
                for (int c = 0; c < 4; c++) acc[a][b][c] = 0.f;
        wgemm32<HID / 16, PT * 2>(aHi, aLo, bHi, bLo, acc);

        float* out = last ? dout : g_x;
#pragma unroll
        for (int mt = 0; mt < 2; mt++) {
#pragma unroll
            for (int dr = 0; dr < 2; dr++) {
                int r = m0 + mt * 16 + g + dr * 8;
                long ro = (long)(rb + r) * HID;
#pragma unroll
                for (int nt = 0; nt < 4; nt++) {
                    int col = n0 + nt * 8 + 2 * tc;
                    float v0 = acc[mt][nt][2 * dr]     + sB3[col] + g_x[ro + col];
                    float v1 = acc[mt][nt][2 * dr + 1] + sB3[col + 1] + g_x[ro + col + 1];
                    *(float2*)&out[ro + col] = make_float2(v0, v1);
                }
            }
        }
    }
}

// ---------------- launch ----------------
extern "C" void kernel_launch(void* const* d_in, const int* in_sizes, int n_in,
                              void* d_out, int out_size) {
    const int*   z       = (const int*)d_in[0];
    const int*   ei      = (const int*)d_in[1];
    const float* ew      = (const float*)d_in[2];
    const float* emb     = (const float*)d_in[3];
    const float* neemb   = (const float*)d_in[4];
    const float* neprojw = (const float*)d_in[5];
    const float* neprojb = (const float*)d_in[6];
    const float* necatw  = (const float*)d_in[7];
    const float* necatb  = (const float*)d_in[8];
    const float* means   = (const float*)d_in[9];
    const float* betas   = (const float*)d_in[10];
    const float* mlpw1   = (const float*)d_in[11];
    const float* mlpb1   = (const float*)d_in[12];
    const float* mlpw2   = (const float*)d_in[13];
    const float* mlpb2   = (const float*)d_in[14];
    const float* lin1w   = (const float*)d_in[15];
    const float* lin2w   = (const float*)d_in[16];
    const float* lin2b   = (const float*)d_in[17];
    const float* linw    = (const float*)d_in[18];
    const float* linb    = (const float*)d_in[19];
    float* outp = (float*)d_out;

    const int T_BYTES = HID * PT * 2, R_BYTES = HID * PR * 2;
    const int smI = 4 * T_BYTES + 4 * R_BYTES + 4096;            // 217088
    const int smN = 4 * R_BYTES + HID * PF * 4 + 4096;           // 145408
    const int smG = 2 * (64 * PT * 2) + 2 * T_BYTES + 512;       // 104960
    const int smG2 = 4 * (64 * PT * 2) + 4 * T_BYTES + 1024;     // 209920

    cudaFuncSetAttribute(k_edge<0>, cudaFuncAttributeMaxDynamicSharedMemorySize, smI);
    cudaFuncSetAttribute(k_edge<1>, cudaFuncAttributeMaxDynamicSharedMemorySize, smN);
    cudaFuncSetAttribute(k_ngemm,   cudaFuncAttributeMaxDynamicSharedMemorySize, smG);
    cudaFuncSetAttribute(k_ngemm2,  cudaFuncAttributeMaxDynamicSharedMemorySize, smG2);

    // ---- sort edges by destination + precompute per-edge data ----
    k_zero_cnt<<<NN / 256, 256>>>();
    k_hist<<<EE / 256, 256>>>(ei);
    k_scan<<<1, 1024>>>();
    k_place<<<EE / 256, 256>>>(ei);
    k_build<<<EE / 8, 256>>>(ei, ew, means, betas);
    k_gather<<<NN * HID / 256, 256>>>(z, emb, neemb);   // also zeroes g_agg

    // ---- weight prep ----
    k_wprep1<<<(NLAY * HID * K1 + 255) / 256, 256>>>(mlpw1, 0, NLAY);
    k_wprep1<<<(HID * K1 + 255) / 256, 256>>>(neprojw, 1, 1);
    k_wprep2<<<(NLAY * HID * HID + 255) / 256, 256>>>(mlpw2);
    k_wprepN<<<64, 256>>>(necatw, 0);
    k_wprepN<<<64, 256>>>(necatw + HID * HID, 1);
    for (int l = 0; l < NLAY; l++) {
        k_wprepN<<<64, 256>>>(lin1w + (size_t)l * HID * HID, 2 + l);
        k_wprepN<<<64, 256>>>(lin2w + (size_t)l * HID * HID, 8 + l);
        k_wprepN<<<64, 256>>>(linw  + (size_t)l * HID * HID, 14 + l);
    }

    // ---- NeighborEmbedding ----
    k_edge<1><<<148, 512, smN>>>(0, neprojb, nullptr);
    k_ngemm<<<NN / 64, 256, smG>>>(0, 0, necatb, -1, 2, 0, 0, outp);   // h2 = x@Wtop + b
    k_ngemm<<<NN / 64, 256, smG>>>(3, 1, nullptr, 2, 0, 0, 0, outp);   // x = h2 + agg@Wbot

    // ---- interaction layers ----
    for (int l = 0; l < NLAY; l++) {
        k_ngemm<<<NN / 64, 256, smG>>>(0, 2 + l, nullptr, -1, 1, 0, 1, outp);  // h = x@lin1, zero agg
        k_edge<0><<<148, 512, smI>>>(l, mlpb1 + (size_t)l * HID, mlpb2 + (size_t)l * HID);
        k_ngemm2<<<NN / 64, 256, smG2>>>(8 + l, 14 + l, lin2b + (size_t)l * HID,
                                         linb + (size_t)l * HID, l == NLAY - 1, outp);
    }
}

// round 9
// speedup vs baseline: 4.8000x; 1.0329x over previous
#include <cuda_runtime.h>
#include <cuda_bf16.h>
#include <math.h>

// ---------------- problem constants ----------------
#define NN    8192
#define EE    262144
#define HID   128
#define NRBF  50
#define K1    64
#define NLAY  6
#define PR    72           // smem pitch (bf16) for rbf / W1^T
#define PT    136          // smem pitch (bf16) for T / W2^T / node tiles
#define PF    132          // smem pitch (f32) for F tile
#define NSLOT 20

typedef __nv_bfloat16  bf16;
typedef __nv_bfloat162 bf162;

// ---------------- device scratch ----------------
__device__ __align__(16) bf16 g_rbf_hi[(size_t)EE * K1];
__device__ __align__(16) bf16 g_rbf_lo[(size_t)EE * K1];
__device__ __align__(16) bf16 g_w1t_hi[NLAY * HID * K1];
__device__ __align__(16) bf16 g_w1t_lo[NLAY * HID * K1];
__device__ __align__(16) bf16 g_w2t_hi[NLAY * HID * HID];
__device__ __align__(16) bf16 g_w2t_lo[NLAY * HID * HID];
__device__ __align__(16) bf16 g_npt_hi[HID * K1];
__device__ __align__(16) bf16 g_npt_lo[HID * K1];
__device__ __align__(16) bf16 g_nwt_hi[NSLOT * HID * HID];
__device__ __align__(16) bf16 g_nwt_lo[NSLOT * HID * HID];
__device__ float g_cut[EE];
__device__ float g_cutm[EE];
__device__ int   g_srow[EE];
__device__ int   g_sdst[EE];
__device__ int   g_perm[EE];
__device__ int   g_cnt[NN];
__device__ int   g_offm[NN];
__device__ float g_x  [NN * HID];
__device__ float g_h  [NN * HID];
__device__ float g_agg[NN * HID];
__device__ float g_nex[NN * HID];

// ---------------- small helper kernels ----------------
__global__ void k_zero_cnt() {
    int i = blockIdx.x * blockDim.x + threadIdx.x;
    if (i < NN) g_cnt[i] = 0;
}

__global__ void k_hist(const int* __restrict__ ei) {
    int e = blockIdx.x * blockDim.x + threadIdx.x;
    if (e < EE) atomicAdd(&g_cnt[ei[EE + e]], 1);
}

__global__ void k_scan() {
    __shared__ int part[1024];
    int t = threadIdx.x;
    int base = t * 8;
    int loc[8];
    int s = 0;
#pragma unroll
    for (int i = 0; i < 8; i++) { loc[i] = s; s += g_cnt[base + i]; }
    part[t] = s;
    __syncthreads();
    int val = s;
    for (int off = 1; off < 1024; off <<= 1) {
        int v = (t >= off) ? part[t - off] : 0;
        __syncthreads();
        val += v;
        part[t] = val;
        __syncthreads();
    }
    int pre = (t == 0) ? 0 : part[t - 1];
#pragma unroll
    for (int i = 0; i < 8; i++) g_offm[base + i] = pre + loc[i];
}

__global__ void k_place(const int* __restrict__ ei) {
    int e = blockIdx.x * blockDim.x + threadIdx.x;
    if (e < EE) {
        int c = ei[EE + e];
        int p = atomicAdd(&g_offm[c], 1);
        g_perm[p] = e;
    }
}

__global__ void k_build(const int* __restrict__ ei, const float* __restrict__ ew,
                        const float* __restrict__ means, const float* __restrict__ betas) {
    int warp = (blockIdx.x * blockDim.x + threadIdx.x) >> 5;
    int lane = threadIdx.x & 31;
    if (warp >= EE) return;
    int e = g_perm[warp];
    int r = ei[e];
    int c = ei[EE + e];
    float d = ew[e];
    float cut = 0.5f * (cosf(d * 0.628318530717958647692f) + 1.0f);
    if (!(d < 5.0f)) cut = 0.f;
    float ex = __expf(-d);
    size_t ro = (size_t)warp * K1;
    {
        float m = means[lane], b = betas[lane];
        float v = ex - m;
        float val = cut * __expf(-b * v * v);
        bf16 hi = __float2bfloat16(val);
        g_rbf_hi[ro + lane] = hi;
        g_rbf_lo[ro + lane] = __float2bfloat16(val - __bfloat162float(hi));
    }
    int k2 = lane + 32;
    float val2 = 0.f;
    if (k2 < NRBF) {
        float m = means[k2], b = betas[k2];
        float v = ex - m;
        val2 = cut * __expf(-b * v * v);
    }
    bf16 hi2 = __float2bfloat16(val2);
    g_rbf_hi[ro + k2] = hi2;
    g_rbf_lo[ro + k2] = __float2bfloat16(val2 - __bfloat162float(hi2));
    if (lane == 0) {
        g_cut[warp]  = cut;
        g_cutm[warp] = (r != c) ? cut : 0.f;
        g_srow[warp] = r;
        g_sdst[warp] = c;
    }
}

__global__ void k_gather(const int* __restrict__ z, const float* __restrict__ emb,
                         const float* __restrict__ neemb) {
    int i = blockIdx.x * blockDim.x + threadIdx.x;
    if (i >= NN * HID) return;
    int n = i >> 7, c = i & 127;
    int zi = z[n];
    g_x[i]   = emb[zi * HID + c];
    g_nex[i] = neemb[zi * HID + c];
    g_agg[i] = 0.f;
}

// weight prep: transpose + bf16 hi/lo split
__global__ void k_wprep1(const float* __restrict__ w, int mode, int layers) {
    int i = blockIdx.x * blockDim.x + threadIdx.x;
    if (i >= layers * HID * K1) return;
    int k = i & (K1 - 1);
    int n = (i >> 6) & (HID - 1);
    int l = i >> 13;
    float v = (k < NRBF) ? w[((size_t)l * NRBF + k) * HID + n] : 0.f;
    bf16 hi = __float2bfloat16(v);
    bf16 lo = __float2bfloat16(v - __bfloat162float(hi));
    if (mode == 0) { g_w1t_hi[i] = hi; g_w1t_lo[i] = lo; }
    else           { g_npt_hi[i] = hi; g_npt_lo[i] = lo; }
}

__global__ void k_wprep2(const float* __restrict__ w) {
    int i = blockIdx.x * blockDim.x + threadIdx.x;
    if (i >= NLAY * HID * HID) return;
    int k = i & (HID - 1);
    int n = (i >> 7) & (HID - 1);
    int l = i >> 14;
    float v = w[((size_t)l * HID + k) * HID + n];
    bf16 hi = __float2bfloat16(v);
    g_w2t_hi[i] = hi;
    g_w2t_lo[i] = __float2bfloat16(v - __bfloat162float(hi));
}

// all node-GEMM weights (20 slots) in one launch: grid = 20*64 blocks
__global__ void k_wprepAll(const float* __restrict__ necatw, const float* __restrict__ lin1w,
                           const float* __restrict__ lin2w, const float* __restrict__ linw) {
    int slot = blockIdx.x >> 6;
    int i = (blockIdx.x & 63) * 256 + threadIdx.x;   // 0..16383
    const float* src;
    if (slot < 2)       src = necatw + (size_t)slot * HID * HID;
    else if (slot < 8)  src = lin1w + (size_t)(slot - 2) * HID * HID;
    else if (slot < 14) src = lin2w + (size_t)(slot - 8) * HID * HID;
    else                src = linw  + (size_t)(slot - 14) * HID * HID;
    int k = i & (HID - 1);
    int n = i >> 7;
    float v = src[k * HID + n];
    bf16 hi = __float2bfloat16(v);
    g_nwt_hi[(size_t)slot * HID * HID + i] = hi;
    g_nwt_lo[(size_t)slot * HID * HID + i] = __float2bfloat16(v - __bfloat162float(hi));
}

// ---------------- warp-MMA helpers ----------------
__device__ __forceinline__ void mma16816(float c[4], const unsigned a[4], const unsigned b[2]) {
    asm volatile(
        "mma.sync.aligned.m16n8k16.row.col.f32.bf16.bf16.f32 "
        "{%0,%1,%2,%3}, {%4,%5,%6,%7}, {%8,%9}, {%0,%1,%2,%3};\n"
        : "+f"(c[0]), "+f"(c[1]), "+f"(c[2]), "+f"(c[3])
        : "r"(a[0]), "r"(a[1]), "r"(a[2]), "r"(a[3]), "r"(b[0]), "r"(b[1]));
}

__device__ __forceinline__ void ldsm4(unsigned r[4], unsigned addr) {
    asm volatile("ldmatrix.sync.aligned.m8n8.x4.shared.b16 {%0,%1,%2,%3}, [%4];"
        : "=r"(r[0]), "=r"(r[1]), "=r"(r[2]), "=r"(r[3]) : "r"(addr));
}

__device__ __forceinline__ unsigned a_addr(unsigned base, int m0, int PB, int lane) {
    int sel = lane >> 3, li = lane & 7;
    return base + (m0 + li + (sel & 1) * 8) * PB + ((sel >> 1) * 8) * 2;
}
__device__ __forceinline__ unsigned b_addr(unsigned base, int n0, int PB, int lane) {
    int sel = lane >> 3, li = lane & 7;
    return base + (n0 + li + (sel >> 1) * 8) * PB + ((sel & 1) * 8) * 2;
}

template <int KSTEPS, int PB>
__device__ __forceinline__ void wgemm32(unsigned aHi, unsigned aLo,
                                        unsigned bHi, unsigned bLo,
                                        float acc[2][4][4]) {
#pragma unroll
    for (int ks = 0; ks < KSTEPS; ks++) {
        unsigned off = ks * 32;
        unsigned ah0[4], ah1[4], al0[4], al1[4], bh0[4], bh1[4], bl0[4], bl1[4];
        ldsm4(ah0, aHi + off);
        ldsm4(ah1, aHi + 16 * PB + off);
        ldsm4(al0, aLo + off);
        ldsm4(al1, aLo + 16 * PB + off);
        ldsm4(bh0, bHi + off);
        ldsm4(bh1, bHi + 16 * PB + off);
        ldsm4(bl0, bLo + off);
        ldsm4(bl1, bLo + 16 * PB + off);
#pragma unroll
        for (int nt = 0; nt < 4; nt++) {
            const unsigned* bh = (nt < 2) ? (bh0 + 2 * nt) : (bh1 + 2 * (nt - 2));
            const unsigned* bl = (nt < 2) ? (bl0 + 2 * nt) : (bl1 + 2 * (nt - 2));
            mma16816(acc[0][nt], ah0, bh);
            mma16816(acc[1][nt], ah1, bh);
            mma16816(acc[0][nt], ah0, bl);
            mma16816(acc[1][nt], ah1, bl);
            mma16816(acc[0][nt], al0, bh);
            mma16816(acc[1][nt], al1, bh);
        }
    }
}

// ---------------- cp.async helpers ----------------
__device__ __forceinline__ void cpa16(unsigned saddr, const void* gaddr) {
    asm volatile("cp.async.ca.shared.global [%0], [%1], 16;" :: "r"(saddr), "l"(gaddr));
}
__device__ __forceinline__ void cpa_commit() { asm volatile("cp.async.commit_group;"); }
__device__ __forceinline__ void cpa_wait0()  { asm volatile("cp.async.wait_group 0;"); }

// ---------------- fused edge MLP + segmented aggregation (persistent, pipelined)
template <int NE>
__global__ void __launch_bounds__(512, 1)
k_edge(int layer, const float* __restrict__ b1g, const float* __restrict__ b2g) {
    extern __shared__ __align__(16) char smref[];
    constexpr int T_BYTES = HID * PT * 2;   // 34816
    constexpr int R_BYTES = HID * PR * 2;   // 18432
    const int OFF_THI  = 0;
    const int OFF_TLO  = T_BYTES;
    const int OFF_W2HI = 2 * T_BYTES;
    const int OFF_W2LO = 3 * T_BYTES;
    const int OFF_RHI  = NE ? 0 : 4 * T_BYTES;
    const int OFF_RLO  = OFF_RHI + R_BYTES;
    const int OFF_W1HI = OFF_RLO + R_BYTES;
    const int OFF_W1LO = OFF_W1HI + R_BYTES;
    const int OFF_F    = NE ? (OFF_W1LO + R_BYTES) : 0;   // interaction: overlay T region
    const int OFF_MISC = NE ? (OFF_F + HID * PF * 4) : (OFF_RHI + 4 * R_BYTES);
    const int OFF_CUT  = OFF_MISC;          // [2][128] f32
    const int OFF_ROW  = OFF_MISC + 1024;   // [2][128] i32
    const int OFF_DST  = OFF_MISC + 2048;   // [2][128] i32
    const int OFF_B1   = OFF_MISC + 3072;
    const int OFF_B2   = OFF_MISC + 3584;

    bf16* sThi  = (bf16*)(smref + OFF_THI);
    bf16* sTlo  = (bf16*)(smref + OFF_TLO);
    float* sF   = (float*)(smref + OFF_F);
    float* sB1  = (float*)(smref + OFF_B1);
    float* sB2  = (float*)(smref + OFF_B2);

    int tid = threadIdx.x;
    unsigned sbase = (unsigned)__cvta_generic_to_shared(smref);

    const long NT = EE / 128;
    long tile = blockIdx.x;
    int buf = 0;

    // issue tile-0 rbf + metadata copy
    if (tile < NT) {
        long ebase = tile * 128;
        for (int c = tid; c < 1024; c += 512) {
            int r = c >> 3, ch = c & 7;
            cpa16(sbase + OFF_RHI + r * 144 + ch * 16, &g_rbf_hi[(ebase + r) * K1 + ch * 8]);
            cpa16(sbase + OFF_RLO + r * 144 + ch * 16, &g_rbf_lo[(ebase + r) * K1 + ch * 8]);
        }
        if (tid < 32) {
            const float* cs = NE ? g_cutm : g_cut;
            cpa16(sbase + OFF_CUT + tid * 16, cs + ebase + tid * 4);
        } else if (tid < 64) {
            int t = tid - 32;
            cpa16(sbase + OFF_ROW + t * 16, g_srow + ebase + t * 4);
        } else if (tid < 96) {
            int t = tid - 64;
            cpa16(sbase + OFF_DST + t * 16, g_sdst + ebase + t * 4);
        }
    }
    cpa_commit();

    // ---- stage weights once ----
    {
        const unsigned* ghi = (const unsigned*)(NE ? g_npt_hi : (g_w1t_hi + (size_t)layer * HID * K1));
        const unsigned* glo = (const unsigned*)(NE ? g_npt_lo : (g_w1t_lo + (size_t)layer * HID * K1));
        unsigned* shi = (unsigned*)(smref + OFF_W1HI);
        unsigned* slo = (unsigned*)(smref + OFF_W1LO);
        for (int i = tid; i < 128 * 32; i += 512) {
            int r = i >> 5, wd = i & 31;
            shi[r * (PR / 2) + wd] = ghi[i];
            slo[r * (PR / 2) + wd] = glo[i];
        }
    }
    if (!NE) {
        const unsigned* ghi = (const unsigned*)(g_w2t_hi + (size_t)layer * HID * HID);
        const unsigned* glo = (const unsigned*)(g_w2t_lo + (size_t)layer * HID * HID);
        unsigned* shi = (unsigned*)(smref + OFF_W2HI);
        unsigned* slo = (unsigned*)(smref + OFF_W2LO);
        for (int i = tid; i < 128 * 64; i += 512) {
            int r = i >> 6, wd = i & 63;
            shi[r * (PT / 2) + wd] = ghi[i];
            slo[r * (PT / 2) + wd] = glo[i];
        }
    }
    if (tid < 128) {
        sB1[tid] = b1g[tid];
        sB2[tid] = NE ? 0.f : b2g[tid];
    }

    int w = tid >> 5, lane = tid & 31;
    int m0 = (w & 3) * 32, n0 = (w >> 2) * 32;
    int g = lane >> 2, tc = lane & 3;

    unsigned g1aHi = a_addr(sbase + OFF_RHI,  m0, PR * 2, lane);
    unsigned g1aLo = g1aHi + R_BYTES;
    unsigned g1bHi = b_addr(sbase + OFF_W1HI, n0, PR * 2, lane);
    unsigned g1bLo = g1bHi + R_BYTES;
    unsigned g2aHi = a_addr(sbase + OFF_THI,  m0, PT * 2, lane);
    unsigned g2aLo = g2aHi + T_BYTES;
    unsigned g2bHi = b_addr(sbase + OFF_W2HI, n0, PT * 2, lane);
    unsigned g2bLo = g2bHi + T_BYTES;

    const float* hsrc = NE ? g_nex : g_h;

    for (; tile < NT; tile += gridDim.x, buf ^= 1) {
        cpa_wait0();
        __syncthreads();   // rbf + meta[buf] ready; prev aggregation done

        float* sCut = (float*)(smref + OFF_CUT + buf * 512);
        int*   sRow = (int*)(smref + OFF_ROW + buf * 512);
        int*   sDst = (int*)(smref + OFF_DST + buf * 512);

        // ---- GEMM1: rbf[128,64] @ W1[64,128] ----
        {
            float acc[2][4][4];
#pragma unroll
            for (int a = 0; a < 2; a++)
#pragma unroll
                for (int b = 0; b < 4; b++)
#pragma unroll
                    for (int c = 0; c < 4; c++) acc[a][b][c] = 0.f;
            wgemm32<K1 / 16, PR * 2>(g1aHi, g1aLo, g1bHi, g1bLo, acc);

            if (NE) {
#pragma unroll
                for (int mt = 0; mt < 2; mt++) {
                    int ra = m0 + mt * 16 + g, rb2 = ra + 8;
                    float cua = sCut[ra], cub = sCut[rb2];
#pragma unroll
                    for (int nt = 0; nt < 4; nt++) {
                        int col = n0 + nt * 8 + 2 * tc;
                        float2 v0, v1;
                        v0.x = (acc[mt][nt][0] + sB1[col])     * cua;
                        v0.y = (acc[mt][nt][1] + sB1[col + 1]) * cua;
                        v1.x = (acc[mt][nt][2] + sB1[col])     * cub;
                        v1.y = (acc[mt][nt][3] + sB1[col + 1]) * cub;
                        *(float2*)&sF[ra * PF + col]  = v0;
                        *(float2*)&sF[rb2 * PF + col] = v1;
                    }
                }
            } else {
#pragma unroll
                for (int mt = 0; mt < 2; mt++) {
                    int ra = m0 + mt * 16 + g, rb2 = ra + 8;
#pragma unroll
                    for (int nt = 0; nt < 4; nt++) {
                        int col = n0 + nt * 8 + 2 * tc;
                        float x0 = acc[mt][nt][0] + sB1[col];
                        float x1 = acc[mt][nt][1] + sB1[col + 1];
                        float x2 = acc[mt][nt][2] + sB1[col];
                        float x3 = acc[mt][nt][3] + sB1[col + 1];
                        x0 = x0 / (1.f + __expf(-x0));
                        x1 = x1 / (1.f + __expf(-x1));
                        x2 = x2 / (1.f + __expf(-x2));
                        x3 = x3 / (1.f + __expf(-x3));
                        bf162 h0, h1, l0, l1;
                        h0.x = __float2bfloat16(x0); h0.y = __float2bfloat16(x1);
                        h1.x = __float2bfloat16(x2); h1.y = __float2bfloat16(x3);
                        l0.x = __float2bfloat16(x0 - __bfloat162float(h0.x));
                        l0.y = __float2bfloat16(x1 - __bfloat162float(h0.y));
                        l1.x = __float2bfloat16(x2 - __bfloat162float(h1.x));
                        l1.y = __float2bfloat16(x3 - __bfloat162float(h1.y));
                        *(bf162*)&sThi[ra * PT + col]  = h0;
                        *(bf162*)&sThi[rb2 * PT + col] = h1;
                        *(bf162*)&sTlo[ra * PT + col]  = l0;
                        *(bf162*)&sTlo[rb2 * PT + col] = l1;
                    }
                }
            }
        }
        __syncthreads();   // all rbf reads done; T written

        // ---- issue next tile's rbf + metadata ----
        {
            long nxt = tile + gridDim.x;
            if (nxt < NT) {
                long ebase = nxt * 128;
                int nb = buf ^ 1;
                for (int c = tid; c < 1024; c += 512) {
                    int r = c >> 3, ch = c & 7;
                    cpa16(sbase + OFF_RHI + r * 144 + ch * 16, &g_rbf_hi[(ebase + r) * K1 + ch * 8]);
                    cpa16(sbase + OFF_RLO + r * 144 + ch * 16, &g_rbf_lo[(ebase + r) * K1 + ch * 8]);
                }
                if (tid < 32) {
                    const float* cs = NE ? g_cutm : g_cut;
                    cpa16(sbase + OFF_CUT + nb * 512 + tid * 16, cs + ebase + tid * 4);
                } else if (tid < 64) {
                    int t = tid - 32;
                    cpa16(sbase + OFF_ROW + nb * 512 + t * 16, g_srow + ebase + t * 4);
                } else if (tid < 96) {
                    int t = tid - 64;
                    cpa16(sbase + OFF_DST + nb * 512 + t * 16, g_sdst + ebase + t * 4);
                }
            }
            cpa_commit();
        }

        // ---- GEMM2 (interaction only) ----
        if (!NE) {
            float acc[2][4][4];
#pragma unroll
            for (int a = 0; a < 2; a++)
#pragma unroll
                for (int b = 0; b < 4; b++)
#pragma unroll
                    for (int c = 0; c < 4; c++) acc[a][b][c] = 0.f;
            wgemm32<HID / 16, PT * 2>(g2aHi, g2aLo, g2bHi, g2bLo, acc);
            __syncthreads();   // all T reads done before F overlays T

#pragma unroll
            for (int mt = 0; mt < 2; mt++) {
                int ra = m0 + mt * 16 + g, rb2 = ra + 8;
                float cua = sCut[ra], cub = sCut[rb2];
#pragma unroll
                for (int nt = 0; nt < 4; nt++) {
                    int col = n0 + nt * 8 + 2 * tc;
                    float2 v0, v1;
                    v0.x = (acc[mt][nt][0] + sB2[col])     * cua;
                    v0.y = (acc[mt][nt][1] + sB2[col + 1]) * cua;
                    v1.x = (acc[mt][nt][2] + sB2[col])     * cub;
                    v1.y = (acc[mt][nt][3] + sB2[col + 1]) * cub;
                    *(float2*)&sF[ra * PF + col]  = v0;
                    *(float2*)&sF[rb2 * PF + col] = v1;
                }
            }
        }
        __syncthreads();   // F ready

        // ---- segmented aggregation ----
        int grp = tid >> 7;
        int f = tid & 127;
        int e0 = grp * 32;
        float accv = 0.f;
        int cur = sDst[e0];
#pragma unroll 1
        for (int b = 0; b < 4; b++) {
            float hb[8];
#pragma unroll
            for (int j = 0; j < 8; j++)
                hb[j] = hsrc[(long)sRow[e0 + b * 8 + j] * HID + f];
#pragma unroll
            for (int j = 0; j < 8; j++) {
                int e = e0 + b * 8 + j;
                int dd = sDst[e];
                if (dd != cur) {
                    atomicAdd(&g_agg[(long)cur * HID + f], accv);
                    accv = 0.f;
                    cur = dd;
                }
                accv = fmaf(hb[j], sF[e * PF + f], accv);
            }
        }
        atomicAdd(&g_agg[(long)cur * HID + f], accv);
    }
}

// ---------------- node-kernel shared pieces ----------------
#define NA_BYTES  (64 * PT * 2)     // 17408
#define NW_BYTES  (HID * PT * 2)    // 34816
#define NOFF_A    0
#define NOFF_WA   (2 * NA_BYTES)
#define NOFF_WB   (NOFF_WA + 2 * NW_BYTES)
#define NOFF_H    (NOFF_WB + 2 * NW_BYTES)
#define NOFF_B    (NOFF_H + 2 * NA_BYTES)
#define NSM_TOTAL (NOFF_B + 1024)

__device__ __forceinline__ void stageA_f32(char* smref, int off, const float* src,
                                           int rb, int tid) {
    bf16* hi = (bf16*)(smref + off);
    bf16* lo = (bf16*)(smref + off + NA_BYTES);
    for (int i = tid; i < 64 * HID; i += 256) {
        int r = i >> 7, k = i & 127;
        float v = src[(long)(rb + r) * HID + k];
        bf16 h = __float2bfloat16(v);
        hi[r * PT + k] = h;
        lo[r * PT + k] = __float2bfloat16(v - __bfloat162float(h));
    }
}

__device__ __forceinline__ void stageW(char* smref, int off, int slot, int tid) {
    const unsigned* ghi = (const unsigned*)(g_nwt_hi + (size_t)slot * HID * HID);
    const unsigned* glo = (const unsigned*)(g_nwt_lo + (size_t)slot * HID * HID);
    unsigned* shi = (unsigned*)(smref + off);
    unsigned* slo = (unsigned*)(smref + off + NW_BYTES);
    for (int i = tid; i < 128 * 64; i += 256) {
        int r = i >> 6, wd = i & 63;
        shi[r * (PT / 2) + wd] = ghi[i];
        slo[r * (PT / 2) + wd] = glo[i];
    }
}

// ---------------- NE node kernel: x = x@Wtop + agg@Wbot + b; h = x@lin1[0] ----
__global__ void __launch_bounds__(256, 1)
k_nodeNE(const float* __restrict__ necatb) {
    extern __shared__ __align__(16) char smref[];
    float* sBa = (float*)(smref + NOFF_B);

    int tid = threadIdx.x;
    int rb = blockIdx.x * 64;
    unsigned sbase = (unsigned)__cvta_generic_to_shared(smref);

    stageA_f32(smref, NOFF_A, g_x, rb, tid);
    stageW(smref, NOFF_WA, 0, tid);   // necatw top
    stageW(smref, NOFF_WB, 1, tid);   // necatw bottom
    if (tid < 128) sBa[tid] = necatb[tid];
    __syncthreads();

    int w = tid >> 5, lane = tid & 31;
    int m0 = (w & 1) * 32, n0 = (w >> 1) * 32;
    int g = lane >> 2, tc = lane & 3;

    float acc[2][4][4];
#pragma unroll
    for (int a = 0; a < 2; a++)
#pragma unroll
        for (int b = 0; b < 4; b++)
#pragma unroll
            for (int c = 0; c < 4; c++) acc[a][b][c] = 0.f;

    // GEMM A: acc = x @ Wtop
    {
        unsigned aHi = a_addr(sbase + NOFF_A, m0, PT * 2, lane);
        unsigned bHi = b_addr(sbase + NOFF_WA, n0, PT * 2, lane);
        wgemm32<HID / 16, PT * 2>(aHi, aHi + NA_BYTES, bHi, bHi + NW_BYTES, acc);
    }
    __syncthreads();   // A reads done

    // restage A = agg tile; Wa = lin1[0] (Wa dead)
    stageA_f32(smref, NOFF_A, g_agg, rb, tid);
    stageW(smref, NOFF_WA, 2, tid);
    __syncthreads();   // all g_agg reads done (race-safe), staged data visible

    // zero agg rows AFTER all threads have staged them
    {
        float4* za = (float4*)(g_agg + (long)rb * HID);
        for (int i = tid; i < 64 * HID / 4; i += 256) za[i] = make_float4(0.f, 0.f, 0.f, 0.f);
    }

    // GEMM B: acc += agg @ Wbot; x = acc + b; write g_x + stage into H region
    {
        unsigned aHi = a_addr(sbase + NOFF_A, m0, PT * 2, lane);
        unsigned bHi = b_addr(sbase + NOFF_WB, n0, PT * 2, lane);
        wgemm32<HID / 16, PT * 2>(aHi, aHi + NA_BYTES, bHi, bHi + NW_BYTES, acc);

        bf16* xhi = (bf16*)(smref + NOFF_H);
        bf16* xlo = (bf16*)(smref + NOFF_H + NA_BYTES);
#pragma unroll
        for (int mt = 0; mt < 2; mt++) {
#pragma unroll
            for (int dr = 0; dr < 2; dr++) {
                int r = m0 + mt * 16 + g + dr * 8;
                long ro = (long)(rb + r) * HID;
#pragma unroll
                for (int nt = 0; nt < 4; nt++) {
                    int col = n0 + nt * 8 + 2 * tc;
                    float v0 = acc[mt][nt][2 * dr]     + sBa[col];
                    float v1 = acc[mt][nt][2 * dr + 1] + sBa[col + 1];
                    *(float2*)&g_x[ro + col] = make_float2(v0, v1);
                    bf162 h, l;
                    h.x = __float2bfloat16(v0);
                    h.y = __float2bfloat16(v1);
                    l.x = __float2bfloat16(v0 - __bfloat162float(h.x));
                    l.y = __float2bfloat16(v1 - __bfloat162float(h.y));
                    *(bf162*)&xhi[r * PT + col] = h;
                    *(bf162*)&xlo[r * PT + col] = l;
                }
            }
        }
    }
    __syncthreads();

    // GEMM C: h = x @ lin1[0]
    {
        float acc2[2][4][4];
#pragma unroll
        for (int a = 0; a < 2; a++)
#pragma unroll
            for (int b = 0; b < 4; b++)
#pragma unroll
                for (int c = 0; c < 4; c++) acc2[a][b][c] = 0.f;
        unsigned aHi = a_addr(sbase + NOFF_H, m0, PT * 2, lane);
        unsigned bHi = b_addr(sbase + NOFF_WA, n0, PT * 2, lane);
        wgemm32<HID / 16, PT * 2>(aHi, aHi + NA_BYTES, bHi, bHi + NW_BYTES, acc2);
#pragma unroll
        for (int mt = 0; mt < 2; mt++) {
#pragma unroll
            for (int dr = 0; dr < 2; dr++) {
                int r = m0 + mt * 16 + g + dr * 8;
                long ro = (long)(rb + r) * HID;
#pragma unroll
                for (int nt = 0; nt < 4; nt++) {
                    int col = n0 + nt * 8 + 2 * tc;
                    *(float2*)&g_h[ro + col] =
                        make_float2(acc2[mt][nt][2 * dr], acc2[mt][nt][2 * dr + 1]);
                }
            }
        }
    }
}

// ---------------- layer node kernel ----------------
// x (+)= silu(agg@lin2 + b2) @ lin + b3 ; if !last: h = x@lin1[l+1], zero agg
__global__ void __launch_bounds__(256, 1)
k_nodeL(int l, int last, const float* __restrict__ b2g, const float* __restrict__ b3g,
        float* dout) {
    extern __shared__ __align__(16) char smref[];
    float* sB2 = (float*)(smref + NOFF_B);
    float* sB3 = sB2 + 128;

    int tid = threadIdx.x;
    int rb = blockIdx.x * 64;
    unsigned sbase = (unsigned)__cvta_generic_to_shared(smref);

    stageA_f32(smref, NOFF_A, g_agg, rb, tid);
    stageW(smref, NOFF_WA, 8 + l, tid);    // lin2
    stageW(smref, NOFF_WB, 14 + l, tid);   // lin
    if (tid < 128) { sB2[tid] = b2g[tid]; sB3[tid] = b3g[tid]; }
    __syncthreads();

    int w = tid >> 5, lane = tid & 31;
    int m0 = (w & 1) * 32, n0 = (w >> 1) * 32;
    int g = lane >> 2, tc = lane & 3;

    // GEMM A: H = silu(agg @ lin2 + b2)
    {
        float acc[2][4][4];
#pragma unroll
        for (int a = 0; a < 2; a++)
#pragma unroll
            for (int b = 0; b < 4; b++)
#pragma unroll
                for (int c = 0; c < 4; c++) acc[a][b][c] = 0.f;
        unsigned aHi = a_addr(sbase + NOFF_A, m0, PT * 2, lane);
        unsigned bHi = b_addr(sbase + NOFF_WA, n0, PT * 2, lane);
        wgemm32<HID / 16, PT * 2>(aHi, aHi + NA_BYTES, bHi, bHi + NW_BYTES, acc);

        bf16* sHhi = (bf16*)(smref + NOFF_H);
        bf16* sHlo = (bf16*)(smref + NOFF_H + NA_BYTES);
#pragma unroll
        for (int mt = 0; mt < 2; mt++) {
            int ra = m0 + mt * 16 + g, rb2 = ra + 8;
#pragma unroll
            for (int nt = 0; nt < 4; nt++) {
                int col = n0 + nt * 8 + 2 * tc;
                float x0 = acc[mt][nt][0] + sB2[col];
                float x1 = acc[mt][nt][1] + sB2[col + 1];
                float x2 = acc[mt][nt][2] + sB2[col];
                float x3 = acc[mt][nt][3] + sB2[col + 1];
                x0 = x0 / (1.f + __expf(-x0));
                x1 = x1 / (1.f + __expf(-x1));
                x2 = x2 / (1.f + __expf(-x2));
                x3 = x3 / (1.f + __expf(-x3));
                bf162 h0, h1, l0, l1;
                h0.x = __float2bfloat16(x0); h0.y = __float2bfloat16(x1);
                h1.x = __float2bfloat16(x2); h1.y = __float2bfloat16(x3);
                l0.x = __float2bfloat16(x0 - __bfloat162float(h0.x));
                l0.y = __float2bfloat16(x1 - __bfloat162float(h0.y));
                l1.x = __float2bfloat16(x2 - __bfloat162float(h1.x));
                l1.y = __float2bfloat16(x3 - __bfloat162float(h1.y));
                *(bf162*)&sHhi[ra * PT + col]  = h0;
                *(bf162*)&sHhi[rb2 * PT + col] = h1;
                *(bf162*)&sHlo[ra * PT + col]  = l0;
                *(bf162*)&sHlo[rb2 * PT + col] = l1;
            }
        }
    }
    __syncthreads();

    // Wa dead: stage lin1[l+1]; zero agg rows (for next layer)
    if (!last) {
        stageW(smref, NOFF_WA, 2 + (l + 1), tid);
        float4* za = (float4*)(g_agg + (long)rb * HID);
        for (int i = tid; i < 64 * HID / 4; i += 256) za[i] = make_float4(0.f, 0.f, 0.f, 0.f);
    }

    // GEMM B: x = H @ lin + b3 + x_old
    {
        float acc[2][4][4];
#pragma unroll
        for (int a = 0; a < 2; a++)
#pragma unroll
            for (int b = 0; b < 4; b++)
#pragma unroll
                for (int c = 0; c < 4; c++) acc[a][b][c] = 0.f;
        unsigned aHi = a_addr(sbase + NOFF_H, m0, PT * 2, lane);
        unsigned bHi = b_addr(sbase + NOFF_WB, n0, PT * 2, lane);
        wgemm32<HID / 16, PT * 2>(aHi, aHi + NA_BYTES, bHi, bHi + NW_BYTES, acc);

        float* out = last ? dout : g_x;
        bf16* xhi = (bf16*)(smref + NOFF_A);
        bf16* xlo = (bf16*)(smref + NOFF_A + NA_BYTES);
#pragma unroll
        for (int mt = 0; mt < 2; mt++) {
#pragma unroll
            for (int dr = 0; dr < 2; dr++) {
                int r = m0 + mt * 16 + g + dr * 8;
                long ro = (long)(rb + r) * HID;
#pragma unroll
                for (int nt = 0; nt < 4; nt++) {
                    int col = n0 + nt * 8 + 2 * tc;
                    float v0 = acc[mt][nt][2 * dr]     + sB3[col] + g_x[ro + col];
                    float v1 = acc[mt][nt][2 * dr + 1] + sB3[col + 1] + g_x[ro + col + 1];
                    *(float2*)&out[ro + col] = make_float2(v0, v1);
                    if (!last) {
                        bf162 h, lo;
                        h.x = __float2bfloat16(v0);
                        h.y = __float2bfloat16(v1);
                        lo.x = __float2bfloat16(v0 - __bfloat162float(h.x));
                        lo.y = __float2bfloat16(v1 - __bfloat162float(h.y));
                        *(bf162*)&xhi[r * PT + col] = h;
                        *(bf162*)&xlo[r * PT + col] = lo;
                    }
                }
            }
        }
    }
    if (last) return;
    __syncthreads();

    // GEMM C: h = x @ lin1[l+1]
    {
        float acc[2][4][4];
#pragma unroll
        for (int a = 0; a < 2; a++)
#pragma unroll
            for (int b = 0; b < 4; b++)
#pragma unroll
                for (int c = 0; c < 4; c++) acc[a][b][c] = 0.f;
        unsigned aHi = a_addr(sbase + NOFF_A, m0, PT * 2, lane);
        unsigned bHi = b_addr(sbase + NOFF_WA, n0, PT * 2, lane);
        wgemm32<HID / 16, PT * 2>(aHi, aHi + NA_BYTES, bHi, bHi + NW_BYTES, acc);
#pragma unroll
        for (int mt = 0; mt < 2; mt++) {
#pragma unroll
            for (int dr = 0; dr < 2; dr++) {
                int r = m0 + mt * 16 + g + dr * 8;
                long ro = (long)(rb + r) * HID;
#pragma unroll
                for (int nt = 0; nt < 4; nt++) {
                    int col = n0 + nt * 8 + 2 * tc;
                    *(float2*)&g_h[ro + col] =
                        make_float2(acc[mt][nt][2 * dr], acc[mt][nt][2 * dr + 1]);
                }
            }
        }
    }
}

// ---------------- launch ----------------
extern "C" void kernel_launch(void* const* d_in, const int* in_sizes, int n_in,
                              void* d_out, int out_size) {
    const int*   z       = (const int*)d_in[0];
    const int*   ei      = (const int*)d_in[1];
    const float* ew      = (const float*)d_in[2];
    const float* emb     = (const float*)d_in[3];
    const float* neemb   = (const float*)d_in[4];
    const float* neprojw = (const float*)d_in[5];
    const float* neprojb = (const float*)d_in[6];
    const float* necatw  = (const float*)d_in[7];
    const float* necatb  = (const float*)d_in[8];
    const float* means   = (const float*)d_in[9];
    const float* betas   = (const float*)d_in[10];
    const float* mlpw1   = (const float*)d_in[11];
    const float* mlpb1   = (const float*)d_in[12];
    const float* mlpw2   = (const float*)d_in[13];
    const float* mlpb2   = (const float*)d_in[14];
    const float* lin1w   = (const float*)d_in[15];
    const float* lin2w   = (const float*)d_in[16];
    const float* lin2b   = (const float*)d_in[17];
    const float* linw    = (const float*)d_in[18];
    const float* linb    = (const float*)d_in[19];
    float* outp = (float*)d_out;

    const int T_BYTES = HID * PT * 2, R_BYTES = HID * PR * 2;
    const int smI = 4 * T_BYTES + 4 * R_BYTES + 4096;            // 217088
    const int smN = 4 * R_BYTES + HID * PF * 4 + 4096;           // 145408

    cudaFuncSetAttribute(k_edge<0>, cudaFuncAttributeMaxDynamicSharedMemorySize, smI);
    cudaFuncSetAttribute(k_edge<1>, cudaFuncAttributeMaxDynamicSharedMemorySize, smN);
    cudaFuncSetAttribute(k_nodeNE,  cudaFuncAttributeMaxDynamicSharedMemorySize, NSM_TOTAL);
    cudaFuncSetAttribute(k_nodeL,   cudaFuncAttributeMaxDynamicSharedMemorySize, NSM_TOTAL);

    // ---- sort edges by destination + precompute per-edge data ----
    k_zero_cnt<<<NN / 256, 256>>>();
    k_hist<<<EE / 256, 256>>>(ei);
    k_scan<<<1, 1024>>>();
    k_place<<<EE / 256, 256>>>(ei);
    k_build<<<EE / 8, 256>>>(ei, ew, means, betas);
    k_gather<<<NN * HID / 256, 256>>>(z, emb, neemb);   // also zeroes g_agg

    // ---- weight prep ----
    k_wprep1<<<(NLAY * HID * K1 + 255) / 256, 256>>>(mlpw1, 0, NLAY);
    k_wprep1<<<(HID * K1 + 255) / 256, 256>>>(neprojw, 1, 1);
    k_wprep2<<<(NLAY * HID * HID + 255) / 256, 256>>>(mlpw2);
    k_wprepAll<<<NSLOT * 64, 256>>>(necatw, lin1w, lin2w, linw);

    // ---- NeighborEmbedding + initial lin1 ----
    k_edge<1><<<148, 512, smN>>>(0, neprojb, nullptr);
    k_nodeNE<<<NN / 64, 256, NSM_TOTAL>>>(necatb);

    // ---- interaction layers ----
    for (int l = 0; l < NLAY; l++) {
        k_edge<0><<<148, 512, smI>>>(l, mlpb1 + (size_t)l * HID, mlpb2 + (size_t)l * HID);
        k_nodeL<<<NN / 64, 256, NSM_TOTAL>>>(l, l == NLAY - 1,
                                             lin2b + (size_t)l * HID,
                                             linb + (size_t)l * HID, outp);
    }
}

// round 10
// speedup vs baseline: 5.9625x; 1.2422x over previous
#include <cuda_runtime.h>
#include <cuda_fp16.h>
#include <math.h>

// ---------------- problem constants ----------------
#define NN    8192
#define EE    262144
#define HID   128
#define NRBF  50
#define K1    64
#define NLAY  6
#define PR    72           // smem pitch (fp16) for rbf / W1^T
#define PT    136          // smem pitch (fp16) for T / W2^T / node tiles
#define PF    132          // smem pitch (f32) for F tile
#define NSLOT 20

typedef __half  h16;
typedef __half2 h162;

// ---------------- device scratch ----------------
__device__ __align__(16) h16 g_rbf[(size_t)EE * K1];      // single fp16
__device__ __align__(16) h16 g_w1t_hi[NLAY * HID * K1];
__device__ __align__(16) h16 g_w1t_lo[NLAY * HID * K1];
__device__ __align__(16) h16 g_w2t_hi[NLAY * HID * HID];
__device__ __align__(16) h16 g_w2t_lo[NLAY * HID * HID];
__device__ __align__(16) h16 g_npt_hi[HID * K1];
__device__ __align__(16) h16 g_npt_lo[HID * K1];
__device__ __align__(16) h16 g_nwt_hi[NSLOT * HID * HID];
__device__ __align__(16) h16 g_nwt_lo[NSLOT * HID * HID];
__device__ float g_cut[EE];
__device__ float g_cutm[EE];
__device__ int   g_srow[EE];
__device__ int   g_sdst[EE];
__device__ int   g_perm[EE];
__device__ int   g_cnt[NN];
__device__ int   g_offm[NN];
__device__ float g_x  [NN * HID];
__device__ float g_h  [NN * HID];
__device__ float g_agg[NN * HID];
__device__ float g_nex[NN * HID];

// ---------------- small helper kernels ----------------
__global__ void k_zero_cnt() {
    int i = blockIdx.x * blockDim.x + threadIdx.x;
    if (i < NN) g_cnt[i] = 0;
}

__global__ void k_hist(const int* __restrict__ ei) {
    int e = blockIdx.x * blockDim.x + threadIdx.x;
    if (e < EE) atomicAdd(&g_cnt[ei[EE + e]], 1);
}

__global__ void k_scan() {
    __shared__ int part[1024];
    int t = threadIdx.x;
    int base = t * 8;
    int loc[8];
    int s = 0;
#pragma unroll
    for (int i = 0; i < 8; i++) { loc[i] = s; s += g_cnt[base + i]; }
    part[t] = s;
    __syncthreads();
    int val = s;
    for (int off = 1; off < 1024; off <<= 1) {
        int v = (t >= off) ? part[t - off] : 0;
        __syncthreads();
        val += v;
        part[t] = val;
        __syncthreads();
    }
    int pre = (t == 0) ? 0 : part[t - 1];
#pragma unroll
    for (int i = 0; i < 8; i++) g_offm[base + i] = pre + loc[i];
}

__global__ void k_place(const int* __restrict__ ei) {
    int e = blockIdx.x * blockDim.x + threadIdx.x;
    if (e < EE) {
        int c = ei[EE + e];
        int p = atomicAdd(&g_offm[c], 1);
        g_perm[p] = e;
    }
}

__global__ void k_build(const int* __restrict__ ei, const float* __restrict__ ew,
                        const float* __restrict__ means, const float* __restrict__ betas) {
    int warp = (blockIdx.x * blockDim.x + threadIdx.x) >> 5;
    int lane = threadIdx.x & 31;
    if (warp >= EE) return;
    int e = g_perm[warp];
    int r = ei[e];
    int c = ei[EE + e];
    float d = ew[e];
    float cut = 0.5f * (cosf(d * 0.628318530717958647692f) + 1.0f);
    if (!(d < 5.0f)) cut = 0.f;
    float ex = __expf(-d);
    size_t ro = (size_t)warp * K1;
    {
        float m = means[lane], b = betas[lane];
        float v = ex - m;
        g_rbf[ro + lane] = __float2half_rn(cut * __expf(-b * v * v));
    }
    int k2 = lane + 32;
    float val2 = 0.f;
    if (k2 < NRBF) {
        float m = means[k2], b = betas[k2];
        float v = ex - m;
        val2 = cut * __expf(-b * v * v);
    }
    g_rbf[ro + k2] = __float2half_rn(val2);
    if (lane == 0) {
        g_cut[warp]  = cut;
        g_cutm[warp] = (r != c) ? cut : 0.f;
        g_srow[warp] = r;
        g_sdst[warp] = c;
    }
}

__global__ void k_gather(const int* __restrict__ z, const float* __restrict__ emb,
                         const float* __restrict__ neemb) {
    int i = blockIdx.x * blockDim.x + threadIdx.x;
    if (i >= NN * HID) return;
    int n = i >> 7, c = i & 127;
    int zi = z[n];
    g_x[i]   = emb[zi * HID + c];
    g_nex[i] = neemb[zi * HID + c];
    g_agg[i] = 0.f;
}

// weight prep: transpose + fp16 hi/lo split
__global__ void k_wprep1(const float* __restrict__ w, int mode, int layers) {
    int i = blockIdx.x * blockDim.x + threadIdx.x;
    if (i >= layers * HID * K1) return;
    int k = i & (K1 - 1);
    int n = (i >> 6) & (HID - 1);
    int l = i >> 13;
    float v = (k < NRBF) ? w[((size_t)l * NRBF + k) * HID + n] : 0.f;
    h16 hi = __float2half_rn(v);
    h16 lo = __float2half_rn(v - __half2float(hi));
    if (mode == 0) { g_w1t_hi[i] = hi; g_w1t_lo[i] = lo; }
    else           { g_npt_hi[i] = hi; g_npt_lo[i] = lo; }
}

__global__ void k_wprep2(const float* __restrict__ w) {
    int i = blockIdx.x * blockDim.x + threadIdx.x;
    if (i >= NLAY * HID * HID) return;
    int k = i & (HID - 1);
    int n = (i >> 7) & (HID - 1);
    int l = i >> 14;
    float v = w[((size_t)l * HID + k) * HID + n];
    h16 hi = __float2half_rn(v);
    g_w2t_hi[i] = hi;
    g_w2t_lo[i] = __float2half_rn(v - __half2float(hi));
}

__global__ void k_wprepAll(const float* __restrict__ necatw, const float* __restrict__ lin1w,
                           const float* __restrict__ lin2w, const float* __restrict__ linw) {
    int slot = blockIdx.x >> 6;
    int i = (blockIdx.x & 63) * 256 + threadIdx.x;
    const float* src;
    if (slot < 2)       src = necatw + (size_t)slot * HID * HID;
    else if (slot < 8)  src = lin1w + (size_t)(slot - 2) * HID * HID;
    else if (slot < 14) src = lin2w + (size_t)(slot - 8) * HID * HID;
    else                src = linw  + (size_t)(slot - 14) * HID * HID;
    int k = i & (HID - 1);
    int n = i >> 7;
    float v = src[k * HID + n];
    h16 hi = __float2half_rn(v);
    g_nwt_hi[(size_t)slot * HID * HID + i] = hi;
    g_nwt_lo[(size_t)slot * HID * HID + i] = __float2half_rn(v - __half2float(hi));
}

// ---------------- warp-MMA helpers (fp16) ----------------
__device__ __forceinline__ void mma16816(float c[4], const unsigned a[4], const unsigned b[2]) {
    asm volatile(
        "mma.sync.aligned.m16n8k16.row.col.f32.f16.f16.f32 "
        "{%0,%1,%2,%3}, {%4,%5,%6,%7}, {%8,%9}, {%0,%1,%2,%3};\n"
        : "+f"(c[0]), "+f"(c[1]), "+f"(c[2]), "+f"(c[3])
        : "r"(a[0]), "r"(a[1]), "r"(a[2]), "r"(a[3]), "r"(b[0]), "r"(b[1]));
}

__device__ __forceinline__ void ldsm4(unsigned r[4], unsigned addr) {
    asm volatile("ldmatrix.sync.aligned.m8n8.x4.shared.b16 {%0,%1,%2,%3}, [%4];"
        : "=r"(r[0]), "=r"(r[1]), "=r"(r[2]), "=r"(r[3]) : "r"(addr));
}

__device__ __forceinline__ unsigned a_addr(unsigned base, int m0, int PB, int lane) {
    int sel = lane >> 3, li = lane & 7;
    return base + (m0 + li + (sel & 1) * 8) * PB + ((sel >> 1) * 8) * 2;
}
__device__ __forceinline__ unsigned b_addr(unsigned base, int n0, int PB, int lane) {
    int sel = lane >> 3, li = lane & 7;
    return base + (n0 + li + (sel >> 1) * 8) * PB + ((sel & 1) * 8) * 2;
}

// 2-term compensated fp16 32x32 warp GEMM: acc += A*(Bhi+Blo); A single fp16
template <int KSTEPS, int PB>
__device__ __forceinline__ void wgemm2(unsigned aA, unsigned bHi, unsigned bLo,
                                       float acc[2][4][4]) {
#pragma unroll
    for (int ks = 0; ks < KSTEPS; ks++) {
        unsigned off = ks * 32;
        unsigned a0[4], a1[4], bh0[4], bh1[4], bl0[4], bl1[4];
        ldsm4(a0, aA + off);
        ldsm4(a1, aA + 16 * PB + off);
        ldsm4(bh0, bHi + off);
        ldsm4(bh1, bHi + 16 * PB + off);
        ldsm4(bl0, bLo + off);
        ldsm4(bl1, bLo + 16 * PB + off);
#pragma unroll
        for (int nt = 0; nt < 4; nt++) {
            const unsigned* bh = (nt < 2) ? (bh0 + 2 * nt) : (bh1 + 2 * (nt - 2));
            const unsigned* bl = (nt < 2) ? (bl0 + 2 * nt) : (bl1 + 2 * (nt - 2));
            mma16816(acc[0][nt], a0, bh);
            mma16816(acc[1][nt], a1, bh);
            mma16816(acc[0][nt], a0, bl);
            mma16816(acc[1][nt], a1, bl);
        }
    }
}

// ---------------- cp.async helpers ----------------
__device__ __forceinline__ void cpa16(unsigned saddr, const void* gaddr) {
    asm volatile("cp.async.ca.shared.global [%0], [%1], 16;" :: "r"(saddr), "l"(gaddr));
}
__device__ __forceinline__ void cpa_commit() { asm volatile("cp.async.commit_group;"); }
__device__ __forceinline__ void cpa_wait0()  { asm volatile("cp.async.wait_group 0;"); }

// ---------------- fused edge MLP + segmented aggregation (persistent, pipelined)
// interaction smem: T[0,34816) W2hi[34816) W2lo[69632) rbf[104448,+18432)
//                   W1hi[122880) W1lo[141312) F[159744,+67584) misc[227328,+4096)
// NE smem: rbf[0,18432) W1hi[18432) W1lo[36864) F[55296,+67584) misc[122880,+4096)
template <int NE>
__global__ void __launch_bounds__(512, 1)
k_edge(int layer, const float* __restrict__ b1g, const float* __restrict__ b2g) {
    extern __shared__ __align__(16) char smref[];
    constexpr int W2_BYTES = HID * PT * 2;   // 34816
    constexpr int R_BYTES  = HID * PR * 2;   // 18432
    const int OFF_T    = 0;
    const int OFF_W2HI = 34816;
    const int OFF_W2LO = 69632;
    const int OFF_R    = NE ? 0 : 104448;
    const int OFF_W1HI = OFF_R + R_BYTES;
    const int OFF_W1LO = OFF_W1HI + R_BYTES;
    const int OFF_F    = OFF_W1LO + R_BYTES;
    const int OFF_MISC = OFF_F + HID * PF * 4;
    const int OFF_CUT  = OFF_MISC;
    const int OFF_ROW  = OFF_MISC + 1024;
    const int OFF_DST  = OFF_MISC + 2048;
    const int OFF_B1   = OFF_MISC + 3072;
    const int OFF_B2   = OFF_MISC + 3584;

    h16*  sT  = (h16*)(smref + OFF_T);
    float* sF = (float*)(smref + OFF_F);
    float* sB1 = (float*)(smref + OFF_B1);
    float* sB2 = (float*)(smref + OFF_B2);

    int tid = threadIdx.x;
    unsigned sbase = (unsigned)__cvta_generic_to_shared(smref);

    const long NT = EE / 128;
    long tile = blockIdx.x;
    int buf = 0;

    // issue tile-0 rbf + metadata copy
    if (tile < NT) {
        long ebase = tile * 128;
        for (int c = tid; c < 1024; c += 512) {
            int r = c >> 3, ch = c & 7;
            cpa16(sbase + OFF_R + r * 144 + ch * 16, &g_rbf[(ebase + r) * K1 + ch * 8]);
        }
        if (tid < 32) {
            const float* cs = NE ? g_cutm : g_cut;
            cpa16(sbase + OFF_CUT + tid * 16, cs + ebase + tid * 4);
        } else if (tid < 64) {
            int t = tid - 32;
            cpa16(sbase + OFF_ROW + t * 16, g_srow + ebase + t * 4);
        } else if (tid < 96) {
            int t = tid - 64;
            cpa16(sbase + OFF_DST + t * 16, g_sdst + ebase + t * 4);
        }
    }
    cpa_commit();

    // ---- stage weights once ----
    {
        const unsigned* ghi = (const unsigned*)(NE ? g_npt_hi : (g_w1t_hi + (size_t)layer * HID * K1));
        const unsigned* glo = (const unsigned*)(NE ? g_npt_lo : (g_w1t_lo + (size_t)layer * HID * K1));
        unsigned* shi = (unsigned*)(smref + OFF_W1HI);
        unsigned* slo = (unsigned*)(smref + OFF_W1LO);
        for (int i = tid; i < 128 * 32; i += 512) {
            int r = i >> 5, wd = i & 31;
            shi[r * (PR / 2) + wd] = ghi[i];
            slo[r * (PR / 2) + wd] = glo[i];
        }
    }
    if (!NE) {
        const unsigned* ghi = (const unsigned*)(g_w2t_hi + (size_t)layer * HID * HID);
        const unsigned* glo = (const unsigned*)(g_w2t_lo + (size_t)layer * HID * HID);
        unsigned* shi = (unsigned*)(smref + OFF_W2HI);
        unsigned* slo = (unsigned*)(smref + OFF_W2LO);
        for (int i = tid; i < 128 * 64; i += 512) {
            int r = i >> 6, wd = i & 63;
            shi[r * (PT / 2) + wd] = ghi[i];
            slo[r * (PT / 2) + wd] = glo[i];
        }
    }
    if (tid < 128) {
        sB1[tid] = b1g[tid];
        sB2[tid] = NE ? 0.f : b2g[tid];
    }

    int w = tid >> 5, lane = tid & 31;
    int m0 = (w & 3) * 32, n0 = (w >> 2) * 32;
    int g = lane >> 2, tc = lane & 3;

    unsigned g1a   = a_addr(sbase + OFF_R,    m0, PR * 2, lane);
    unsigned g1bHi = b_addr(sbase + OFF_W1HI, n0, PR * 2, lane);
    unsigned g1bLo = g1bHi + R_BYTES;
    unsigned g2a   = a_addr(sbase + OFF_T,    m0, PT * 2, lane);
    unsigned g2bHi = b_addr(sbase + OFF_W2HI, n0, PT * 2, lane);
    unsigned g2bLo = g2bHi + W2_BYTES;

    const float* hsrc = NE ? g_nex : g_h;

    for (; tile < NT; tile += gridDim.x, buf ^= 1) {
        cpa_wait0();
        __syncthreads();   // rbf + meta[buf] ready; prev aggregation done

        float* sCut = (float*)(smref + OFF_CUT + buf * 512);
        int*   sRow = (int*)(smref + OFF_ROW + buf * 512);
        int*   sDst = (int*)(smref + OFF_DST + buf * 512);

        // ---- GEMM1: rbf[128,64] @ W1[64,128] ----
        {
            float acc[2][4][4];
#pragma unroll
            for (int a = 0; a < 2; a++)
#pragma unroll
                for (int b = 0; b < 4; b++)
#pragma unroll
                    for (int c = 0; c < 4; c++) acc[a][b][c] = 0.f;
            wgemm2<K1 / 16, PR * 2>(g1a, g1bHi, g1bLo, acc);

            if (NE) {
#pragma unroll
                for (int mt = 0; mt < 2; mt++) {
                    int ra = m0 + mt * 16 + g, rb2 = ra + 8;
                    float cua = sCut[ra], cub = sCut[rb2];
#pragma unroll
                    for (int nt = 0; nt < 4; nt++) {
                        int col = n0 + nt * 8 + 2 * tc;
                        float2 v0, v1;
                        v0.x = (acc[mt][nt][0] + sB1[col])     * cua;
                        v0.y = (acc[mt][nt][1] + sB1[col + 1]) * cua;
                        v1.x = (acc[mt][nt][2] + sB1[col])     * cub;
                        v1.y = (acc[mt][nt][3] + sB1[col + 1]) * cub;
                        *(float2*)&sF[ra * PF + col]  = v0;
                        *(float2*)&sF[rb2 * PF + col] = v1;
                    }
                }
            } else {
#pragma unroll
                for (int mt = 0; mt < 2; mt++) {
                    int ra = m0 + mt * 16 + g, rb2 = ra + 8;
#pragma unroll
                    for (int nt = 0; nt < 4; nt++) {
                        int col = n0 + nt * 8 + 2 * tc;
                        float x0 = acc[mt][nt][0] + sB1[col];
                        float x1 = acc[mt][nt][1] + sB1[col + 1];
                        float x2 = acc[mt][nt][2] + sB1[col];
                        float x3 = acc[mt][nt][3] + sB1[col + 1];
                        x0 = x0 / (1.f + __expf(-x0));
                        x1 = x1 / (1.f + __expf(-x1));
                        x2 = x2 / (1.f + __expf(-x2));
                        x3 = x3 / (1.f + __expf(-x3));
                        *(h162*)&sT[ra * PT + col]  = __floats2half2_rn(x0, x1);
                        *(h162*)&sT[rb2 * PT + col] = __floats2half2_rn(x2, x3);
                    }
                }
            }
        }
        __syncthreads();   // rbf dead; T written (interaction)

        // ---- issue next tile's rbf + metadata ----
        {
            long nxt = tile + gridDim.x;
            if (nxt < NT) {
                long ebase = nxt * 128;
                int nb = buf ^ 1;
                for (int c = tid; c < 1024; c += 512) {
                    int r = c >> 3, ch = c & 7;
                    cpa16(sbase + OFF_R + r * 144 + ch * 16, &g_rbf[(ebase + r) * K1 + ch * 8]);
                }
                if (tid < 32) {
                    const float* cs = NE ? g_cutm : g_cut;
                    cpa16(sbase + OFF_CUT + nb * 512 + tid * 16, cs + ebase + tid * 4);
                } else if (tid < 64) {
                    int t = tid - 32;
                    cpa16(sbase + OFF_ROW + nb * 512 + t * 16, g_srow + ebase + t * 4);
                } else if (tid < 96) {
                    int t = tid - 64;
                    cpa16(sbase + OFF_DST + nb * 512 + t * 16, g_sdst + ebase + t * 4);
                }
            }
            cpa_commit();
        }

        // ---- GEMM2 (interaction only): F gets its own region, no overlay sync
        if (!NE) {
            float acc[2][4][4];
#pragma unroll
            for (int a = 0; a < 2; a++)
#pragma unroll
                for (int b = 0; b < 4; b++)
#pragma unroll
                    for (int c = 0; c < 4; c++) acc[a][b][c] = 0.f;
            wgemm2<HID / 16, PT * 2>(g2a, g2bHi, g2bLo, acc);

#pragma unroll
            for (int mt = 0; mt < 2; mt++) {
                int ra = m0 + mt * 16 + g, rb2 = ra + 8;
                float cua = sCut[ra], cub = sCut[rb2];
#pragma unroll
                for (int nt = 0; nt < 4; nt++) {
                    int col = n0 + nt * 8 + 2 * tc;
                    float2 v0, v1;
                    v0.x = (acc[mt][nt][0] + sB2[col])     * cua;
                    v0.y = (acc[mt][nt][1] + sB2[col + 1]) * cua;
                    v1.x = (acc[mt][nt][2] + sB2[col])     * cub;
                    v1.y = (acc[mt][nt][3] + sB2[col + 1]) * cub;
                    *(float2*)&sF[ra * PF + col]  = v0;
                    *(float2*)&sF[rb2 * PF + col] = v1;
                }
            }
        }
        __syncthreads();   // F ready

        // ---- segmented aggregation ----
        int grp = tid >> 7;
        int f = tid & 127;
        int e0 = grp * 32;
        float accv = 0.f;
        int cur = sDst[e0];
#pragma unroll 1
        for (int b = 0; b < 4; b++) {
            float hb[8];
#pragma unroll
            for (int j = 0; j < 8; j++)
                hb[j] = hsrc[(long)sRow[e0 + b * 8 + j] * HID + f];
#pragma unroll
            for (int j = 0; j < 8; j++) {
                int e = e0 + b * 8 + j;
                int dd = sDst[e];
                if (dd != cur) {
                    atomicAdd(&g_agg[(long)cur * HID + f], accv);
                    accv = 0.f;
                    cur = dd;
                }
                accv = fmaf(hb[j], sF[e * PF + f], accv);
            }
        }
        atomicAdd(&g_agg[(long)cur * HID + f], accv);
    }
}

// ---------------- node-kernel shared pieces ----------------
// A single fp16 [0,17408); Wa hi/lo [17408,87040); Wb hi/lo [87040,156672);
// H single [156672,174080); biases [174080,175104)
#define NA_BYTES  (64 * PT * 2)     // 17408
#define NW_BYTES  (HID * PT * 2)    // 34816
#define NOFF_A    0
#define NOFF_WA   NA_BYTES
#define NOFF_WB   (NOFF_WA + 2 * NW_BYTES)
#define NOFF_H    (NOFF_WB + 2 * NW_BYTES)
#define NOFF_B    (NOFF_H + NA_BYTES)
#define NSM_TOTAL (NOFF_B + 1024)

__device__ __forceinline__ void stageA_f16(char* smref, int off, const float* src,
                                           int rb, int tid) {
    h16* dst = (h16*)(smref + off);
    for (int i = tid; i < 64 * HID; i += 256) {
        int r = i >> 7, k = i & 127;
        dst[r * PT + k] = __float2half_rn(src[(long)(rb + r) * HID + k]);
    }
}

__device__ __forceinline__ void stageW(char* smref, int off, int slot, int tid) {
    const unsigned* ghi = (const unsigned*)(g_nwt_hi + (size_t)slot * HID * HID);
    const unsigned* glo = (const unsigned*)(g_nwt_lo + (size_t)slot * HID * HID);
    unsigned* shi = (unsigned*)(smref + off);
    unsigned* slo = (unsigned*)(smref + off + NW_BYTES);
    for (int i = tid; i < 128 * 64; i += 256) {
        int r = i >> 6, wd = i & 63;
        shi[r * (PT / 2) + wd] = ghi[i];
        slo[r * (PT / 2) + wd] = glo[i];
    }
}

// ---------------- NE node kernel: x = x@Wtop + agg@Wbot + b; h = x@lin1[0] ----
__global__ void __launch_bounds__(256, 1)
k_nodeNE(const float* __restrict__ necatb) {
    extern __shared__ __align__(16) char smref[];
    float* sBa = (float*)(smref + NOFF_B);

    int tid = threadIdx.x;
    int rb = blockIdx.x * 64;
    unsigned sbase = (unsigned)__cvta_generic_to_shared(smref);

    stageA_f16(smref, NOFF_A, g_x, rb, tid);
    stageW(smref, NOFF_WA, 0, tid);
    stageW(smref, NOFF_WB, 1, tid);
    if (tid < 128) sBa[tid] = necatb[tid];
    __syncthreads();

    int w = tid >> 5, lane = tid & 31;
    int m0 = (w & 1) * 32, n0 = (w >> 1) * 32;
    int g = lane >> 2, tc = lane & 3;

    float acc[2][4][4];
#pragma unroll
    for (int a = 0; a < 2; a++)
#pragma unroll
        for (int b = 0; b < 4; b++)
#pragma unroll
            for (int c = 0; c < 4; c++) acc[a][b][c] = 0.f;

    // GEMM A: acc = x @ Wtop
    {
        unsigned aA = a_addr(sbase + NOFF_A, m0, PT * 2, lane);
        unsigned bHi = b_addr(sbase + NOFF_WA, n0, PT * 2, lane);
        wgemm2<HID / 16, PT * 2>(aA, bHi, bHi + NW_BYTES, acc);
    }
    __syncthreads();   // A reads done

    // restage A = agg tile; Wa = lin1[0]
    stageA_f16(smref, NOFF_A, g_agg, rb, tid);
    stageW(smref, NOFF_WA, 2, tid);
    __syncthreads();

    // zero agg rows AFTER all threads have staged them
    {
        float4* za = (float4*)(g_agg + (long)rb * HID);
        for (int i = tid; i < 64 * HID / 4; i += 256) za[i] = make_float4(0.f, 0.f, 0.f, 0.f);
    }

    // GEMM B: acc += agg @ Wbot; x = acc + b -> g_x and H (fp16)
    {
        unsigned aA = a_addr(sbase + NOFF_A, m0, PT * 2, lane);
        unsigned bHi = b_addr(sbase + NOFF_WB, n0, PT * 2, lane);
        wgemm2<HID / 16, PT * 2>(aA, bHi, bHi + NW_BYTES, acc);

        h16* xh = (h16*)(smref + NOFF_H);
#pragma unroll
        for (int mt = 0; mt < 2; mt++) {
#pragma unroll
            for (int dr = 0; dr < 2; dr++) {
                int r = m0 + mt * 16 + g + dr * 8;
                long ro = (long)(rb + r) * HID;
#pragma unroll
                for (int nt = 0; nt < 4; nt++) {
                    int col = n0 + nt * 8 + 2 * tc;
                    float v0 = acc[mt][nt][2 * dr]     + sBa[col];
                    float v1 = acc[mt][nt][2 * dr + 1] + sBa[col + 1];
                    *(float2*)&g_x[ro + col] = make_float2(v0, v1);
                    *(h162*)&xh[r * PT + col] = __floats2half2_rn(v0, v1);
                }
            }
        }
    }
    __syncthreads();

    // GEMM C: h = x @ lin1[0]
    {
        float acc2[2][4][4];
#pragma unroll
        for (int a = 0; a < 2; a++)
#pragma unroll
            for (int b = 0; b < 4; b++)
#pragma unroll
                for (int c = 0; c < 4; c++) acc2[a][b][c] = 0.f;
        unsigned aA = a_addr(sbase + NOFF_H, m0, PT * 2, lane);
        unsigned bHi = b_addr(sbase + NOFF_WA, n0, PT * 2, lane);
        wgemm2<HID / 16, PT * 2>(aA, bHi, bHi + NW_BYTES, acc2);
#pragma unroll
        for (int mt = 0; mt < 2; mt++) {
#pragma unroll
            for (int dr = 0; dr < 2; dr++) {
                int r = m0 + mt * 16 + g + dr * 8;
                long ro = (long)(rb + r) * HID;
#pragma unroll
                for (int nt = 0; nt < 4; nt++) {
                    int col = n0 + nt * 8 + 2 * tc;
                    *(float2*)&g_h[ro + col] =
                        make_float2(acc2[mt][nt][2 * dr], acc2[mt][nt][2 * dr + 1]);
                }
            }
        }
    }
}

// ---------------- layer node kernel ----------------
__global__ void __launch_bounds__(256, 1)
k_nodeL(int l, int last, const float* __restrict__ b2g, const float* __restrict__ b3g,
        float* dout) {
    extern __shared__ __align__(16) char smref[];
    float* sB2 = (float*)(smref + NOFF_B);
    float* sB3 = sB2 + 128;

    int tid = threadIdx.x;
    int rb = blockIdx.x * 64;
    unsigned sbase = (unsigned)__cvta_generic_to_shared(smref);

    stageA_f16(smref, NOFF_A, g_agg, rb, tid);
    stageW(smref, NOFF_WA, 8 + l, tid);    // lin2
    stageW(smref, NOFF_WB, 14 + l, tid);   // lin
    if (tid < 128) { sB2[tid] = b2g[tid]; sB3[tid] = b3g[tid]; }
    __syncthreads();

    int w = tid >> 5, lane = tid & 31;
    int m0 = (w & 1) * 32, n0 = (w >> 1) * 32;
    int g = lane >> 2, tc = lane & 3;

    // GEMM A: H = silu(agg @ lin2 + b2)
    {
        float acc[2][4][4];
#pragma unroll
        for (int a = 0; a < 2; a++)
#pragma unroll
            for (int b = 0; b < 4; b++)
#pragma unroll
                for (int c = 0; c < 4; c++) acc[a][b][c] = 0.f;
        unsigned aA = a_addr(sbase + NOFF_A, m0, PT * 2, lane);
        unsigned bHi = b_addr(sbase + NOFF_WA, n0, PT * 2, lane);
        wgemm2<HID / 16, PT * 2>(aA, bHi, bHi + NW_BYTES, acc);

        h16* sH = (h16*)(smref + NOFF_H);
#pragma unroll
        for (int mt = 0; mt < 2; mt++) {
            int ra = m0 + mt * 16 + g, rb2 = ra + 8;
#pragma unroll
            for (int nt = 0; nt < 4; nt++) {
                int col = n0 + nt * 8 + 2 * tc;
                float x0 = acc[mt][nt][0] + sB2[col];
                float x1 = acc[mt][nt][1] + sB2[col + 1];
                float x2 = acc[mt][nt][2] + sB2[col];
                float x3 = acc[mt][nt][3] + sB2[col + 1];
                x0 = x0 / (1.f + __expf(-x0));
                x1 = x1 / (1.f + __expf(-x1));
                x2 = x2 / (1.f + __expf(-x2));
                x3 = x3 / (1.f + __expf(-x3));
                *(h162*)&sH[ra * PT + col]  = __floats2half2_rn(x0, x1);
                *(h162*)&sH[rb2 * PT + col] = __floats2half2_rn(x2, x3);
            }
        }
    }
    __syncthreads();

    // Wa dead: stage lin1[l+1]; zero agg rows
    if (!last) {
        stageW(smref, NOFF_WA, 2 + (l + 1), tid);
        float4* za = (float4*)(g_agg + (long)rb * HID);
        for (int i = tid; i < 64 * HID / 4; i += 256) za[i] = make_float4(0.f, 0.f, 0.f, 0.f);
    }

    // GEMM B: x = H @ lin + b3 + x_old
    {
        float acc[2][4][4];
#pragma unroll
        for (int a = 0; a < 2; a++)
#pragma unroll
            for (int b = 0; b < 4; b++)
#pragma unroll
                for (int c = 0; c < 4; c++) acc[a][b][c] = 0.f;
        unsigned aA = a_addr(sbase + NOFF_H, m0, PT * 2, lane);
        unsigned bHi = b_addr(sbase + NOFF_WB, n0, PT * 2, lane);
        wgemm2<HID / 16, PT * 2>(aA, bHi, bHi + NW_BYTES, acc);

        float* out = last ? dout : g_x;
        h16* xh = (h16*)(smref + NOFF_A);
#pragma unroll
        for (int mt = 0; mt < 2; mt++) {
#pragma unroll
            for (int dr = 0; dr < 2; dr++) {
                int r = m0 + mt * 16 + g + dr * 8;
                long ro = (long)(rb + r) * HID;
#pragma unroll
                for (int nt = 0; nt < 4; nt++) {
                    int col = n0 + nt * 8 + 2 * tc;
                    float v0 = acc[mt][nt][2 * dr]     + sB3[col] + g_x[ro + col];
                    float v1 = acc[mt][nt][2 * dr + 1] + sB3[col + 1] + g_x[ro + col + 1];
                    *(float2*)&out[ro + col] = make_float2(v0, v1);
                    if (!last)
                        *(h162*)&xh[r * PT + col] = __floats2half2_rn(v0, v1);
                }
            }
        }
    }
    if (last) return;
    __syncthreads();

    // GEMM C: h = x @ lin1[l+1]
    {
        float acc[2][4][4];
#pragma unroll
        for (int a = 0; a < 2; a++)
#pragma unroll
            for (int b = 0; b < 4; b++)
#pragma unroll
                for (int c = 0; c < 4; c++) acc[a][b][c] = 0.f;
        unsigned aA = a_addr(sbase + NOFF_A, m0, PT * 2, lane);
        unsigned bHi = b_addr(sbase + NOFF_WA, n0, PT * 2, lane);
        wgemm2<HID / 16, PT * 2>(aA, bHi, bHi + NW_BYTES, acc);
#pragma unroll
        for (int mt = 0; mt < 2; mt++) {
#pragma unroll
            for (int dr = 0; dr < 2; dr++) {
                int r = m0 + mt * 16 + g + dr * 8;
                long ro = (long)(rb + r) * HID;
#pragma unroll
                for (int nt = 0; nt < 4; nt++) {
                    int col = n0 + nt * 8 + 2 * tc;
                    *(float2*)&g_h[ro + col] =
                        make_float2(acc[mt][nt][2 * dr], acc[mt][nt][2 * dr + 1]);
                }
            }
        }
    }
}

// ---------------- launch ----------------
extern "C" void kernel_launch(void* const* d_in, const int* in_sizes, int n_in,
                              void* d_out, int out_size) {
    const int*   z       = (const int*)d_in[0];
    const int*   ei      = (const int*)d_in[1];
    const float* ew      = (const float*)d_in[2];
    const float* emb     = (const float*)d_in[3];
    const float* neemb   = (const float*)d_in[4];
    const float* neprojw = (const float*)d_in[5];
    const float* neprojb = (const float*)d_in[6];
    const float* necatw  = (const float*)d_in[7];
    const float* necatb  = (const float*)d_in[8];
    const float* means   = (const float*)d_in[9];
    const float* betas   = (const float*)d_in[10];
    const float* mlpw1   = (const float*)d_in[11];
    const float* mlpb1   = (const float*)d_in[12];
    const float* mlpw2   = (const float*)d_in[13];
    const float* mlpb2   = (const float*)d_in[14];
    const float* lin1w   = (const float*)d_in[15];
    const float* lin2w   = (const float*)d_in[16];
    const float* lin2b   = (const float*)d_in[17];
    const float* linw    = (const float*)d_in[18];
    const float* linb    = (const float*)d_in[19];
    float* outp = (float*)d_out;

    const int smI = 104448 + 3 * (HID * PR * 2) + HID * PF * 4 + 4096;   // 231424
    const int smN = 3 * (HID * PR * 2) + HID * PF * 4 + 4096;            // 126976

    cudaFuncSetAttribute(k_edge<0>, cudaFuncAttributeMaxDynamicSharedMemorySize, smI);
    cudaFuncSetAttribute(k_edge<1>, cudaFuncAttributeMaxDynamicSharedMemorySize, smN);
    cudaFuncSetAttribute(k_nodeNE,  cudaFuncAttributeMaxDynamicSharedMemorySize, NSM_TOTAL);
    cudaFuncSetAttribute(k_nodeL,   cudaFuncAttributeMaxDynamicSharedMemorySize, NSM_TOTAL);

    // ---- sort edges by destination + precompute per-edge data ----
    k_zero_cnt<<<NN / 256, 256>>>();
    k_hist<<<EE / 256, 256>>>(ei);
    k_scan<<<1, 1024>>>();
    k_place<<<EE / 256, 256>>>(ei);
    k_build<<<EE / 8, 256>>>(ei, ew, means, betas);
    k_gather<<<NN * HID / 256, 256>>>(z, emb, neemb);

    // ---- weight prep ----
    k_wprep1<<<(NLAY * HID * K1 + 255) / 256, 256>>>(mlpw1, 0, NLAY);
    k_wprep1<<<(HID * K1 + 255) / 256, 256>>>(neprojw, 1, 1);
    k_wprep2<<<(NLAY * HID * HID + 255) / 256, 256>>>(mlpw2);
    k_wprepAll<<<NSLOT * 64, 256>>>(necatw, lin1w, lin2w, linw);

    // ---- NeighborEmbedding + initial lin1 ----
    k_edge<1><<<148, 512, smN>>>(0, neprojb, nullptr);
    k_nodeNE<<<NN / 64, 256, NSM_TOTAL>>>(necatb);

    // ---- interaction layers ----
    for (int l = 0; l < NLAY; l++) {
        k_edge<0><<<148, 512, smI>>>(l, mlpb1 + (size_t)l * HID, mlpb2 + (size_t)l * HID);
        k_nodeL<<<NN / 64, 256, NSM_TOTAL>>>(l, l == NLAY - 1,
                                             lin2b + (size_t)l * HID,
                                             linb + (size_t)l * HID, outp);
    }
}